// round 8
// baseline (speedup 1.0000x reference)
#include <cuda_runtime.h>
#include <cuda_bf16.h>
#include <cstdint>

#define D_MODEL 1024
#define N_TOK   2048
#define N_HEADS 16
#define HEAD_D  64
#define SEQ     512
#define NB      4
#define FFN_D   4096
#define NEXP    8
#define CAPV    512

typedef __nv_bfloat16 bf16;

// ================= device scratch =================
__device__ bf16 g_h1h[2097152], g_h1l[2097152];
__device__ bf16 g_h2h[2097152], g_h2l[2097152];
__device__ float g_h2[2097152];
__device__ bf16 g_qh[2097152], g_ql[2097152];
__device__ bf16 g_kh[2097152], g_kl[2097152];
__device__ bf16 g_vh[2097152], g_vl[2097152];
__device__ bf16 g_ath[2097152], g_atl[2097152];
__device__ bf16 g_midh[16777216], g_midl[16777216];
__device__ bf16 g_ph[16777216], g_pl[16777216];
__device__ float g_sc[16777216];
__device__ float g_y[4194304];
__device__ int   g_top1[N_TOK], g_top2[N_TOK];
__device__ float g_p1[N_TOK], g_p2[N_TOK];
__device__ int   g_s1[N_TOK], g_s2[N_TOK];
__device__ float g_g1[N_TOK], g_g2[N_TOK];
__device__ int   g_disp[NEXP * CAPV];

// ================= helpers =================
__device__ __forceinline__ uint32_t smem_u32(const void* p) {
    uint32_t a;
    asm("{ .reg .u64 t; cvta.to.shared.u64 t, %1; cvt.u32.u64 %0, t; }" : "=r"(a) : "l"(p));
    return a;
}
__device__ __forceinline__ void ldsm_x4(uint32_t* r, uint32_t addr) {
    asm volatile("ldmatrix.sync.aligned.m8n8.x4.shared.b16 {%0,%1,%2,%3}, [%4];"
        : "=r"(r[0]), "=r"(r[1]), "=r"(r[2]), "=r"(r[3]) : "r"(addr));
}
__device__ __forceinline__ void ldsm_x4t(uint32_t* r, uint32_t addr) {
    asm volatile("ldmatrix.sync.aligned.m8n8.x4.trans.shared.b16 {%0,%1,%2,%3}, [%4];"
        : "=r"(r[0]), "=r"(r[1]), "=r"(r[2]), "=r"(r[3]) : "r"(addr));
}
__device__ __forceinline__ void mma16816(float* c, const uint32_t* a, uint32_t b0, uint32_t b1) {
    asm volatile(
        "mma.sync.aligned.m16n8k16.row.col.f32.bf16.bf16.f32 "
        "{%0,%1,%2,%3}, {%4,%5,%6,%7}, {%8,%9}, {%0,%1,%2,%3};"
        : "+f"(c[0]), "+f"(c[1]), "+f"(c[2]), "+f"(c[3])
        : "r"(a[0]), "r"(a[1]), "r"(a[2]), "r"(a[3]), "r"(b0), "r"(b1));
}
__device__ __forceinline__ void split2(float x, uint16_t& h, uint16_t& l) {
    __nv_bfloat16 hb = __float2bfloat16(x);
    float r = x - __bfloat162float(hb);
    h = __bfloat16_as_ushort(hb);
    l = __bfloat16_as_ushort(__float2bfloat16(r));
}
__device__ __forceinline__ void pack2(float x, float y, uint32_t& hi, uint32_t& lo) {
    uint16_t hx, lx, hy, ly;
    split2(x, hx, lx); split2(y, hy, ly);
    hi = (uint32_t)hx | ((uint32_t)hy << 16);
    lo = (uint32_t)lx | ((uint32_t)ly << 16);
}

// ================= split-bf16 HMMA GEMM: CTA 128x128, Kc=32, double-buffered =================
// A: pre-split bf16 hi/lo planes [M,K].  B: NATIVE fp32 [K,N], split in-kernel.
#define AH_O 0
#define AL_O 10240
#define BH_O 20480
#define BL_O 28672
#define STG  36864
#define GEMM_SMEM (2 * STG)

template <bool RELU, bool GATHER, bool MULTI, bool OSPLIT>
__global__ __launch_bounds__(256, 1)
void gemm_mma(const bf16* __restrict__ Ah, const bf16* __restrict__ Al,
              const float* __restrict__ B0, const float* __restrict__ B1,
              const float* __restrict__ B2,
              const float* __restrict__ bi0, const float* __restrict__ bi1,
              const float* __restrict__ bi2,
              float* __restrict__ oF0,
              bf16* __restrict__ oH0, bf16* __restrict__ oL0,
              bf16* __restrict__ oH1, bf16* __restrict__ oL1,
              bf16* __restrict__ oH2, bf16* __restrict__ oL2,
              float s0, float s1, float s2,
              const float* __restrict__ resid, const int* __restrict__ gather,
              int K, int N,
              long aStride, long bStride, long biStride, long oStride) {
    extern __shared__ char sm[];
    uint32_t sb = smem_u32(sm);
    int tid = threadIdx.x, wid = tid >> 5, lane = tid & 31;
    int z = blockIdx.z;
    int m0 = blockIdx.y * 128, n0 = blockIdx.x * 128;

    const float* B; const float* bi; float scale;
    float* oF = nullptr; bf16 *oH = nullptr, *oL = nullptr;
    if (MULTI) {
        B = (z == 0) ? B0 : (z == 1) ? B1 : B2;
        bi = (z == 0) ? bi0 : (z == 1) ? bi1 : bi2;
        scale = (z == 0) ? s0 : (z == 1) ? s1 : s2;
        oH = (z == 0) ? oH0 : (z == 1) ? oH1 : oH2;
        oL = (z == 0) ? oL0 : (z == 1) ? oL1 : oL2;
    } else {
        B = B0 + (long)z * bStride;
        bi = bi0 + (long)z * biStride;
        scale = s0;
        if (OSPLIT) { oH = oH0 + (long)z * oStride; oL = oL0 + (long)z * oStride; }
        else oF = oF0 + (long)z * oStride;
    }
    const bf16* Ahz = Ah + (MULTI ? 0 : (long)z * aStride);
    const bf16* Alz = Al + (MULTI ? 0 : (long)z * aStride);
    const int* gz = GATHER ? (gather + z * CAPV) : nullptr;

    // A load mapping: 2 uint4 vectors per plane per thread (rows of 32 bf16)
    int aR0 = tid >> 2, aC0 = (tid & 3) * 8;
    int aR1 = (tid + 256) >> 2, aC1 = ((tid + 256) & 3) * 8;
    long aRow0 = GATHER ? (long)gz[m0 + aR0] : (long)(m0 + aR0);
    long aRow1 = GATHER ? (long)gz[m0 + aR1] : (long)(m0 + aR1);
    long aG0 = aRow0 * K + aC0;
    long aG1 = aRow1 * K + aC1;
    int aD0 = aR0 * 80 + aC0 * 2;
    int aD1 = aR1 * 80 + aC1 * 2;

    // B fp32 load mapping: 4 float4 per thread (32 rows x 128 fp32)
    long bG[4]; int bD[4];
#pragma unroll
    for (int i = 0; i < 4; i++) {
        int v = tid + 256 * i;
        int row = v >> 5;           // 0..31
        int colE = (v & 31) * 4;    // 0..124 (elements)
        bG[i] = (long)row * N + n0 + colE;
        bD[i] = row * 256 + ((colE * 2) ^ ((row & 7) << 4));
    }

    float c[4][4][4];
#pragma unroll
    for (int mt = 0; mt < 4; mt++)
#pragma unroll
        for (int nt = 0; nt < 4; nt++)
#pragma unroll
            for (int f = 0; f < 4; f++) c[mt][nt][f] = 0.f;

    int wm = wid >> 2, wn = wid & 3;
    int aRowOff = (lane & 7) + ((lane >> 3) & 1) * 8;
    int aColSel = ((lane >> 4) & 1) * 16;
    int bKoff = (lane & 7) + ((lane >> 3) & 1) * 8;
    int bN8 = ((lane >> 4) & 1) * 8;

    // prologue loads
    uint4 vah0 = *(const uint4*)(Ahz + aG0), vah1 = *(const uint4*)(Ahz + aG1);
    uint4 val0 = *(const uint4*)(Alz + aG0), val1 = *(const uint4*)(Alz + aG1);
    float4 wb[4];
#pragma unroll
    for (int i = 0; i < 4; i++) wb[i] = *(const float4*)(B + bG[i]);

    int nCh = K >> 5;
    for (int ch = 0; ch < nCh; ch++) {
        char* smb = sm + (ch & 1) * STG;
        uint32_t sbuf = sb + (ch & 1) * STG;
        __syncthreads();
        *(uint4*)(smb + AH_O + aD0) = vah0; *(uint4*)(smb + AH_O + aD1) = vah1;
        *(uint4*)(smb + AL_O + aD0) = val0; *(uint4*)(smb + AL_O + aD1) = val1;
#pragma unroll
        for (int i = 0; i < 4; i++) {
            uint32_t h0, l0, h1, l1;
            pack2(wb[i].x, wb[i].y, h0, l0);
            pack2(wb[i].z, wb[i].w, h1, l1);
            *(uint2*)(smb + BH_O + bD[i]) = make_uint2(h0, h1);
            *(uint2*)(smb + BL_O + bD[i]) = make_uint2(l0, l1);
        }
        __syncthreads();
        if (ch + 1 < nCh) {
            int k0 = (ch + 1) << 5;
            vah0 = *(const uint4*)(Ahz + aG0 + k0); vah1 = *(const uint4*)(Ahz + aG1 + k0);
            val0 = *(const uint4*)(Alz + aG0 + k0); val1 = *(const uint4*)(Alz + aG1 + k0);
            long ko = (long)k0 * N;
#pragma unroll
            for (int i = 0; i < 4; i++) wb[i] = *(const float4*)(B + ko + bG[i]);
        }
#pragma unroll
        for (int ks = 0; ks < 2; ks++) {
            uint32_t ah[4][4], al[4][4];
#pragma unroll
            for (int mt = 0; mt < 4; mt++) {
                uint32_t ro = (wm * 64 + mt * 16 + aRowOff) * 80 + ks * 32 + aColSel;
                ldsm_x4(ah[mt], sbuf + AH_O + ro);
                ldsm_x4(al[mt], sbuf + AL_O + ro);
            }
            uint32_t bh[2][4], bl[2][4];
#pragma unroll
            for (int nb = 0; nb < 2; nb++) {
                int kk = ks * 16 + bKoff;
                int nn = wn * 32 + nb * 16 + bN8;
                uint32_t off = kk * 256 + ((nn * 2) ^ ((kk & 7) << 4));
                ldsm_x4t(bh[nb], sbuf + BH_O + off);
                ldsm_x4t(bl[nb], sbuf + BL_O + off);
            }
#pragma unroll
            for (int mt = 0; mt < 4; mt++)
#pragma unroll
                for (int nt = 0; nt < 4; nt++) {
                    const uint32_t* bp = &bh[nt >> 1][(nt & 1) * 2];
                    mma16816(c[mt][nt], ah[mt], bp[0], bp[1]);
                }
#pragma unroll
            for (int mt = 0; mt < 4; mt++)
#pragma unroll
                for (int nt = 0; nt < 4; nt++) {
                    const uint32_t* lp = &bl[nt >> 1][(nt & 1) * 2];
                    mma16816(c[mt][nt], ah[mt], lp[0], lp[1]);
                }
#pragma unroll
            for (int mt = 0; mt < 4; mt++)
#pragma unroll
                for (int nt = 0; nt < 4; nt++) {
                    const uint32_t* bp = &bh[nt >> 1][(nt & 1) * 2];
                    mma16816(c[mt][nt], al[mt], bp[0], bp[1]);
                }
        }
    }

    int r0 = m0 + wm * 64 + (lane >> 2);
    int col0 = n0 + wn * 32 + (lane & 3) * 2;
#pragma unroll
    for (int mt = 0; mt < 4; mt++) {
#pragma unroll
        for (int nt = 0; nt < 4; nt++) {
            int row = r0 + mt * 16;
            int cn = col0 + nt * 8;
            float2 bb = *(const float2*)(bi + cn);
            float v0x = (c[mt][nt][0] + bb.x) * scale;
            float v0y = (c[mt][nt][1] + bb.y) * scale;
            float v1x = (c[mt][nt][2] + bb.x) * scale;
            float v1y = (c[mt][nt][3] + bb.y) * scale;
            if (resid) {
                float2 ra = *(const float2*)(resid + (long)row * N + cn);
                float2 rb = *(const float2*)(resid + (long)(row + 8) * N + cn);
                v0x += ra.x; v0y += ra.y; v1x += rb.x; v1y += rb.y;
            }
            if (RELU) {
                v0x = fmaxf(v0x, 0.f); v0y = fmaxf(v0y, 0.f);
                v1x = fmaxf(v1x, 0.f); v1y = fmaxf(v1y, 0.f);
            }
            if (OSPLIT) {
                uint32_t h0, l0, h1, l1;
                pack2(v0x, v0y, h0, l0);
                pack2(v1x, v1y, h1, l1);
                *(uint32_t*)(oH + (long)row * N + cn) = h0;
                *(uint32_t*)(oL + (long)row * N + cn) = l0;
                *(uint32_t*)(oH + (long)(row + 8) * N + cn) = h1;
                *(uint32_t*)(oL + (long)(row + 8) * N + cn) = l1;
            } else {
                *(float2*)(oF + (long)row * N + cn) = make_float2(v0x, v0y);
                *(float2*)(oF + (long)(row + 8) * N + cn) = make_float2(v1x, v1y);
            }
        }
    }
}

// ================= scores: S = Q.K^T per (b,h), CTA 128x128, K=64 =================
#define SC_QH 0
#define SC_QL 18432
#define SC_KH 36864
#define SC_KL 55296
#define SC_SMEM 73728

__global__ __launch_bounds__(256, 1)
void scores_mma(const bf16* __restrict__ qh, const bf16* __restrict__ ql,
                const bf16* __restrict__ kh, const bf16* __restrict__ kl,
                float* __restrict__ sc) {
    extern __shared__ char sm[];
    uint32_t sb = smem_u32(sm);
    int tid = threadIdx.x, wid = tid >> 5, lane = tid & 31;
    int bh = blockIdx.z;
    int b = bh >> 4, h = bh & 15;
    int m0 = blockIdx.y * 128, n0 = blockIdx.x * 128;

#pragma unroll
    for (int i = 0; i < 4; i++) {
        int v = tid + 256 * i;
        int row = v >> 3, c8 = (v & 7) * 8;
        int off = row * 144 + c8 * 2;
        long qg = (long)(b * SEQ + m0 + row) * D_MODEL + h * HEAD_D + c8;
        long kg = (long)(b * SEQ + n0 + row) * D_MODEL + h * HEAD_D + c8;
        *(uint4*)(sm + SC_QH + off) = *(const uint4*)(qh + qg);
        *(uint4*)(sm + SC_QL + off) = *(const uint4*)(ql + qg);
        *(uint4*)(sm + SC_KH + off) = *(const uint4*)(kh + kg);
        *(uint4*)(sm + SC_KL + off) = *(const uint4*)(kl + kg);
    }
    __syncthreads();

    float c[4][4][4];
#pragma unroll
    for (int mt = 0; mt < 4; mt++)
#pragma unroll
        for (int nt = 0; nt < 4; nt++)
#pragma unroll
            for (int f = 0; f < 4; f++) c[mt][nt][f] = 0.f;

    int wm = wid >> 2, wn = wid & 3;
    int rowOff = (lane & 7) + ((lane >> 3) & 1) * 8;
    int colSel = ((lane >> 4) & 1) * 16;

#pragma unroll
    for (int ks = 0; ks < 4; ks++) {
        uint32_t ah[4][4], al[4][4];
#pragma unroll
        for (int mt = 0; mt < 4; mt++) {
            uint32_t ro = (wm * 64 + mt * 16 + rowOff) * 144 + ks * 32 + colSel;
            ldsm_x4(ah[mt], sb + SC_QH + ro);
            ldsm_x4(al[mt], sb + SC_QL + ro);
        }
        uint32_t bh_[2][4], bl_[2][4];
#pragma unroll
        for (int nb = 0; nb < 2; nb++) {
            uint32_t ro = (wn * 32 + nb * 16 + rowOff) * 144 + ks * 32 + colSel;
            ldsm_x4(bh_[nb], sb + SC_KH + ro);
            ldsm_x4(bl_[nb], sb + SC_KL + ro);
        }
#pragma unroll
        for (int mt = 0; mt < 4; mt++)
#pragma unroll
            for (int nt = 0; nt < 4; nt++) {
                int nb = nt >> 1, hf = nt & 1;
                mma16816(c[mt][nt], ah[mt], bh_[nb][hf], bh_[nb][hf + 2]);
            }
#pragma unroll
        for (int mt = 0; mt < 4; mt++)
#pragma unroll
            for (int nt = 0; nt < 4; nt++) {
                int nb = nt >> 1, hf = nt & 1;
                mma16816(c[mt][nt], ah[mt], bl_[nb][hf], bl_[nb][hf + 2]);
            }
#pragma unroll
        for (int mt = 0; mt < 4; mt++)
#pragma unroll
            for (int nt = 0; nt < 4; nt++) {
                int nb = nt >> 1, hf = nt & 1;
                mma16816(c[mt][nt], al[mt], bh_[nb][hf], bh_[nb][hf + 2]);
            }
    }

    long base = (long)bh * SEQ * SEQ;
    int r0 = m0 + wm * 64 + (lane >> 2);
    int col0 = n0 + wn * 32 + (lane & 3) * 2;
#pragma unroll
    for (int mt = 0; mt < 4; mt++)
#pragma unroll
        for (int nt = 0; nt < 4; nt++) {
            int row = r0 + mt * 16, cn = col0 + nt * 8;
            *(float2*)(sc + base + (long)row * SEQ + cn) = make_float2(c[mt][nt][0], c[mt][nt][1]);
            *(float2*)(sc + base + (long)(row + 8) * SEQ + cn) = make_float2(c[mt][nt][2], c[mt][nt][3]);
        }
}

// ================= softmax: fp32 -> split bf16 P =================
__global__ __launch_bounds__(128)
void softmax_kernel(const float* __restrict__ sc, bf16* __restrict__ ph,
                    bf16* __restrict__ pl) {
    __shared__ float redM[4], redS[4];
    const float* row = sc + (size_t)blockIdx.x * SEQ;
    float v[4]; float m = -1e30f;
#pragma unroll
    for (int i = 0; i < 4; i++) { v[i] = row[threadIdx.x + 128 * i]; m = fmaxf(m, v[i]); }
#pragma unroll
    for (int o = 16; o; o >>= 1) m = fmaxf(m, __shfl_xor_sync(~0u, m, o));
    if ((threadIdx.x & 31) == 0) redM[threadIdx.x >> 5] = m;
    __syncthreads();
    m = fmaxf(fmaxf(redM[0], redM[1]), fmaxf(redM[2], redM[3]));
    float s = 0.f;
#pragma unroll
    for (int i = 0; i < 4; i++) { v[i] = expf(v[i] - m); s += v[i]; }
#pragma unroll
    for (int o = 16; o; o >>= 1) s += __shfl_xor_sync(~0u, s, o);
    if ((threadIdx.x & 31) == 0) redS[threadIdx.x >> 5] = s;
    __syncthreads();
    s = redS[0] + redS[1] + redS[2] + redS[3];
    float inv = 1.f / s;
    size_t base = (size_t)blockIdx.x * SEQ;
#pragma unroll
    for (int i = 0; i < 4; i++) {
        float p = v[i] * inv;
        uint16_t hh, ll;
        split2(p, hh, ll);
        int cidx = threadIdx.x + 128 * i;
        ph[base + cidx] = __ushort_as_bfloat16(hh);
        pl[base + cidx] = __ushort_as_bfloat16(ll);
    }
}

// ================= PV: O = P.V per (b,h), CTA 128x64, Kc=32 =================
#define PV_PH 0
#define PV_PL 10240
#define PV_VH 20480
#define PV_VL 24576
#define PV_BUF 28672
#define PV_SMEM (2 * PV_BUF)

__global__ __launch_bounds__(256, 1)
void pv_mma(const bf16* __restrict__ ph, const bf16* __restrict__ pl,
            const bf16* __restrict__ vh, const bf16* __restrict__ vl,
            bf16* __restrict__ oh, bf16* __restrict__ ol) {
    extern __shared__ char sm[];
    uint32_t sb = smem_u32(sm);
    int tid = threadIdx.x, wid = tid >> 5, lane = tid & 31;
    int bh = blockIdx.y;
    int b = bh >> 4, h = bh & 15;
    int m0 = blockIdx.x * 128;

    int v0 = tid, v1 = tid + 256;
    int aR0 = v0 >> 2, aC0 = (v0 & 3) * 8;
    int aR1 = v1 >> 2, aC1 = (v1 & 3) * 8;
    long pBase = (long)bh * SEQ * SEQ;
    long aG0 = pBase + (long)(m0 + aR0) * SEQ + aC0;
    long aG1 = pBase + (long)(m0 + aR1) * SEQ + aC1;
    int aS0 = aR0 * 80 + aC0 * 2;
    int aS1 = aR1 * 80 + aC1 * 2;
    int bKr = tid >> 3, bN0 = (tid & 7) * 8;
    long bG = (long)(b * SEQ + bKr) * D_MODEL + h * HEAD_D + bN0;
    int bS = bKr * 128 + ((bN0 * 2) ^ ((bKr & 7) << 4));

    float c[4][2][4];
#pragma unroll
    for (int mt = 0; mt < 4; mt++)
#pragma unroll
        for (int nt = 0; nt < 2; nt++)
#pragma unroll
            for (int f = 0; f < 4; f++) c[mt][nt][f] = 0.f;

    int wm = wid >> 2, wn = wid & 3;
    int aRowOff = (lane & 7) + ((lane >> 3) & 1) * 8;
    int aColSel = ((lane >> 4) & 1) * 16;
    int bKoff = (lane & 7) + ((lane >> 3) & 1) * 8;
    int bN8 = ((lane >> 4) & 1) * 8;

    uint4 vph0 = *(const uint4*)(ph + aG0), vph1 = *(const uint4*)(ph + aG1);
    uint4 vpl0 = *(const uint4*)(pl + aG0), vpl1 = *(const uint4*)(pl + aG1);
    uint4 vvh = *(const uint4*)(vh + bG);
    uint4 vvl = *(const uint4*)(vl + bG);

    for (int ch = 0; ch < 16; ch++) {
        char* smb = sm + (ch & 1) * PV_BUF;
        uint32_t sbuf = sb + (ch & 1) * PV_BUF;
        __syncthreads();
        *(uint4*)(smb + PV_PH + aS0) = vph0; *(uint4*)(smb + PV_PH + aS1) = vph1;
        *(uint4*)(smb + PV_PL + aS0) = vpl0; *(uint4*)(smb + PV_PL + aS1) = vpl1;
        *(uint4*)(smb + PV_VH + bS) = vvh;
        *(uint4*)(smb + PV_VL + bS) = vvl;
        __syncthreads();
        if (ch < 15) {
            int k0 = (ch + 1) << 5;
            vph0 = *(const uint4*)(ph + aG0 + k0);
            vph1 = *(const uint4*)(ph + aG1 + k0);
            vpl0 = *(const uint4*)(pl + aG0 + k0);
            vpl1 = *(const uint4*)(pl + aG1 + k0);
            vvh = *(const uint4*)(vh + bG + (long)k0 * D_MODEL);
            vvl = *(const uint4*)(vl + bG + (long)k0 * D_MODEL);
        }
#pragma unroll
        for (int ks = 0; ks < 2; ks++) {
            uint32_t ah[4][4], al[4][4];
#pragma unroll
            for (int mt = 0; mt < 4; mt++) {
                uint32_t ro = (wm * 64 + mt * 16 + aRowOff) * 80 + ks * 32 + aColSel;
                ldsm_x4(ah[mt], sbuf + PV_PH + ro);
                ldsm_x4(al[mt], sbuf + PV_PL + ro);
            }
            uint32_t bh_[4], bl_[4];
            {
                int kk = ks * 16 + bKoff;
                int nn = wn * 16 + bN8;
                uint32_t off = kk * 128 + ((nn * 2) ^ ((kk & 7) << 4));
                ldsm_x4t(bh_, sbuf + PV_VH + off);
                ldsm_x4t(bl_, sbuf + PV_VL + off);
            }
#pragma unroll
            for (int mt = 0; mt < 4; mt++)
#pragma unroll
                for (int nt = 0; nt < 2; nt++)
                    mma16816(c[mt][nt], ah[mt], bh_[nt * 2], bh_[nt * 2 + 1]);
#pragma unroll
            for (int mt = 0; mt < 4; mt++)
#pragma unroll
                for (int nt = 0; nt < 2; nt++)
                    mma16816(c[mt][nt], ah[mt], bl_[nt * 2], bl_[nt * 2 + 1]);
#pragma unroll
            for (int mt = 0; mt < 4; mt++)
#pragma unroll
                for (int nt = 0; nt < 2; nt++)
                    mma16816(c[mt][nt], al[mt], bh_[nt * 2], bh_[nt * 2 + 1]);
        }
    }

    int r0 = m0 + wm * 64 + (lane >> 2);
    int col0 = wn * 16 + (lane & 3) * 2;
#pragma unroll
    for (int mt = 0; mt < 4; mt++)
#pragma unroll
        for (int nt = 0; nt < 2; nt++) {
            int row = r0 + mt * 16;
            int cn = col0 + nt * 8;
            long o0 = (long)(b * SEQ + row) * D_MODEL + h * HEAD_D + cn;
            long o1 = (long)(b * SEQ + row + 8) * D_MODEL + h * HEAD_D + cn;
            uint32_t h0, l0, h1, l1;
            pack2(c[mt][nt][0], c[mt][nt][1], h0, l0);
            pack2(c[mt][nt][2], c[mt][nt][3], h1, l1);
            *(uint32_t*)(oh + o0) = h0; *(uint32_t*)(ol + o0) = l0;
            *(uint32_t*)(oh + o1) = h1; *(uint32_t*)(ol + o1) = l1;
        }
}

// ================= LayerNorm -> optional fp32 + split bf16 =================
__global__ void ln_kernel(const float* __restrict__ x, const float* __restrict__ gam,
                          const float* __restrict__ bet, float* __restrict__ outF,
                          bf16* __restrict__ oh, bf16* __restrict__ ol) {
    __shared__ float redA[8], redB[8];
    int t = blockIdx.x;
    const float* xr = x + (size_t)t * D_MODEL;
    float v[4]; float s = 0.f;
#pragma unroll
    for (int i = 0; i < 4; i++) { v[i] = xr[threadIdx.x + 256 * i]; s += v[i]; }
#pragma unroll
    for (int o = 16; o; o >>= 1) s += __shfl_xor_sync(~0u, s, o);
    if ((threadIdx.x & 31) == 0) redA[threadIdx.x >> 5] = s;
    __syncthreads();
    if (threadIdx.x == 0) { float r = 0.f; for (int i = 0; i < 8; i++) r += redA[i]; redA[0] = r; }
    __syncthreads();
    float mu = redA[0] * (1.f / D_MODEL);
    float s2 = 0.f;
#pragma unroll
    for (int i = 0; i < 4; i++) { float d = v[i] - mu; s2 += d * d; }
#pragma unroll
    for (int o = 16; o; o >>= 1) s2 += __shfl_xor_sync(~0u, s2, o);
    if ((threadIdx.x & 31) == 0) redB[threadIdx.x >> 5] = s2;
    __syncthreads();
    if (threadIdx.x == 0) { float r = 0.f; for (int i = 0; i < 8; i++) r += redB[i]; redB[0] = r; }
    __syncthreads();
    float rstd = rsqrtf(redB[0] * (1.f / D_MODEL) + 1e-5f);
    size_t base = (size_t)t * D_MODEL;
#pragma unroll
    for (int i = 0; i < 4; i++) {
        int cc = threadIdx.x + 256 * i;
        float r = (v[i] - mu) * rstd * gam[cc] + bet[cc];
        if (outF) outF[base + cc] = r;
        uint16_t hh, ll;
        split2(r, hh, ll);
        oh[base + cc] = __ushort_as_bfloat16(hh);
        ol[base + cc] = __ushort_as_bfloat16(ll);
    }
}

// ================= router / scan / combine =================
__global__ __launch_bounds__(256)
void router_kernel(const float* __restrict__ h2, const float* __restrict__ wr) {
    int t = blockIdx.x * 8 + (threadIdx.x >> 5);
    int lane = threadIdx.x & 31;
    const float* xr = h2 + (long)t * D_MODEL;
    float acc[8];
#pragma unroll
    for (int e = 0; e < 8; e++) acc[e] = 0.f;
    for (int i = lane; i < D_MODEL; i += 32) {
        float xv = xr[i];
        const float* w = wr + i * 8;
#pragma unroll
        for (int e = 0; e < 8; e++) acc[e] = fmaf(xv, w[e], acc[e]);
    }
#pragma unroll
    for (int o = 16; o; o >>= 1)
#pragma unroll
        for (int e = 0; e < 8; e++) acc[e] += __shfl_xor_sync(~0u, acc[e], o);
    if (lane == 0) {
        float m = acc[0]; int t1 = 0;
#pragma unroll
        for (int e = 1; e < 8; e++) if (acc[e] > m) { m = acc[e]; t1 = e; }
        float s = 0.f, pr[8];
#pragma unroll
        for (int e = 0; e < 8; e++) { pr[e] = expf(acc[e] - m); s += pr[e]; }
        float inv = 1.f / s;
        float m2 = -1e30f; int t2 = 0;
#pragma unroll
        for (int e = 0; e < 8; e++) {
            if (e == t1) continue;
            if (acc[e] > m2) { m2 = acc[e]; t2 = e; }
        }
        g_top1[t] = t1; g_top2[t] = t2;
        g_p1[t] = pr[t1] * inv;
        g_p2[t] = pr[t2] * inv;
    }
}

__global__ __launch_bounds__(256)
void scan_kernel() {
    int tid = threadIdx.x;
    for (int i = tid; i < NEXP * CAPV; i += 256) g_disp[i] = 0;
    __syncthreads();
    int e = tid >> 5;
    int lane = tid & 31;
    unsigned lt = (1u << lane) - 1u;
    int base = 0;
    for (int c0 = 0; c0 < N_TOK; c0 += 32) {
        int t = c0 + lane;
        bool f = (g_top1[t] == e);
        unsigned msk = __ballot_sync(~0u, f);
        if (f) {
            int loc = base + __popc(msk & lt);
            if (loc < CAPV) { g_s1[t] = loc; g_disp[e * CAPV + loc] = t; }
            else g_s1[t] = -1;
        }
        base += __popc(msk);
    }
    for (int c0 = 0; c0 < N_TOK; c0 += 32) {
        int t = c0 + lane;
        bool f = (g_top2[t] == e);
        unsigned msk = __ballot_sync(~0u, f);
        if (f) {
            int loc = base + __popc(msk & lt);
            if (loc < CAPV) { g_s2[t] = loc; g_disp[e * CAPV + loc] = t; }
            else g_s2[t] = -1;
        }
        base += __popc(msk);
    }
    __syncthreads();
    for (int t = tid; t < N_TOK; t += 256) {
        float t1 = (g_s1[t] >= 0) ? g_p1[t] : 0.f;
        float t2 = (g_s2[t] >= 0) ? g_p2[t] : 0.f;
        float den = fmaxf(t1 + t2, 1.1920929e-7f);
        g_g1[t] = t1 / den;
        g_g2[t] = t2 / den;
    }
}

__global__ __launch_bounds__(256)
void combine_kernel(float* __restrict__ out) {
    int t = blockIdx.x;
    int s1 = g_s1[t], s2 = g_s2[t];
    float g1 = g_g1[t], g2 = g_g2[t];
    const float* y1 = (s1 >= 0) ? g_y + ((long)g_top1[t] * CAPV + s1) * D_MODEL : 0;
    const float* y2 = (s2 >= 0) ? g_y + ((long)g_top2[t] * CAPV + s2) * D_MODEL : 0;
    long ro = (long)t * D_MODEL;
#pragma unroll
    for (int i = 0; i < 4; i++) {
        int d = threadIdx.x + 256 * i;
        float a = out[ro + d];
        if (y1) a = fmaf(g1, y1[d], a);
        if (y2) a = fmaf(g2, y2[d], a);
        out[ro + d] = a;
    }
}

// ================= launch =================
extern "C" void kernel_launch(void* const* d_in, const int* in_sizes, int n_in,
                              void* d_out, int out_size) {
    const float* x    = (const float*)d_in[0];
    const float* wq   = (const float*)d_in[1];
    const float* bq   = (const float*)d_in[2];
    const float* wk   = (const float*)d_in[3];
    const float* bk   = (const float*)d_in[4];
    const float* wv   = (const float*)d_in[5];
    const float* bv   = (const float*)d_in[6];
    const float* wo   = (const float*)d_in[7];
    const float* bo   = (const float*)d_in[8];
    const float* ln1g = (const float*)d_in[9];
    const float* ln1b = (const float*)d_in[10];
    const float* ln2g = (const float*)d_in[11];
    const float* ln2b = (const float*)d_in[12];
    const float* wr   = (const float*)d_in[13];
    const float* w1   = (const float*)d_in[14];
    const float* b1   = (const float*)d_in[15];
    const float* w2   = (const float*)d_in[16];
    const float* b2   = (const float*)d_in[17];
    float* out = (float*)d_out;

    bf16 *h1h, *h1l, *h2h, *h2l, *qh, *ql, *kh, *kl, *vh, *vl, *ath, *atl;
    bf16 *midh, *midl, *ph, *pl;
    float *h2, *sc, *y;
    int* disp;
    cudaGetSymbolAddress((void**)&h1h, g_h1h); cudaGetSymbolAddress((void**)&h1l, g_h1l);
    cudaGetSymbolAddress((void**)&h2h, g_h2h); cudaGetSymbolAddress((void**)&h2l, g_h2l);
    cudaGetSymbolAddress((void**)&qh, g_qh);   cudaGetSymbolAddress((void**)&ql, g_ql);
    cudaGetSymbolAddress((void**)&kh, g_kh);   cudaGetSymbolAddress((void**)&kl, g_kl);
    cudaGetSymbolAddress((void**)&vh, g_vh);   cudaGetSymbolAddress((void**)&vl, g_vl);
    cudaGetSymbolAddress((void**)&ath, g_ath); cudaGetSymbolAddress((void**)&atl, g_atl);
    cudaGetSymbolAddress((void**)&midh, g_midh); cudaGetSymbolAddress((void**)&midl, g_midl);
    cudaGetSymbolAddress((void**)&ph, g_ph);   cudaGetSymbolAddress((void**)&pl, g_pl);
    cudaGetSymbolAddress((void**)&h2, g_h2);
    cudaGetSymbolAddress((void**)&sc, g_sc);
    cudaGetSymbolAddress((void**)&y, g_y);
    cudaGetSymbolAddress((void**)&disp, g_disp);

    cudaFuncSetAttribute(gemm_mma<false, false, true, true>,
                         cudaFuncAttributeMaxDynamicSharedMemorySize, GEMM_SMEM);
    cudaFuncSetAttribute(gemm_mma<false, false, false, false>,
                         cudaFuncAttributeMaxDynamicSharedMemorySize, GEMM_SMEM);
    cudaFuncSetAttribute(gemm_mma<true, true, false, true>,
                         cudaFuncAttributeMaxDynamicSharedMemorySize, GEMM_SMEM);
    cudaFuncSetAttribute(scores_mma, cudaFuncAttributeMaxDynamicSharedMemorySize, SC_SMEM);
    cudaFuncSetAttribute(pv_mma, cudaFuncAttributeMaxDynamicSharedMemorySize, PV_SMEM);

    // 1) LN1 -> split (weights consumed as native fp32 inside the GEMMs)
    ln_kernel<<<N_TOK, 256>>>(x, ln1g, ln1b, nullptr, h1h, h1l);

    // 2) QKV fused (B = fp32 wq/wk/wv, split in-kernel)
    gemm_mma<false, false, true, true><<<dim3(8, 16, 3), 256, GEMM_SMEM>>>(
        h1h, h1l, wq, wk, wv, bq, bk, bv,
        nullptr, qh, ql, kh, kl, vh, vl, 0.125f, 1.f, 1.f,
        nullptr, nullptr, 1024, 1024, 0, 0, 0, 0);

    // 3) attention
    scores_mma<<<dim3(4, 4, NB * N_HEADS), 256, SC_SMEM>>>(qh, ql, kh, kl, sc);
    softmax_kernel<<<NB * N_HEADS * SEQ, 128>>>(sc, ph, pl);
    pv_mma<<<dim3(4, NB * N_HEADS), 256, PV_SMEM>>>(ph, pl, vh, vl, ath, atl);

    // 4) O projection + residual -> out (fp32)
    gemm_mma<false, false, false, false><<<dim3(8, 16, 1), 256, GEMM_SMEM>>>(
        ath, atl, wo, nullptr, nullptr, bo, nullptr, nullptr,
        out, nullptr, nullptr, nullptr, nullptr, nullptr, nullptr, 1.f, 0.f, 0.f,
        x, nullptr, 1024, 1024, 0, 0, 0, 0);

    // 5) LN2
    ln_kernel<<<N_TOK, 256>>>(out, ln2g, ln2b, h2, h2h, h2l);

    // 6) router + scan
    router_kernel<<<N_TOK / 8, 256>>>(h2, wr);
    scan_kernel<<<1, 256>>>();

    // 7) FFN1 gathered + relu -> split mid (B = fp32 w1)
    gemm_mma<true, true, false, true><<<dim3(32, 4, 8), 256, GEMM_SMEM>>>(
        h2h, h2l, w1, nullptr, nullptr, b1, nullptr, nullptr,
        nullptr, midh, midl, nullptr, nullptr, nullptr, nullptr, 1.f, 0.f, 0.f,
        nullptr, disp, 1024, 4096, 0, (long)D_MODEL * FFN_D, FFN_D, (long)CAPV * FFN_D);

    // 8) FFN2 -> fp32 y (*0.8)  (B = fp32 w2)
    gemm_mma<false, false, false, false><<<dim3(8, 4, 8), 256, GEMM_SMEM>>>(
        midh, midl, w2, nullptr, nullptr, b2, nullptr, nullptr,
        y, nullptr, nullptr, nullptr, nullptr, nullptr, nullptr, 0.8f, 0.f, 0.f,
        nullptr, nullptr, 4096, 1024,
        (long)CAPV * FFN_D, (long)FFN_D * D_MODEL, D_MODEL, (long)CAPV * D_MODEL);

    // 9) combine
    combine_kernel<<<N_TOK, 256>>>(out);
}

// round 10
// speedup vs baseline: 1.0780x; 1.0780x over previous
#include <cuda_runtime.h>
#include <cuda_bf16.h>
#include <cstdint>

#define D_MODEL 1024
#define N_TOK   2048
#define N_HEADS 16
#define HEAD_D  64
#define SEQ     512
#define NB      4
#define FFN_D   4096
#define NEXP    8
#define CAPV    512

typedef __nv_bfloat16 bf16;

// ================= device scratch =================
__device__ bf16 g_wqh[1048576], g_wql[1048576];
__device__ bf16 g_wkh[1048576], g_wkl[1048576];
__device__ bf16 g_wvh[1048576], g_wvl[1048576];
__device__ bf16 g_woh[1048576], g_wol[1048576];
__device__ bf16 g_w1h[33554432], g_w1l[33554432];
__device__ bf16 g_w2h[33554432], g_w2l[33554432];
__device__ bf16 g_h1h[2097152], g_h1l[2097152];
__device__ bf16 g_h2h[2097152], g_h2l[2097152];
__device__ float g_h2[2097152];
__device__ bf16 g_qh[2097152], g_ql[2097152];
__device__ bf16 g_kh[2097152], g_kl[2097152];
__device__ bf16 g_vh[2097152], g_vl[2097152];
__device__ bf16 g_ath[2097152], g_atl[2097152];
__device__ bf16 g_midh[16777216], g_midl[16777216];
__device__ bf16 g_ph[16777216], g_pl[16777216];
__device__ float g_sc[16777216];
__device__ float g_y[4194304];
__device__ int   g_top1[N_TOK], g_top2[N_TOK];
__device__ float g_p1[N_TOK], g_p2[N_TOK];
__device__ int   g_s1[N_TOK], g_s2[N_TOK];
__device__ float g_g1[N_TOK], g_g2[N_TOK];
__device__ int   g_disp[NEXP * CAPV];

// ================= helpers =================
__device__ __forceinline__ uint32_t smem_u32(const void* p) {
    uint32_t a;
    asm("{ .reg .u64 t; cvta.to.shared.u64 t, %1; cvt.u32.u64 %0, t; }" : "=r"(a) : "l"(p));
    return a;
}
__device__ __forceinline__ void ldsm_x4(uint32_t* r, uint32_t addr) {
    asm volatile("ldmatrix.sync.aligned.m8n8.x4.shared.b16 {%0,%1,%2,%3}, [%4];"
        : "=r"(r[0]), "=r"(r[1]), "=r"(r[2]), "=r"(r[3]) : "r"(addr));
}
__device__ __forceinline__ void ldsm_x4t(uint32_t* r, uint32_t addr) {
    asm volatile("ldmatrix.sync.aligned.m8n8.x4.trans.shared.b16 {%0,%1,%2,%3}, [%4];"
        : "=r"(r[0]), "=r"(r[1]), "=r"(r[2]), "=r"(r[3]) : "r"(addr));
}
__device__ __forceinline__ void mma16816(float* c, const uint32_t* a, uint32_t b0, uint32_t b1) {
    asm volatile(
        "mma.sync.aligned.m16n8k16.row.col.f32.bf16.bf16.f32 "
        "{%0,%1,%2,%3}, {%4,%5,%6,%7}, {%8,%9}, {%0,%1,%2,%3};"
        : "+f"(c[0]), "+f"(c[1]), "+f"(c[2]), "+f"(c[3])
        : "r"(a[0]), "r"(a[1]), "r"(a[2]), "r"(a[3]), "r"(b0), "r"(b1));
}
__device__ __forceinline__ void cp16(uint32_t dst, const void* src) {
    asm volatile("cp.async.cg.shared.global [%0], [%1], 16;" :: "r"(dst), "l"(src) : "memory");
}
#define CP_COMMIT() asm volatile("cp.async.commit_group;" ::: "memory")
__device__ __forceinline__ void split2(float x, uint16_t& h, uint16_t& l) {
    __nv_bfloat16 hb = __float2bfloat16(x);
    float r = x - __bfloat162float(hb);
    h = __bfloat16_as_ushort(hb);
    l = __bfloat16_as_ushort(__float2bfloat16(r));
}
__device__ __forceinline__ void pack2(float x, float y, uint32_t& hi, uint32_t& lo) {
    uint16_t hx, lx, hy, ly;
    split2(x, hx, lx); split2(y, hy, ly);
    hi = (uint32_t)hx | ((uint32_t)hy << 16);
    lo = (uint32_t)lx | ((uint32_t)ly << 16);
}

// ================= weight split passes =================
__global__ __launch_bounds__(256)
void split_pass(const float* __restrict__ src, bf16* __restrict__ hi,
                bf16* __restrict__ lo, long n4) {
    for (long i = blockIdx.x * 256 + threadIdx.x; i < n4; i += (long)gridDim.x * 256) {
        float4 v = *(const float4*)(src + i * 4);
        uint32_t h0, l0, h1, l1;
        pack2(v.x, v.y, h0, l0);
        pack2(v.z, v.w, h1, l1);
        *(uint2*)(hi + i * 4) = make_uint2(h0, h1);
        *(uint2*)(lo + i * 4) = make_uint2(l0, l1);
    }
}

__global__ __launch_bounds__(256)
void split_attn(const float* __restrict__ wq, const float* __restrict__ wk,
                const float* __restrict__ wv, const float* __restrict__ wo,
                bf16* __restrict__ qh, bf16* __restrict__ ql,
                bf16* __restrict__ kh, bf16* __restrict__ kl,
                bf16* __restrict__ vh, bf16* __restrict__ vl,
                bf16* __restrict__ oh, bf16* __restrict__ ol) {
    int z = blockIdx.z;
    const float* src = (z == 0) ? wq : (z == 1) ? wk : (z == 2) ? wv : wo;
    bf16* hi = (z == 0) ? qh : (z == 1) ? kh : (z == 2) ? vh : oh;
    bf16* lo = (z == 0) ? ql : (z == 1) ? kl : (z == 2) ? vl : ol;
    const long n4 = 262144;
    for (long i = blockIdx.x * 256 + threadIdx.x; i < n4; i += (long)gridDim.x * 256) {
        float4 v = *(const float4*)(src + i * 4);
        uint32_t h0, l0, h1, l1;
        pack2(v.x, v.y, h0, l0);
        pack2(v.z, v.w, h1, l1);
        *(uint2*)(hi + i * 4) = make_uint2(h0, h1);
        *(uint2*)(lo + i * 4) = make_uint2(l0, l1);
    }
}

// ================= split-bf16 HMMA GEMM: CTA 128xTN, Kc=32, 3-stage cp.async =================
#define AH_O 0
#define AL_O 10240
#define BH_O 20480

template <int TNv, bool RELU, bool GATHER, bool MULTI, bool OSPLIT>
__global__ __launch_bounds__(256, 1)
void gemm_mma(const bf16* __restrict__ Ah, const bf16* __restrict__ Al,
              const bf16* __restrict__ Bh0, const bf16* __restrict__ Bl0,
              const bf16* __restrict__ Bh1, const bf16* __restrict__ Bl1,
              const bf16* __restrict__ Bh2, const bf16* __restrict__ Bl2,
              const float* __restrict__ bi0, const float* __restrict__ bi1,
              const float* __restrict__ bi2,
              float* __restrict__ oF0,
              bf16* __restrict__ oH0, bf16* __restrict__ oL0,
              bf16* __restrict__ oH1, bf16* __restrict__ oL1,
              bf16* __restrict__ oH2, bf16* __restrict__ oL2,
              float s0, float s1, float s2,
              const float* __restrict__ resid, const int* __restrict__ gather,
              int K, int N,
              long aStride, long bStride, long biStride, long oStride) {
    constexpr int BROW = TNv * 2;
    constexpr int BPLANE = 32 * BROW;
    constexpr int BL_OFS = BH_O + BPLANE;
    constexpr int STGB = BH_O + 2 * BPLANE;
    constexpr int BPT = TNv / 64;
    constexpr int WN = TNv / 4;
    constexpr int NT = WN / 8;
    constexpr int NBF = WN / 16;

    extern __shared__ char sm[];
    uint32_t sb = smem_u32(sm);
    int tid = threadIdx.x, wid = tid >> 5, lane = tid & 31;
    int z = blockIdx.z;
    int m0 = blockIdx.y * 128, n0 = blockIdx.x * TNv;

    const bf16 *Bh, *Bl; const float* bi; float scale;
    float* oF = nullptr; bf16 *oH = nullptr, *oL = nullptr;
    if (MULTI) {
        Bh = (z == 0) ? Bh0 : (z == 1) ? Bh1 : Bh2;
        Bl = (z == 0) ? Bl0 : (z == 1) ? Bl1 : Bl2;
        bi = (z == 0) ? bi0 : (z == 1) ? bi1 : bi2;
        scale = (z == 0) ? s0 : (z == 1) ? s1 : s2;
        oH = (z == 0) ? oH0 : (z == 1) ? oH1 : oH2;
        oL = (z == 0) ? oL0 : (z == 1) ? oL1 : oL2;
    } else {
        Bh = Bh0 + (long)z * bStride;
        Bl = Bl0 + (long)z * bStride;
        bi = bi0 + (long)z * biStride;
        scale = s0;
        if (OSPLIT) { oH = oH0 + (long)z * oStride; oL = oL0 + (long)z * oStride; }
        else oF = oF0 + (long)z * oStride;
    }
    const bf16* Ahz = Ah + (MULTI ? 0 : (long)z * aStride);
    const bf16* Alz = Al + (MULTI ? 0 : (long)z * aStride);
    const int* gz = GATHER ? (gather + z * CAPV) : nullptr;

    // A load mapping (proven TN=128 path)
    int aR0 = tid >> 2, aC0 = (tid & 3) * 8;
    int aR1 = (tid + 256) >> 2, aC1 = ((tid + 256) & 3) * 8;
    long aRow0 = GATHER ? (long)gz[m0 + aR0] : (long)(m0 + aR0);
    long aRow1 = GATHER ? (long)gz[m0 + aR1] : (long)(m0 + aR1);
    long aG0 = aRow0 * K + aC0;
    long aG1 = aRow1 * K + aC1;
    int aD0 = aR0 * 80 + aC0 * 2;
    int aD1 = aR1 * 80 + aC1 * 2;

    // B load mapping
    long bG[BPT]; int bD[BPT];
#pragma unroll
    for (int i = 0; i < BPT; i++) {
        int v = tid + 256 * i;
        int row = (TNv == 256) ? (v >> 5) : (v >> 4);
        int nv  = (TNv == 256) ? (v & 31) : (v & 15);
        bG[i] = (long)row * N + n0 + nv * 8;
        bD[i] = row * BROW + ((nv * 16) ^ ((row & 7) << 4));
    }

    int nCh = K >> 5;
#pragma unroll
    for (int pre = 0; pre < 2; pre++) {
        uint32_t base = sb + (uint32_t)pre * STGB;
        int k0 = pre << 5;
        long ko = (long)k0 * N;
        cp16(base + AH_O + aD0, Ahz + aG0 + k0);
        cp16(base + AH_O + aD1, Ahz + aG1 + k0);
        cp16(base + AL_O + aD0, Alz + aG0 + k0);
        cp16(base + AL_O + aD1, Alz + aG1 + k0);
#pragma unroll
        for (int i = 0; i < BPT; i++) {
            cp16(base + BH_O + bD[i], Bh + ko + bG[i]);
            cp16(base + BL_OFS + bD[i], Bl + ko + bG[i]);
        }
        CP_COMMIT();
    }

    float c[4][NT][4];
#pragma unroll
    for (int mt = 0; mt < 4; mt++)
#pragma unroll
        for (int nt = 0; nt < NT; nt++)
#pragma unroll
            for (int f = 0; f < 4; f++) c[mt][nt][f] = 0.f;

    int wm = wid >> 2, wn = wid & 3;
    int aRowOff = (lane & 7) + ((lane >> 3) & 1) * 8;
    int aColSel = ((lane >> 4) & 1) * 16;
    int bKoff = (lane & 7) + ((lane >> 3) & 1) * 8;
    int bN8 = ((lane >> 4) & 1) * 8;

    for (int ch = 0; ch < nCh; ch++) {
        if (ch + 1 < nCh) asm volatile("cp.async.wait_group 1;" ::: "memory");
        else              asm volatile("cp.async.wait_group 0;" ::: "memory");
        __syncthreads();
        if (ch + 2 < nCh) {
            int chn = ch + 2;
            uint32_t base = sb + (uint32_t)(chn % 3) * STGB;
            int k0 = chn << 5;
            long ko = (long)k0 * N;
            cp16(base + AH_O + aD0, Ahz + aG0 + k0);
            cp16(base + AH_O + aD1, Ahz + aG1 + k0);
            cp16(base + AL_O + aD0, Alz + aG0 + k0);
            cp16(base + AL_O + aD1, Alz + aG1 + k0);
#pragma unroll
            for (int i = 0; i < BPT; i++) {
                cp16(base + BH_O + bD[i], Bh + ko + bG[i]);
                cp16(base + BL_OFS + bD[i], Bl + ko + bG[i]);
            }
            CP_COMMIT();
        }
        uint32_t sbuf = sb + (uint32_t)(ch % 3) * STGB;
#pragma unroll
        for (int ks = 0; ks < 2; ks++) {
            uint32_t ah[4][4], al[4][4];
#pragma unroll
            for (int mt = 0; mt < 4; mt++) {
                uint32_t ro = (wm * 64 + mt * 16 + aRowOff) * 80 + ks * 32 + aColSel;
                ldsm_x4(ah[mt], sbuf + AH_O + ro);
                ldsm_x4(al[mt], sbuf + AL_O + ro);
            }
#pragma unroll
            for (int nb = 0; nb < NBF; nb++) {
                uint32_t bhf[4], blf[4];
                int kk = ks * 16 + bKoff;
                int nn = wn * WN + nb * 16 + bN8;
                uint32_t off = kk * BROW + ((nn * 2) ^ ((kk & 7) << 4));
                ldsm_x4t(bhf, sbuf + BH_O + off);
                ldsm_x4t(blf, sbuf + BL_OFS + off);
#pragma unroll
                for (int hf = 0; hf < 2; hf++) {
                    int nt = nb * 2 + hf;
                    // FIX vs R5/R9: trans-ldsm fragment pairing is consecutive
                    // regs (2hf, 2hf+1), matching every passing TN=128 kernel.
#pragma unroll
                    for (int mt = 0; mt < 4; mt++)
                        mma16816(c[mt][nt], ah[mt], bhf[hf * 2], bhf[hf * 2 + 1]);
#pragma unroll
                    for (int mt = 0; mt < 4; mt++)
                        mma16816(c[mt][nt], ah[mt], blf[hf * 2], blf[hf * 2 + 1]);
#pragma unroll
                    for (int mt = 0; mt < 4; mt++)
                        mma16816(c[mt][nt], al[mt], bhf[hf * 2], bhf[hf * 2 + 1]);
                }
            }
        }
    }

    int r0 = m0 + wm * 64 + (lane >> 2);
    int col0 = n0 + wn * WN + (lane & 3) * 2;
#pragma unroll
    for (int mt = 0; mt < 4; mt++) {
#pragma unroll
        for (int nt = 0; nt < NT; nt++) {
            int row = r0 + mt * 16;
            int cn = col0 + nt * 8;
            float2 bb = *(const float2*)(bi + cn);
            float v0x = (c[mt][nt][0] + bb.x) * scale;
            float v0y = (c[mt][nt][1] + bb.y) * scale;
            float v1x = (c[mt][nt][2] + bb.x) * scale;
            float v1y = (c[mt][nt][3] + bb.y) * scale;
            if (resid) {
                float2 ra = *(const float2*)(resid + (long)row * N + cn);
                float2 rb = *(const float2*)(resid + (long)(row + 8) * N + cn);
                v0x += ra.x; v0y += ra.y; v1x += rb.x; v1y += rb.y;
            }
            if (RELU) {
                v0x = fmaxf(v0x, 0.f); v0y = fmaxf(v0y, 0.f);
                v1x = fmaxf(v1x, 0.f); v1y = fmaxf(v1y, 0.f);
            }
            if (OSPLIT) {
                uint32_t h0, l0, h1, l1;
                pack2(v0x, v0y, h0, l0);
                pack2(v1x, v1y, h1, l1);
                *(uint32_t*)(oH + (long)row * N + cn) = h0;
                *(uint32_t*)(oL + (long)row * N + cn) = l0;
                *(uint32_t*)(oH + (long)(row + 8) * N + cn) = h1;
                *(uint32_t*)(oL + (long)(row + 8) * N + cn) = l1;
            } else {
                *(float2*)(oF + (long)row * N + cn) = make_float2(v0x, v0y);
                *(float2*)(oF + (long)(row + 8) * N + cn) = make_float2(v1x, v1y);
            }
        }
    }
}

// ================= scores: S = Q.K^T per (b,h), CTA 128x128, K=64 =================
#define SC_QH 0
#define SC_QL 18432
#define SC_KH 36864
#define SC_KL 55296
#define SC_SMEM 73728

__global__ __launch_bounds__(256, 1)
void scores_mma(const bf16* __restrict__ qh, const bf16* __restrict__ ql,
                const bf16* __restrict__ kh, const bf16* __restrict__ kl,
                float* __restrict__ sc) {
    extern __shared__ char sm[];
    uint32_t sb = smem_u32(sm);
    int tid = threadIdx.x, wid = tid >> 5, lane = tid & 31;
    int bh = blockIdx.z;
    int b = bh >> 4, h = bh & 15;
    int m0 = blockIdx.y * 128, n0 = blockIdx.x * 128;

#pragma unroll
    for (int i = 0; i < 4; i++) {
        int v = tid + 256 * i;
        int row = v >> 3, c8 = (v & 7) * 8;
        int off = row * 144 + c8 * 2;
        long qg = (long)(b * SEQ + m0 + row) * D_MODEL + h * HEAD_D + c8;
        long kg = (long)(b * SEQ + n0 + row) * D_MODEL + h * HEAD_D + c8;
        *(uint4*)(sm + SC_QH + off) = *(const uint4*)(qh + qg);
        *(uint4*)(sm + SC_QL + off) = *(const uint4*)(ql + qg);
        *(uint4*)(sm + SC_KH + off) = *(const uint4*)(kh + kg);
        *(uint4*)(sm + SC_KL + off) = *(const uint4*)(kl + kg);
    }
    __syncthreads();

    float c[4][4][4];
#pragma unroll
    for (int mt = 0; mt < 4; mt++)
#pragma unroll
        for (int nt = 0; nt < 4; nt++)
#pragma unroll
            for (int f = 0; f < 4; f++) c[mt][nt][f] = 0.f;

    int wm = wid >> 2, wn = wid & 3;
    int rowOff = (lane & 7) + ((lane >> 3) & 1) * 8;
    int colSel = ((lane >> 4) & 1) * 16;

#pragma unroll
    for (int ks = 0; ks < 4; ks++) {
        uint32_t ah[4][4], al[4][4];
#pragma unroll
        for (int mt = 0; mt < 4; mt++) {
            uint32_t ro = (wm * 64 + mt * 16 + rowOff) * 144 + ks * 32 + colSel;
            ldsm_x4(ah[mt], sb + SC_QH + ro);
            ldsm_x4(al[mt], sb + SC_QL + ro);
        }
        uint32_t bh_[2][4], bl_[2][4];
#pragma unroll
        for (int nb = 0; nb < 2; nb++) {
            uint32_t ro = (wn * 32 + nb * 16 + rowOff) * 144 + ks * 32 + colSel;
            ldsm_x4(bh_[nb], sb + SC_KH + ro);
            ldsm_x4(bl_[nb], sb + SC_KL + ro);
        }
#pragma unroll
        for (int mt = 0; mt < 4; mt++)
#pragma unroll
            for (int nt = 0; nt < 4; nt++) {
                int nb = nt >> 1, hf = nt & 1;
                mma16816(c[mt][nt], ah[mt], bh_[nb][hf], bh_[nb][hf + 2]);
            }
#pragma unroll
        for (int mt = 0; mt < 4; mt++)
#pragma unroll
            for (int nt = 0; nt < 4; nt++) {
                int nb = nt >> 1, hf = nt & 1;
                mma16816(c[mt][nt], ah[mt], bl_[nb][hf], bl_[nb][hf + 2]);
            }
#pragma unroll
        for (int mt = 0; mt < 4; mt++)
#pragma unroll
            for (int nt = 0; nt < 4; nt++) {
                int nb = nt >> 1, hf = nt & 1;
                mma16816(c[mt][nt], al[mt], bh_[nb][hf], bh_[nb][hf + 2]);
            }
    }

    long base = (long)bh * SEQ * SEQ;
    int r0 = m0 + wm * 64 + (lane >> 2);
    int col0 = n0 + wn * 32 + (lane & 3) * 2;
#pragma unroll
    for (int mt = 0; mt < 4; mt++)
#pragma unroll
        for (int nt = 0; nt < 4; nt++) {
            int row = r0 + mt * 16, cn = col0 + nt * 8;
            *(float2*)(sc + base + (long)row * SEQ + cn) = make_float2(c[mt][nt][0], c[mt][nt][1]);
            *(float2*)(sc + base + (long)(row + 8) * SEQ + cn) = make_float2(c[mt][nt][2], c[mt][nt][3]);
        }
}

// ================= softmax: fp32 -> split bf16 P =================
__global__ __launch_bounds__(128)
void softmax_kernel(const float* __restrict__ sc, bf16* __restrict__ ph,
                    bf16* __restrict__ pl) {
    __shared__ float redM[4], redS[4];
    const float* row = sc + (size_t)blockIdx.x * SEQ;
    float v[4]; float m = -1e30f;
#pragma unroll
    for (int i = 0; i < 4; i++) { v[i] = row[threadIdx.x + 128 * i]; m = fmaxf(m, v[i]); }
#pragma unroll
    for (int o = 16; o; o >>= 1) m = fmaxf(m, __shfl_xor_sync(~0u, m, o));
    if ((threadIdx.x & 31) == 0) redM[threadIdx.x >> 5] = m;
    __syncthreads();
    m = fmaxf(fmaxf(redM[0], redM[1]), fmaxf(redM[2], redM[3]));
    float s = 0.f;
#pragma unroll
    for (int i = 0; i < 4; i++) { v[i] = expf(v[i] - m); s += v[i]; }
#pragma unroll
    for (int o = 16; o; o >>= 1) s += __shfl_xor_sync(~0u, s, o);
    if ((threadIdx.x & 31) == 0) redS[threadIdx.x >> 5] = s;
    __syncthreads();
    s = redS[0] + redS[1] + redS[2] + redS[3];
    float inv = 1.f / s;
    size_t base = (size_t)blockIdx.x * SEQ;
#pragma unroll
    for (int i = 0; i < 4; i++) {
        float p = v[i] * inv;
        uint16_t hh, ll;
        split2(p, hh, ll);
        int cidx = threadIdx.x + 128 * i;
        ph[base + cidx] = __ushort_as_bfloat16(hh);
        pl[base + cidx] = __ushort_as_bfloat16(ll);
    }
}

// ================= PV: O = P.V per (b,h), CTA 128x64, Kc=32 =================
#define PV_PH 0
#define PV_PL 10240
#define PV_VH 20480
#define PV_VL 24576
#define PV_BUF 28672
#define PV_SMEM (2 * PV_BUF)

__global__ __launch_bounds__(256, 1)
void pv_mma(const bf16* __restrict__ ph, const bf16* __restrict__ pl,
            const bf16* __restrict__ vh, const bf16* __restrict__ vl,
            bf16* __restrict__ oh, bf16* __restrict__ ol) {
    extern __shared__ char sm[];
    uint32_t sb = smem_u32(sm);
    int tid = threadIdx.x, wid = tid >> 5, lane = tid & 31;
    int bh = blockIdx.y;
    int b = bh >> 4, h = bh & 15;
    int m0 = blockIdx.x * 128;

    int v0 = tid, v1 = tid + 256;
    int aR0 = v0 >> 2, aC0 = (v0 & 3) * 8;
    int aR1 = v1 >> 2, aC1 = (v1 & 3) * 8;
    long pBase = (long)bh * SEQ * SEQ;
    long aG0 = pBase + (long)(m0 + aR0) * SEQ + aC0;
    long aG1 = pBase + (long)(m0 + aR1) * SEQ + aC1;
    int aS0 = aR0 * 80 + aC0 * 2;
    int aS1 = aR1 * 80 + aC1 * 2;
    int bKr = tid >> 3, bN0 = (tid & 7) * 8;
    long bG = (long)(b * SEQ + bKr) * D_MODEL + h * HEAD_D + bN0;
    int bS = bKr * 128 + ((bN0 * 2) ^ ((bKr & 7) << 4));

    float c[4][2][4];
#pragma unroll
    for (int mt = 0; mt < 4; mt++)
#pragma unroll
        for (int nt = 0; nt < 2; nt++)
#pragma unroll
            for (int f = 0; f < 4; f++) c[mt][nt][f] = 0.f;

    int wm = wid >> 2, wn = wid & 3;
    int aRowOff = (lane & 7) + ((lane >> 3) & 1) * 8;
    int aColSel = ((lane >> 4) & 1) * 16;
    int bKoff = (lane & 7) + ((lane >> 3) & 1) * 8;
    int bN8 = ((lane >> 4) & 1) * 8;

    uint4 vph0 = *(const uint4*)(ph + aG0), vph1 = *(const uint4*)(ph + aG1);
    uint4 vpl0 = *(const uint4*)(pl + aG0), vpl1 = *(const uint4*)(pl + aG1);
    uint4 vvh = *(const uint4*)(vh + bG);
    uint4 vvl = *(const uint4*)(vl + bG);

    for (int ch = 0; ch < 16; ch++) {
        char* smb = sm + (ch & 1) * PV_BUF;
        uint32_t sbuf = sb + (ch & 1) * PV_BUF;
        __syncthreads();
        *(uint4*)(smb + PV_PH + aS0) = vph0; *(uint4*)(smb + PV_PH + aS1) = vph1;
        *(uint4*)(smb + PV_PL + aS0) = vpl0; *(uint4*)(smb + PV_PL + aS1) = vpl1;
        *(uint4*)(smb + PV_VH + bS) = vvh;
        *(uint4*)(smb + PV_VL + bS) = vvl;
        __syncthreads();
        if (ch < 15) {
            int k0 = (ch + 1) << 5;
            vph0 = *(const uint4*)(ph + aG0 + k0);
            vph1 = *(const uint4*)(ph + aG1 + k0);
            vpl0 = *(const uint4*)(pl + aG0 + k0);
            vpl1 = *(const uint4*)(pl + aG1 + k0);
            vvh = *(const uint4*)(vh + bG + (long)k0 * D_MODEL);
            vvl = *(const uint4*)(vl + bG + (long)k0 * D_MODEL);
        }
#pragma unroll
        for (int ks = 0; ks < 2; ks++) {
            uint32_t ah[4][4], al[4][4];
#pragma unroll
            for (int mt = 0; mt < 4; mt++) {
                uint32_t ro = (wm * 64 + mt * 16 + aRowOff) * 80 + ks * 32 + aColSel;
                ldsm_x4(ah[mt], sbuf + PV_PH + ro);
                ldsm_x4(al[mt], sbuf + PV_PL + ro);
            }
            uint32_t bh_[4], bl_[4];
            {
                int kk = ks * 16 + bKoff;
                int nn = wn * 16 + bN8;
                uint32_t off = kk * 128 + ((nn * 2) ^ ((kk & 7) << 4));
                ldsm_x4t(bh_, sbuf + PV_VH + off);
                ldsm_x4t(bl_, sbuf + PV_VL + off);
            }
#pragma unroll
            for (int mt = 0; mt < 4; mt++)
#pragma unroll
                for (int nt = 0; nt < 2; nt++)
                    mma16816(c[mt][nt], ah[mt], bh_[nt * 2], bh_[nt * 2 + 1]);
#pragma unroll
            for (int mt = 0; mt < 4; mt++)
#pragma unroll
                for (int nt = 0; nt < 2; nt++)
                    mma16816(c[mt][nt], ah[mt], bl_[nt * 2], bl_[nt * 2 + 1]);
#pragma unroll
            for (int mt = 0; mt < 4; mt++)
#pragma unroll
                for (int nt = 0; nt < 2; nt++)
                    mma16816(c[mt][nt], al[mt], bh_[nt * 2], bh_[nt * 2 + 1]);
        }
    }

    int r0 = m0 + wm * 64 + (lane >> 2);
    int col0 = wn * 16 + (lane & 3) * 2;
#pragma unroll
    for (int mt = 0; mt < 4; mt++)
#pragma unroll
        for (int nt = 0; nt < 2; nt++) {
            int row = r0 + mt * 16;
            int cn = col0 + nt * 8;
            long o0 = (long)(b * SEQ + row) * D_MODEL + h * HEAD_D + cn;
            long o1 = (long)(b * SEQ + row + 8) * D_MODEL + h * HEAD_D + cn;
            uint32_t h0, l0, h1, l1;
            pack2(c[mt][nt][0], c[mt][nt][1], h0, l0);
            pack2(c[mt][nt][2], c[mt][nt][3], h1, l1);
            *(uint32_t*)(oh + o0) = h0; *(uint32_t*)(ol + o0) = l0;
            *(uint32_t*)(oh + o1) = h1; *(uint32_t*)(ol + o1) = l1;
        }
}

// ================= LayerNorm -> optional fp32 + split bf16 =================
__global__ void ln_kernel(const float* __restrict__ x, const float* __restrict__ gam,
                          const float* __restrict__ bet, float* __restrict__ outF,
                          bf16* __restrict__ oh, bf16* __restrict__ ol) {
    __shared__ float redA[8], redB[8];
    int t = blockIdx.x;
    const float* xr = x + (size_t)t * D_MODEL;
    float v[4]; float s = 0.f;
#pragma unroll
    for (int i = 0; i < 4; i++) { v[i] = xr[threadIdx.x + 256 * i]; s += v[i]; }
#pragma unroll
    for (int o = 16; o; o >>= 1) s += __shfl_xor_sync(~0u, s, o);
    if ((threadIdx.x & 31) == 0) redA[threadIdx.x >> 5] = s;
    __syncthreads();
    if (threadIdx.x == 0) { float r = 0.f; for (int i = 0; i < 8; i++) r += redA[i]; redA[0] = r; }
    __syncthreads();
    float mu = redA[0] * (1.f / D_MODEL);
    float s2 = 0.f;
#pragma unroll
    for (int i = 0; i < 4; i++) { float d = v[i] - mu; s2 += d * d; }
#pragma unroll
    for (int o = 16; o; o >>= 1) s2 += __shfl_xor_sync(~0u, s2, o);
    if ((threadIdx.x & 31) == 0) redB[threadIdx.x >> 5] = s2;
    __syncthreads();
    if (threadIdx.x == 0) { float r = 0.f; for (int i = 0; i < 8; i++) r += redB[i]; redB[0] = r; }
    __syncthreads();
    float rstd = rsqrtf(redB[0] * (1.f / D_MODEL) + 1e-5f);
    size_t base = (size_t)t * D_MODEL;
#pragma unroll
    for (int i = 0; i < 4; i++) {
        int cc = threadIdx.x + 256 * i;
        float r = (v[i] - mu) * rstd * gam[cc] + bet[cc];
        if (outF) outF[base + cc] = r;
        uint16_t hh, ll;
        split2(r, hh, ll);
        oh[base + cc] = __ushort_as_bfloat16(hh);
        ol[base + cc] = __ushort_as_bfloat16(ll);
    }
}

// ================= router / scan / combine =================
__global__ __launch_bounds__(256)
void router_kernel(const float* __restrict__ h2, const float* __restrict__ wr) {
    int t = blockIdx.x * 8 + (threadIdx.x >> 5);
    int lane = threadIdx.x & 31;
    const float* xr = h2 + (long)t * D_MODEL;
    float acc[8];
#pragma unroll
    for (int e = 0; e < 8; e++) acc[e] = 0.f;
    for (int i = lane; i < D_MODEL; i += 32) {
        float xv = xr[i];
        const float* w = wr + i * 8;
#pragma unroll
        for (int e = 0; e < 8; e++) acc[e] = fmaf(xv, w[e], acc[e]);
    }
#pragma unroll
    for (int o = 16; o; o >>= 1)
#pragma unroll
        for (int e = 0; e < 8; e++) acc[e] += __shfl_xor_sync(~0u, acc[e], o);
    if (lane == 0) {
        float m = acc[0]; int t1 = 0;
#pragma unroll
        for (int e = 1; e < 8; e++) if (acc[e] > m) { m = acc[e]; t1 = e; }
        float s = 0.f, pr[8];
#pragma unroll
        for (int e = 0; e < 8; e++) { pr[e] = expf(acc[e] - m); s += pr[e]; }
        float inv = 1.f / s;
        float m2 = -1e30f; int t2 = 0;
#pragma unroll
        for (int e = 0; e < 8; e++) {
            if (e == t1) continue;
            if (acc[e] > m2) { m2 = acc[e]; t2 = e; }
        }
        g_top1[t] = t1; g_top2[t] = t2;
        g_p1[t] = pr[t1] * inv;
        g_p2[t] = pr[t2] * inv;
    }
}

__global__ __launch_bounds__(256)
void scan_kernel() {
    int tid = threadIdx.x;
    for (int i = tid; i < NEXP * CAPV; i += 256) g_disp[i] = 0;
    __syncthreads();
    int e = tid >> 5;
    int lane = tid & 31;
    unsigned lt = (1u << lane) - 1u;
    int base = 0;
    for (int c0 = 0; c0 < N_TOK; c0 += 32) {
        int t = c0 + lane;
        bool f = (g_top1[t] == e);
        unsigned msk = __ballot_sync(~0u, f);
        if (f) {
            int loc = base + __popc(msk & lt);
            if (loc < CAPV) { g_s1[t] = loc; g_disp[e * CAPV + loc] = t; }
            else g_s1[t] = -1;
        }
        base += __popc(msk);
    }
    for (int c0 = 0; c0 < N_TOK; c0 += 32) {
        int t = c0 + lane;
        bool f = (g_top2[t] == e);
        unsigned msk = __ballot_sync(~0u, f);
        if (f) {
            int loc = base + __popc(msk & lt);
            if (loc < CAPV) { g_s2[t] = loc; g_disp[e * CAPV + loc] = t; }
            else g_s2[t] = -1;
        }
        base += __popc(msk);
    }
    __syncthreads();
    for (int t = tid; t < N_TOK; t += 256) {
        float t1 = (g_s1[t] >= 0) ? g_p1[t] : 0.f;
        float t2 = (g_s2[t] >= 0) ? g_p2[t] : 0.f;
        float den = fmaxf(t1 + t2, 1.1920929e-7f);
        g_g1[t] = t1 / den;
        g_g2[t] = t2 / den;
    }
}

__global__ __launch_bounds__(256)
void combine_kernel(float* __restrict__ out) {
    int t = blockIdx.x;
    int s1 = g_s1[t], s2 = g_s2[t];
    float g1 = g_g1[t], g2 = g_g2[t];
    const float* y1 = (s1 >= 0) ? g_y + ((long)g_top1[t] * CAPV + s1) * D_MODEL : 0;
    const float* y2 = (s2 >= 0) ? g_y + ((long)g_top2[t] * CAPV + s2) * D_MODEL : 0;
    long ro = (long)t * D_MODEL;
#pragma unroll
    for (int i = 0; i < 4; i++) {
        int d = threadIdx.x + 256 * i;
        float a = out[ro + d];
        if (y1) a = fmaf(g1, y1[d], a);
        if (y2) a = fmaf(g2, y2[d], a);
        out[ro + d] = a;
    }
}

// ================= launch =================
extern "C" void kernel_launch(void* const* d_in, const int* in_sizes, int n_in,
                              void* d_out, int out_size) {
    const float* x    = (const float*)d_in[0];
    const float* wq   = (const float*)d_in[1];
    const float* bq   = (const float*)d_in[2];
    const float* wk   = (const float*)d_in[3];
    const float* bk   = (const float*)d_in[4];
    const float* wv   = (const float*)d_in[5];
    const float* bv   = (const float*)d_in[6];
    const float* wo   = (const float*)d_in[7];
    const float* bo   = (const float*)d_in[8];
    const float* ln1g = (const float*)d_in[9];
    const float* ln1b = (const float*)d_in[10];
    const float* ln2g = (const float*)d_in[11];
    const float* ln2b = (const float*)d_in[12];
    const float* wr   = (const float*)d_in[13];
    const float* w1   = (const float*)d_in[14];
    const float* b1   = (const float*)d_in[15];
    const float* w2   = (const float*)d_in[16];
    const float* b2   = (const float*)d_in[17];
    float* out = (float*)d_out;

    bf16 *wqh, *wql, *wkh, *wkl, *wvh, *wvl, *woh, *wol, *w1h, *w1l, *w2h, *w2l;
    bf16 *h1h, *h1l, *h2h, *h2l, *qh, *ql, *kh, *kl, *vh, *vl, *ath, *atl;
    bf16 *midh, *midl, *ph, *pl;
    float *h2, *sc, *y;
    int* disp;
    cudaGetSymbolAddress((void**)&wqh, g_wqh); cudaGetSymbolAddress((void**)&wql, g_wql);
    cudaGetSymbolAddress((void**)&wkh, g_wkh); cudaGetSymbolAddress((void**)&wkl, g_wkl);
    cudaGetSymbolAddress((void**)&wvh, g_wvh); cudaGetSymbolAddress((void**)&wvl, g_wvl);
    cudaGetSymbolAddress((void**)&woh, g_woh); cudaGetSymbolAddress((void**)&wol, g_wol);
    cudaGetSymbolAddress((void**)&w1h, g_w1h); cudaGetSymbolAddress((void**)&w1l, g_w1l);
    cudaGetSymbolAddress((void**)&w2h, g_w2h); cudaGetSymbolAddress((void**)&w2l, g_w2l);
    cudaGetSymbolAddress((void**)&h1h, g_h1h); cudaGetSymbolAddress((void**)&h1l, g_h1l);
    cudaGetSymbolAddress((void**)&h2h, g_h2h); cudaGetSymbolAddress((void**)&h2l, g_h2l);
    cudaGetSymbolAddress((void**)&qh, g_qh);   cudaGetSymbolAddress((void**)&ql, g_ql);
    cudaGetSymbolAddress((void**)&kh, g_kh);   cudaGetSymbolAddress((void**)&kl, g_kl);
    cudaGetSymbolAddress((void**)&vh, g_vh);   cudaGetSymbolAddress((void**)&vl, g_vl);
    cudaGetSymbolAddress((void**)&ath, g_ath); cudaGetSymbolAddress((void**)&atl, g_atl);
    cudaGetSymbolAddress((void**)&midh, g_midh); cudaGetSymbolAddress((void**)&midl, g_midl);
    cudaGetSymbolAddress((void**)&ph, g_ph);   cudaGetSymbolAddress((void**)&pl, g_pl);
    cudaGetSymbolAddress((void**)&h2, g_h2);
    cudaGetSymbolAddress((void**)&sc, g_sc);
    cudaGetSymbolAddress((void**)&y, g_y);
    cudaGetSymbolAddress((void**)&disp, g_disp);

    constexpr int SMEM128 = 3 * 36864;   // 110592
    constexpr int SMEM256 = 3 * 53248;   // 159744
    cudaFuncSetAttribute(gemm_mma<128, false, false, true, true>,
                         cudaFuncAttributeMaxDynamicSharedMemorySize, SMEM128);
    cudaFuncSetAttribute(gemm_mma<128, false, false, false, false>,
                         cudaFuncAttributeMaxDynamicSharedMemorySize, SMEM128);
    cudaFuncSetAttribute(gemm_mma<256, true, true, false, true>,
                         cudaFuncAttributeMaxDynamicSharedMemorySize, SMEM256);
    cudaFuncSetAttribute(gemm_mma<256, false, false, false, false>,
                         cudaFuncAttributeMaxDynamicSharedMemorySize, SMEM256);
    cudaFuncSetAttribute(scores_mma, cudaFuncAttributeMaxDynamicSharedMemorySize, SC_SMEM);
    cudaFuncSetAttribute(pv_mma, cudaFuncAttributeMaxDynamicSharedMemorySize, PV_SMEM);

    // 0) weight splits
    split_attn<<<dim3(256, 1, 4), 256>>>(wq, wk, wv, wo, wqh, wql, wkh, wkl,
                                         wvh, wvl, woh, wol);
    split_pass<<<2048, 256>>>(w1, w1h, w1l, 33554432 / 8);
    split_pass<<<2048, 256>>>(w1 + 16777216, w1h + 16777216, w1l + 16777216, 33554432 / 8);
    split_pass<<<4096, 256>>>(w2, w2h, w2l, 33554432 / 4);

    // 1) LN1 -> split
    ln_kernel<<<N_TOK, 256>>>(x, ln1g, ln1b, nullptr, h1h, h1l);

    // 2) QKV fused (TN=128, proven)
    gemm_mma<128, false, false, true, true><<<dim3(8, 16, 3), 256, SMEM128>>>(
        h1h, h1l, wqh, wql, wkh, wkl, wvh, wvl, bq, bk, bv,
        nullptr, qh, ql, kh, kl, vh, vl, 0.125f, 1.f, 1.f,
        nullptr, nullptr, 1024, 1024, 0, 0, 0, 0);

    // 3) attention
    scores_mma<<<dim3(4, 4, NB * N_HEADS), 256, SC_SMEM>>>(qh, ql, kh, kl, sc);
    softmax_kernel<<<NB * N_HEADS * SEQ, 128>>>(sc, ph, pl);
    pv_mma<<<dim3(4, NB * N_HEADS), 256, PV_SMEM>>>(ph, pl, vh, vl, ath, atl);

    // 4) O projection + residual (TN=128, proven)
    gemm_mma<128, false, false, false, false><<<dim3(8, 16, 1), 256, SMEM128>>>(
        ath, atl, woh, wol, nullptr, nullptr, nullptr, nullptr, bo, nullptr, nullptr,
        out, nullptr, nullptr, nullptr, nullptr, nullptr, nullptr, 1.f, 0.f, 0.f,
        x, nullptr, 1024, 1024, 0, 0, 0, 0);

    // 5) LN2
    ln_kernel<<<N_TOK, 256>>>(out, ln2g, ln2b, h2, h2h, h2l);

    // 6) router + scan
    router_kernel<<<N_TOK / 8, 256>>>(h2, wr);
    scan_kernel<<<1, 256>>>();

    // 7) FFN1 gathered + relu -> split mid (TN=256: warp 64x64)
    gemm_mma<256, true, true, false, true><<<dim3(16, 4, 8), 256, SMEM256>>>(
        h2h, h2l, w1h, w1l, nullptr, nullptr, nullptr, nullptr, b1, nullptr, nullptr,
        nullptr, midh, midl, nullptr, nullptr, nullptr, nullptr, 1.f, 0.f, 0.f,
        nullptr, disp, 1024, 4096, 0, (long)D_MODEL * FFN_D, FFN_D, (long)CAPV * FFN_D);

    // 8) FFN2 -> fp32 y (*0.8) (TN=256)
    gemm_mma<256, false, false, false, false><<<dim3(4, 4, 8), 256, SMEM256>>>(
        midh, midl, w2h, w2l, nullptr, nullptr, nullptr, nullptr, b2, nullptr, nullptr,
        y, nullptr, nullptr, nullptr, nullptr, nullptr, nullptr, 0.8f, 0.f, 0.f,
        nullptr, nullptr, 4096, 1024,
        (long)CAPV * FFN_D, (long)FFN_D * D_MODEL, D_MODEL, (long)CAPV * D_MODEL);

    // 9) combine
    combine_kernel<<<N_TOK, 256>>>(out);
}

// round 11
// speedup vs baseline: 1.3842x; 1.2840x over previous
#include <cuda_runtime.h>
#include <cuda_fp16.h>
#include <cstdint>

#define D_MODEL 1024
#define N_TOK   2048
#define N_HEADS 16
#define HEAD_D  64
#define SEQ     512
#define NB      4
#define FFN_D   4096
#define NEXP    8
#define CAPV    512

typedef __half hf;

// ================= device scratch =================
__device__ hf g_wq1[1048576], g_wk1[1048576], g_wv1[1048576], g_wo1[1048576];
__device__ hf g_w11[33554432], g_w21[33554432];
__device__ hf g_h1h[2097152], g_h1l[2097152];
__device__ hf g_h2h[2097152], g_h2l[2097152];
__device__ float g_h2[2097152];
__device__ hf g_qh[2097152], g_ql[2097152];
__device__ hf g_kh[2097152];
__device__ hf g_vh[2097152];
__device__ hf g_ath[2097152], g_atl[2097152];
__device__ hf g_midh[16777216], g_midl[16777216];
__device__ hf g_ph[16777216], g_pl[16777216];
__device__ float g_sc[16777216];
__device__ float g_y[4194304];
__device__ int   g_top1[N_TOK], g_top2[N_TOK];
__device__ float g_p1[N_TOK], g_p2[N_TOK];
__device__ int   g_s1[N_TOK], g_s2[N_TOK];
__device__ float g_g1[N_TOK], g_g2[N_TOK];
__device__ int   g_disp[NEXP * CAPV];

// ================= helpers =================
__device__ __forceinline__ uint32_t smem_u32(const void* p) {
    uint32_t a;
    asm("{ .reg .u64 t; cvta.to.shared.u64 t, %1; cvt.u32.u64 %0, t; }" : "=r"(a) : "l"(p));
    return a;
}
__device__ __forceinline__ void ldsm_x4(uint32_t* r, uint32_t addr) {
    asm volatile("ldmatrix.sync.aligned.m8n8.x4.shared.b16 {%0,%1,%2,%3}, [%4];"
        : "=r"(r[0]), "=r"(r[1]), "=r"(r[2]), "=r"(r[3]) : "r"(addr));
}
__device__ __forceinline__ void ldsm_x4t(uint32_t* r, uint32_t addr) {
    asm volatile("ldmatrix.sync.aligned.m8n8.x4.trans.shared.b16 {%0,%1,%2,%3}, [%4];"
        : "=r"(r[0]), "=r"(r[1]), "=r"(r[2]), "=r"(r[3]) : "r"(addr));
}
__device__ __forceinline__ void mma16816(float* c, const uint32_t* a, uint32_t b0, uint32_t b1) {
    asm volatile(
        "mma.sync.aligned.m16n8k16.row.col.f32.f16.f16.f32 "
        "{%0,%1,%2,%3}, {%4,%5,%6,%7}, {%8,%9}, {%0,%1,%2,%3};"
        : "+f"(c[0]), "+f"(c[1]), "+f"(c[2]), "+f"(c[3])
        : "r"(a[0]), "r"(a[1]), "r"(a[2]), "r"(a[3]), "r"(b0), "r"(b1));
}
__device__ __forceinline__ void cp16(uint32_t dst, const void* src) {
    asm volatile("cp.async.cg.shared.global [%0], [%1], 16;" :: "r"(dst), "l"(src) : "memory");
}
#define CP_COMMIT() asm volatile("cp.async.commit_group;" ::: "memory")
__device__ __forceinline__ void split2(float x, uint16_t& h, uint16_t& l) {
    __half hb = __float2half_rn(x);
    float r = x - __half2float(hb);
    h = __half_as_ushort(hb);
    l = __half_as_ushort(__float2half_rn(r));
}
__device__ __forceinline__ void pack2(float x, float y, uint32_t& hi, uint32_t& lo) {
    uint16_t hx, lx, hy, ly;
    split2(x, hx, lx); split2(y, hy, ly);
    hi = (uint32_t)hx | ((uint32_t)hy << 16);
    lo = (uint32_t)lx | ((uint32_t)ly << 16);
}
__device__ __forceinline__ uint32_t pack2s(float x, float y) {
    return (uint32_t)__half_as_ushort(__float2half_rn(x)) |
           ((uint32_t)__half_as_ushort(__float2half_rn(y)) << 16);
}

// ================= weight rounding passes (single fp16 plane) =================
__global__ __launch_bounds__(256)
void round_pass(const float* __restrict__ src, hf* __restrict__ dst, long n4) {
    for (long i = blockIdx.x * 256 + threadIdx.x; i < n4; i += (long)gridDim.x * 256) {
        float4 v = *(const float4*)(src + i * 4);
        *(uint2*)(dst + i * 4) = make_uint2(pack2s(v.x, v.y), pack2s(v.z, v.w));
    }
}

__global__ __launch_bounds__(256)
void round_attn(const float* __restrict__ wq, const float* __restrict__ wk,
                const float* __restrict__ wv, const float* __restrict__ wo,
                hf* __restrict__ q1, hf* __restrict__ k1,
                hf* __restrict__ v1, hf* __restrict__ o1) {
    int z = blockIdx.z;
    const float* src = (z == 0) ? wq : (z == 1) ? wk : (z == 2) ? wv : wo;
    hf* dst = (z == 0) ? q1 : (z == 1) ? k1 : (z == 2) ? v1 : o1;
    const long n4 = 262144;
    for (long i = blockIdx.x * 256 + threadIdx.x; i < n4; i += (long)gridDim.x * 256) {
        float4 v = *(const float4*)(src + i * 4);
        *(uint2*)(dst + i * 4) = make_uint2(pack2s(v.x, v.y), pack2s(v.z, v.w));
    }
}

// ================= split-fp16 HMMA GEMM: CTA 128xTN, Kc=32, 3-stage cp.async =================
// A: 2-plane fp16 (hi+lo, 22-bit). B: single fp16 plane.  D = Ah*B + Al*B (2 mma terms)
#define AH_O 0
#define AL_O 10240
#define BH_O 20480

template <int TNv, bool RELU, bool GATHER, bool MULTI, bool OSPLIT>
__global__ __launch_bounds__(256, 1)
void gemm_mma(const hf* __restrict__ Ah, const hf* __restrict__ Al,
              const hf* __restrict__ B0, const hf* __restrict__ B1,
              const hf* __restrict__ B2,
              const float* __restrict__ bi0, const float* __restrict__ bi1,
              const float* __restrict__ bi2,
              float* __restrict__ oF0,
              hf* __restrict__ oH0, hf* __restrict__ oL0,
              hf* __restrict__ oH1, hf* __restrict__ oL1,
              hf* __restrict__ oH2, hf* __restrict__ oL2,
              float s0, float s1, float s2,
              const float* __restrict__ resid, const int* __restrict__ gather,
              int K, int N,
              long aStride, long bStride, long biStride, long oStride) {
    constexpr int BROW = TNv * 2;
    constexpr int BPLANE = 32 * BROW;
    constexpr int STGB = BH_O + BPLANE;
    constexpr int BPT = TNv / 64;          // B uint4 vectors per thread (single plane)
    constexpr int WN = TNv / 4;
    constexpr int NT = WN / 8;
    constexpr int NBF = WN / 16;

    extern __shared__ char sm[];
    uint32_t sb = smem_u32(sm);
    int tid = threadIdx.x, wid = tid >> 5, lane = tid & 31;
    int z = blockIdx.z;
    int m0 = blockIdx.y * 128, n0 = blockIdx.x * TNv;

    const hf* B; const float* bi; float scale;
    float* oF = nullptr; hf *oH = nullptr, *oL = nullptr;
    if (MULTI) {
        B = (z == 0) ? B0 : (z == 1) ? B1 : B2;
        bi = (z == 0) ? bi0 : (z == 1) ? bi1 : bi2;
        scale = (z == 0) ? s0 : (z == 1) ? s1 : s2;
        oH = (z == 0) ? oH0 : (z == 1) ? oH1 : oH2;
        oL = (z == 0) ? oL0 : (z == 1) ? oL1 : oL2;
    } else {
        B = B0 + (long)z * bStride;
        bi = bi0 + (long)z * biStride;
        scale = s0;
        if (OSPLIT) { oH = oH0 + (long)z * oStride; oL = oL0 + (long)z * oStride; }
        else oF = oF0 + (long)z * oStride;
    }
    const hf* Ahz = Ah + (MULTI ? 0 : (long)z * aStride);
    const hf* Alz = Al + (MULTI ? 0 : (long)z * aStride);
    const int* gz = GATHER ? (gather + z * CAPV) : nullptr;

    int aR0 = tid >> 2, aC0 = (tid & 3) * 8;
    int aR1 = (tid + 256) >> 2, aC1 = ((tid + 256) & 3) * 8;
    long aRow0 = GATHER ? (long)gz[m0 + aR0] : (long)(m0 + aR0);
    long aRow1 = GATHER ? (long)gz[m0 + aR1] : (long)(m0 + aR1);
    long aG0 = aRow0 * K + aC0;
    long aG1 = aRow1 * K + aC1;
    int aD0 = aR0 * 80 + aC0 * 2;
    int aD1 = aR1 * 80 + aC1 * 2;

    long bG[BPT]; int bD[BPT];
#pragma unroll
    for (int i = 0; i < BPT; i++) {
        int v = tid + 256 * i;
        int row = (TNv == 256) ? (v >> 5) : (v >> 4);
        int nv  = (TNv == 256) ? (v & 31) : (v & 15);
        bG[i] = (long)row * N + n0 + nv * 8;
        bD[i] = row * BROW + ((nv * 16) ^ ((row & 7) << 4));
    }

    int nCh = K >> 5;
#pragma unroll
    for (int pre = 0; pre < 2; pre++) {
        uint32_t base = sb + (uint32_t)pre * STGB;
        int k0 = pre << 5;
        long ko = (long)k0 * N;
        cp16(base + AH_O + aD0, Ahz + aG0 + k0);
        cp16(base + AH_O + aD1, Ahz + aG1 + k0);
        cp16(base + AL_O + aD0, Alz + aG0 + k0);
        cp16(base + AL_O + aD1, Alz + aG1 + k0);
#pragma unroll
        for (int i = 0; i < BPT; i++)
            cp16(base + BH_O + bD[i], B + ko + bG[i]);
        CP_COMMIT();
    }

    float c[4][NT][4];
#pragma unroll
    for (int mt = 0; mt < 4; mt++)
#pragma unroll
        for (int nt = 0; nt < NT; nt++)
#pragma unroll
            for (int f = 0; f < 4; f++) c[mt][nt][f] = 0.f;

    int wm = wid >> 2, wn = wid & 3;
    int aRowOff = (lane & 7) + ((lane >> 3) & 1) * 8;
    int aColSel = ((lane >> 4) & 1) * 16;
    int bKoff = (lane & 7) + ((lane >> 3) & 1) * 8;
    int bN8 = ((lane >> 4) & 1) * 8;

    for (int ch = 0; ch < nCh; ch++) {
        if (ch + 1 < nCh) asm volatile("cp.async.wait_group 1;" ::: "memory");
        else              asm volatile("cp.async.wait_group 0;" ::: "memory");
        __syncthreads();
        if (ch + 2 < nCh) {
            int chn = ch + 2;
            uint32_t base = sb + (uint32_t)(chn % 3) * STGB;
            int k0 = chn << 5;
            long ko = (long)k0 * N;
            cp16(base + AH_O + aD0, Ahz + aG0 + k0);
            cp16(base + AH_O + aD1, Ahz + aG1 + k0);
            cp16(base + AL_O + aD0, Alz + aG0 + k0);
            cp16(base + AL_O + aD1, Alz + aG1 + k0);
#pragma unroll
            for (int i = 0; i < BPT; i++)
                cp16(base + BH_O + bD[i], B + ko + bG[i]);
            CP_COMMIT();
        }
        uint32_t sbuf = sb + (uint32_t)(ch % 3) * STGB;
#pragma unroll
        for (int ks = 0; ks < 2; ks++) {
            uint32_t ah[4][4], al[4][4];
#pragma unroll
            for (int mt = 0; mt < 4; mt++) {
                uint32_t ro = (wm * 64 + mt * 16 + aRowOff) * 80 + ks * 32 + aColSel;
                ldsm_x4(ah[mt], sbuf + AH_O + ro);
                ldsm_x4(al[mt], sbuf + AL_O + ro);
            }
#pragma unroll
            for (int nb = 0; nb < NBF; nb++) {
                uint32_t bhf[4];
                int kk = ks * 16 + bKoff;
                int nn = wn * WN + nb * 16 + bN8;
                uint32_t off = kk * BROW + ((nn * 2) ^ ((kk & 7) << 4));
                ldsm_x4t(bhf, sbuf + BH_O + off);
#pragma unroll
                for (int hfk = 0; hfk < 2; hfk++) {
                    int nt = nb * 2 + hfk;
#pragma unroll
                    for (int mt = 0; mt < 4; mt++)
                        mma16816(c[mt][nt], ah[mt], bhf[hfk * 2], bhf[hfk * 2 + 1]);
#pragma unroll
                    for (int mt = 0; mt < 4; mt++)
                        mma16816(c[mt][nt], al[mt], bhf[hfk * 2], bhf[hfk * 2 + 1]);
                }
            }
        }
    }

    int r0 = m0 + wm * 64 + (lane >> 2);
    int col0 = n0 + wn * WN + (lane & 3) * 2;
#pragma unroll
    for (int mt = 0; mt < 4; mt++) {
#pragma unroll
        for (int nt = 0; nt < NT; nt++) {
            int row = r0 + mt * 16;
            int cn = col0 + nt * 8;
            float2 bb = *(const float2*)(bi + cn);
            float v0x = (c[mt][nt][0] + bb.x) * scale;
            float v0y = (c[mt][nt][1] + bb.y) * scale;
            float v1x = (c[mt][nt][2] + bb.x) * scale;
            float v1y = (c[mt][nt][3] + bb.y) * scale;
            if (resid) {
                float2 ra = *(const float2*)(resid + (long)row * N + cn);
                float2 rb = *(const float2*)(resid + (long)(row + 8) * N + cn);
                v0x += ra.x; v0y += ra.y; v1x += rb.x; v1y += rb.y;
            }
            if (RELU) {
                v0x = fmaxf(v0x, 0.f); v0y = fmaxf(v0y, 0.f);
                v1x = fmaxf(v1x, 0.f); v1y = fmaxf(v1y, 0.f);
            }
            if (OSPLIT) {
                uint32_t h0, l0, h1, l1;
                pack2(v0x, v0y, h0, l0);
                pack2(v1x, v1y, h1, l1);
                *(uint32_t*)(oH + (long)row * N + cn) = h0;
                *(uint32_t*)(oH + (long)(row + 8) * N + cn) = h1;
                if (oL) {
                    *(uint32_t*)(oL + (long)row * N + cn) = l0;
                    *(uint32_t*)(oL + (long)(row + 8) * N + cn) = l1;
                }
            } else {
                *(float2*)(oF + (long)row * N + cn) = make_float2(v0x, v0y);
                *(float2*)(oF + (long)(row + 8) * N + cn) = make_float2(v1x, v1y);
            }
        }
    }
}

// ================= scores: S = Q.K^T per (b,h), CTA 128x128, K=64 =================
// Q 2-plane, K single plane
#define SC_QH 0
#define SC_QL 18432
#define SC_KH 36864
#define SC_SMEM 55296

__global__ __launch_bounds__(256, 1)
void scores_mma(const hf* __restrict__ qh, const hf* __restrict__ ql,
                const hf* __restrict__ kh, float* __restrict__ sc) {
    extern __shared__ char sm[];
    uint32_t sb = smem_u32(sm);
    int tid = threadIdx.x, wid = tid >> 5, lane = tid & 31;
    int bh = blockIdx.z;
    int b = bh >> 4, h = bh & 15;
    int m0 = blockIdx.y * 128, n0 = blockIdx.x * 128;

#pragma unroll
    for (int i = 0; i < 4; i++) {
        int v = tid + 256 * i;
        int row = v >> 3, c8 = (v & 7) * 8;
        int off = row * 144 + c8 * 2;
        long qg = (long)(b * SEQ + m0 + row) * D_MODEL + h * HEAD_D + c8;
        long kg = (long)(b * SEQ + n0 + row) * D_MODEL + h * HEAD_D + c8;
        *(uint4*)(sm + SC_QH + off) = *(const uint4*)(qh + qg);
        *(uint4*)(sm + SC_QL + off) = *(const uint4*)(ql + qg);
        *(uint4*)(sm + SC_KH + off) = *(const uint4*)(kh + kg);
    }
    __syncthreads();

    float c[4][4][4];
#pragma unroll
    for (int mt = 0; mt < 4; mt++)
#pragma unroll
        for (int nt = 0; nt < 4; nt++)
#pragma unroll
            for (int f = 0; f < 4; f++) c[mt][nt][f] = 0.f;

    int wm = wid >> 2, wn = wid & 3;
    int rowOff = (lane & 7) + ((lane >> 3) & 1) * 8;
    int colSel = ((lane >> 4) & 1) * 16;

#pragma unroll
    for (int ks = 0; ks < 4; ks++) {
        uint32_t ah[4][4], al[4][4];
#pragma unroll
        for (int mt = 0; mt < 4; mt++) {
            uint32_t ro = (wm * 64 + mt * 16 + rowOff) * 144 + ks * 32 + colSel;
            ldsm_x4(ah[mt], sb + SC_QH + ro);
            ldsm_x4(al[mt], sb + SC_QL + ro);
        }
        uint32_t bh_[2][4];
#pragma unroll
        for (int nb = 0; nb < 2; nb++) {
            uint32_t ro = (wn * 32 + nb * 16 + rowOff) * 144 + ks * 32 + colSel;
            ldsm_x4(bh_[nb], sb + SC_KH + ro);
        }
#pragma unroll
        for (int mt = 0; mt < 4; mt++)
#pragma unroll
            for (int nt = 0; nt < 4; nt++) {
                int nb = nt >> 1, hfk = nt & 1;
                mma16816(c[mt][nt], ah[mt], bh_[nb][hfk], bh_[nb][hfk + 2]);
            }
#pragma unroll
        for (int mt = 0; mt < 4; mt++)
#pragma unroll
            for (int nt = 0; nt < 4; nt++) {
                int nb = nt >> 1, hfk = nt & 1;
                mma16816(c[mt][nt], al[mt], bh_[nb][hfk], bh_[nb][hfk + 2]);
            }
    }

    long base = (long)bh * SEQ * SEQ;
    int r0 = m0 + wm * 64 + (lane >> 2);
    int col0 = n0 + wn * 32 + (lane & 3) * 2;
#pragma unroll
    for (int mt = 0; mt < 4; mt++)
#pragma unroll
        for (int nt = 0; nt < 4; nt++) {
            int row = r0 + mt * 16, cn = col0 + nt * 8;
            *(float2*)(sc + base + (long)row * SEQ + cn) = make_float2(c[mt][nt][0], c[mt][nt][1]);
            *(float2*)(sc + base + (long)(row + 8) * SEQ + cn) = make_float2(c[mt][nt][2], c[mt][nt][3]);
        }
}

// ================= softmax: fp32 -> split fp16 P =================
__global__ __launch_bounds__(128)
void softmax_kernel(const float* __restrict__ sc, hf* __restrict__ ph,
                    hf* __restrict__ pl) {
    __shared__ float redM[4], redS[4];
    const float* row = sc + (size_t)blockIdx.x * SEQ;
    float v[4]; float m = -1e30f;
#pragma unroll
    for (int i = 0; i < 4; i++) { v[i] = row[threadIdx.x + 128 * i]; m = fmaxf(m, v[i]); }
#pragma unroll
    for (int o = 16; o; o >>= 1) m = fmaxf(m, __shfl_xor_sync(~0u, m, o));
    if ((threadIdx.x & 31) == 0) redM[threadIdx.x >> 5] = m;
    __syncthreads();
    m = fmaxf(fmaxf(redM[0], redM[1]), fmaxf(redM[2], redM[3]));
    float s = 0.f;
#pragma unroll
    for (int i = 0; i < 4; i++) { v[i] = expf(v[i] - m); s += v[i]; }
#pragma unroll
    for (int o = 16; o; o >>= 1) s += __shfl_xor_sync(~0u, s, o);
    if ((threadIdx.x & 31) == 0) redS[threadIdx.x >> 5] = s;
    __syncthreads();
    s = redS[0] + redS[1] + redS[2] + redS[3];
    float inv = 1.f / s;
    size_t base = (size_t)blockIdx.x * SEQ;
#pragma unroll
    for (int i = 0; i < 4; i++) {
        float p = v[i] * inv;
        uint16_t hh, ll;
        split2(p, hh, ll);
        int cidx = threadIdx.x + 128 * i;
        ph[base + cidx] = __ushort_as_half(hh);
        pl[base + cidx] = __ushort_as_half(ll);
    }
}

// ================= PV: O = P.V per (b,h), CTA 128x64, Kc=32 =================
// P 2-plane, V single plane
#define PV_PH 0
#define PV_PL 10240
#define PV_VH 20480
#define PV_BUF 24576
#define PV_SMEM (2 * PV_BUF)

__global__ __launch_bounds__(256, 1)
void pv_mma(const hf* __restrict__ ph, const hf* __restrict__ pl,
            const hf* __restrict__ vh,
            hf* __restrict__ oh, hf* __restrict__ ol) {
    extern __shared__ char sm[];
    uint32_t sb = smem_u32(sm);
    int tid = threadIdx.x, wid = tid >> 5, lane = tid & 31;
    int bh = blockIdx.y;
    int b = bh >> 4, h = bh & 15;
    int m0 = blockIdx.x * 128;

    int v0 = tid, v1 = tid + 256;
    int aR0 = v0 >> 2, aC0 = (v0 & 3) * 8;
    int aR1 = v1 >> 2, aC1 = (v1 & 3) * 8;
    long pBase = (long)bh * SEQ * SEQ;
    long aG0 = pBase + (long)(m0 + aR0) * SEQ + aC0;
    long aG1 = pBase + (long)(m0 + aR1) * SEQ + aC1;
    int aS0 = aR0 * 80 + aC0 * 2;
    int aS1 = aR1 * 80 + aC1 * 2;
    int bKr = tid >> 3, bN0 = (tid & 7) * 8;
    long bG = (long)(b * SEQ + bKr) * D_MODEL + h * HEAD_D + bN0;
    int bS = bKr * 128 + ((bN0 * 2) ^ ((bKr & 7) << 4));

    float c[4][2][4];
#pragma unroll
    for (int mt = 0; mt < 4; mt++)
#pragma unroll
        for (int nt = 0; nt < 2; nt++)
#pragma unroll
            for (int f = 0; f < 4; f++) c[mt][nt][f] = 0.f;

    int wm = wid >> 2, wn = wid & 3;
    int aRowOff = (lane & 7) + ((lane >> 3) & 1) * 8;
    int aColSel = ((lane >> 4) & 1) * 16;
    int bKoff = (lane & 7) + ((lane >> 3) & 1) * 8;
    int bN8 = ((lane >> 4) & 1) * 8;

    uint4 vph0 = *(const uint4*)(ph + aG0), vph1 = *(const uint4*)(ph + aG1);
    uint4 vpl0 = *(const uint4*)(pl + aG0), vpl1 = *(const uint4*)(pl + aG1);
    uint4 vvh = *(const uint4*)(vh + bG);

    for (int ch = 0; ch < 16; ch++) {
        char* smb = sm + (ch & 1) * PV_BUF;
        uint32_t sbuf = sb + (ch & 1) * PV_BUF;
        __syncthreads();
        *(uint4*)(smb + PV_PH + aS0) = vph0; *(uint4*)(smb + PV_PH + aS1) = vph1;
        *(uint4*)(smb + PV_PL + aS0) = vpl0; *(uint4*)(smb + PV_PL + aS1) = vpl1;
        *(uint4*)(smb + PV_VH + bS) = vvh;
        __syncthreads();
        if (ch < 15) {
            int k0 = (ch + 1) << 5;
            vph0 = *(const uint4*)(ph + aG0 + k0);
            vph1 = *(const uint4*)(ph + aG1 + k0);
            vpl0 = *(const uint4*)(pl + aG0 + k0);
            vpl1 = *(const uint4*)(pl + aG1 + k0);
            vvh = *(const uint4*)(vh + bG + (long)k0 * D_MODEL);
        }
#pragma unroll
        for (int ks = 0; ks < 2; ks++) {
            uint32_t ah[4][4], al[4][4];
#pragma unroll
            for (int mt = 0; mt < 4; mt++) {
                uint32_t ro = (wm * 64 + mt * 16 + aRowOff) * 80 + ks * 32 + aColSel;
                ldsm_x4(ah[mt], sbuf + PV_PH + ro);
                ldsm_x4(al[mt], sbuf + PV_PL + ro);
            }
            uint32_t bh_[4];
            {
                int kk = ks * 16 + bKoff;
                int nn = wn * 16 + bN8;
                uint32_t off = kk * 128 + ((nn * 2) ^ ((kk & 7) << 4));
                ldsm_x4t(bh_, sbuf + PV_VH + off);
            }
#pragma unroll
            for (int mt = 0; mt < 4; mt++)
#pragma unroll
                for (int nt = 0; nt < 2; nt++)
                    mma16816(c[mt][nt], ah[mt], bh_[nt * 2], bh_[nt * 2 + 1]);
#pragma unroll
            for (int mt = 0; mt < 4; mt++)
#pragma unroll
                for (int nt = 0; nt < 2; nt++)
                    mma16816(c[mt][nt], al[mt], bh_[nt * 2], bh_[nt * 2 + 1]);
        }
    }

    int r0 = m0 + wm * 64 + (lane >> 2);
    int col0 = wn * 16 + (lane & 3) * 2;
#pragma unroll
    for (int mt = 0; mt < 4; mt++)
#pragma unroll
        for (int nt = 0; nt < 2; nt++) {
            int row = r0 + mt * 16;
            int cn = col0 + nt * 8;
            long o0 = (long)(b * SEQ + row) * D_MODEL + h * HEAD_D + cn;
            long o1 = (long)(b * SEQ + row + 8) * D_MODEL + h * HEAD_D + cn;
            uint32_t h0, l0, h1, l1;
            pack2(c[mt][nt][0], c[mt][nt][1], h0, l0);
            pack2(c[mt][nt][2], c[mt][nt][3], h1, l1);
            *(uint32_t*)(oh + o0) = h0; *(uint32_t*)(ol + o0) = l0;
            *(uint32_t*)(oh + o1) = h1; *(uint32_t*)(ol + o1) = l1;
        }
}

// ================= LayerNorm -> optional fp32 + split fp16 =================
__global__ void ln_kernel(const float* __restrict__ x, const float* __restrict__ gam,
                          const float* __restrict__ bet, float* __restrict__ outF,
                          hf* __restrict__ oh, hf* __restrict__ ol) {
    __shared__ float redA[8], redB[8];
    int t = blockIdx.x;
    const float* xr = x + (size_t)t * D_MODEL;
    float v[4]; float s = 0.f;
#pragma unroll
    for (int i = 0; i < 4; i++) { v[i] = xr[threadIdx.x + 256 * i]; s += v[i]; }
#pragma unroll
    for (int o = 16; o; o >>= 1) s += __shfl_xor_sync(~0u, s, o);
    if ((threadIdx.x & 31) == 0) redA[threadIdx.x >> 5] = s;
    __syncthreads();
    if (threadIdx.x == 0) { float r = 0.f; for (int i = 0; i < 8; i++) r += redA[i]; redA[0] = r; }
    __syncthreads();
    float mu = redA[0] * (1.f / D_MODEL);
    float s2 = 0.f;
#pragma unroll
    for (int i = 0; i < 4; i++) { float d = v[i] - mu; s2 += d * d; }
#pragma unroll
    for (int o = 16; o; o >>= 1) s2 += __shfl_xor_sync(~0u, s2, o);
    if ((threadIdx.x & 31) == 0) redB[threadIdx.x >> 5] = s2;
    __syncthreads();
    if (threadIdx.x == 0) { float r = 0.f; for (int i = 0; i < 8; i++) r += redB[i]; redB[0] = r; }
    __syncthreads();
    float rstd = rsqrtf(redB[0] * (1.f / D_MODEL) + 1e-5f);
    size_t base = (size_t)t * D_MODEL;
#pragma unroll
    for (int i = 0; i < 4; i++) {
        int cc = threadIdx.x + 256 * i;
        float r = (v[i] - mu) * rstd * gam[cc] + bet[cc];
        if (outF) outF[base + cc] = r;
        uint16_t hh, ll;
        split2(r, hh, ll);
        oh[base + cc] = __ushort_as_half(hh);
        ol[base + cc] = __ushort_as_half(ll);
    }
}

// ================= router / scan / combine =================
__global__ __launch_bounds__(256)
void router_kernel(const float* __restrict__ h2, const float* __restrict__ wr) {
    int t = blockIdx.x * 8 + (threadIdx.x >> 5);
    int lane = threadIdx.x & 31;
    const float* xr = h2 + (long)t * D_MODEL;
    float acc[8];
#pragma unroll
    for (int e = 0; e < 8; e++) acc[e] = 0.f;
    for (int i = lane; i < D_MODEL; i += 32) {
        float xv = xr[i];
        const float* w = wr + i * 8;
#pragma unroll
        for (int e = 0; e < 8; e++) acc[e] = fmaf(xv, w[e], acc[e]);
    }
#pragma unroll
    for (int o = 16; o; o >>= 1)
#pragma unroll
        for (int e = 0; e < 8; e++) acc[e] += __shfl_xor_sync(~0u, acc[e], o);
    if (lane == 0) {
        float m = acc[0]; int t1 = 0;
#pragma unroll
        for (int e = 1; e < 8; e++) if (acc[e] > m) { m = acc[e]; t1 = e; }
        float s = 0.f, pr[8];
#pragma unroll
        for (int e = 0; e < 8; e++) { pr[e] = expf(acc[e] - m); s += pr[e]; }
        float inv = 1.f / s;
        float m2 = -1e30f; int t2 = 0;
#pragma unroll
        for (int e = 0; e < 8; e++) {
            if (e == t1) continue;
            if (acc[e] > m2) { m2 = acc[e]; t2 = e; }
        }
        g_top1[t] = t1; g_top2[t] = t2;
        g_p1[t] = pr[t1] * inv;
        g_p2[t] = pr[t2] * inv;
    }
}

__global__ __launch_bounds__(256)
void scan_kernel() {
    int tid = threadIdx.x;
    for (int i = tid; i < NEXP * CAPV; i += 256) g_disp[i] = 0;
    __syncthreads();
    int e = tid >> 5;
    int lane = tid & 31;
    unsigned lt = (1u << lane) - 1u;
    int base = 0;
    for (int c0 = 0; c0 < N_TOK; c0 += 32) {
        int t = c0 + lane;
        bool f = (g_top1[t] == e);
        unsigned msk = __ballot_sync(~0u, f);
        if (f) {
            int loc = base + __popc(msk & lt);
            if (loc < CAPV) { g_s1[t] = loc; g_disp[e * CAPV + loc] = t; }
            else g_s1[t] = -1;
        }
        base += __popc(msk);
    }
    for (int c0 = 0; c0 < N_TOK; c0 += 32) {
        int t = c0 + lane;
        bool f = (g_top2[t] == e);
        unsigned msk = __ballot_sync(~0u, f);
        if (f) {
            int loc = base + __popc(msk & lt);
            if (loc < CAPV) { g_s2[t] = loc; g_disp[e * CAPV + loc] = t; }
            else g_s2[t] = -1;
        }
        base += __popc(msk);
    }
    __syncthreads();
    for (int t = tid; t < N_TOK; t += 256) {
        float t1 = (g_s1[t] >= 0) ? g_p1[t] : 0.f;
        float t2 = (g_s2[t] >= 0) ? g_p2[t] : 0.f;
        float den = fmaxf(t1 + t2, 1.1920929e-7f);
        g_g1[t] = t1 / den;
        g_g2[t] = t2 / den;
    }
}

__global__ __launch_bounds__(256)
void combine_kernel(float* __restrict__ out) {
    int t = blockIdx.x;
    int s1 = g_s1[t], s2 = g_s2[t];
    float g1 = g_g1[t], g2 = g_g2[t];
    const float* y1 = (s1 >= 0) ? g_y + ((long)g_top1[t] * CAPV + s1) * D_MODEL : 0;
    const float* y2 = (s2 >= 0) ? g_y + ((long)g_top2[t] * CAPV + s2) * D_MODEL : 0;
    long ro = (long)t * D_MODEL;
#pragma unroll
    for (int i = 0; i < 4; i++) {
        int d = threadIdx.x + 256 * i;
        float a = out[ro + d];
        if (y1) a = fmaf(g1, y1[d], a);
        if (y2) a = fmaf(g2, y2[d], a);
        out[ro + d] = a;
    }
}

// ================= launch =================
extern "C" void kernel_launch(void* const* d_in, const int* in_sizes, int n_in,
                              void* d_out, int out_size) {
    const float* x    = (const float*)d_in[0];
    const float* wq   = (const float*)d_in[1];
    const float* bq   = (const float*)d_in[2];
    const float* wk   = (const float*)d_in[3];
    const float* bk   = (const float*)d_in[4];
    const float* wv   = (const float*)d_in[5];
    const float* bv   = (const float*)d_in[6];
    const float* wo   = (const float*)d_in[7];
    const float* bo   = (const float*)d_in[8];
    const float* ln1g = (const float*)d_in[9];
    const float* ln1b = (const float*)d_in[10];
    const float* ln2g = (const float*)d_in[11];
    const float* ln2b = (const float*)d_in[12];
    const float* wr   = (const float*)d_in[13];
    const float* w1   = (const float*)d_in[14];
    const float* b1   = (const float*)d_in[15];
    const float* w2   = (const float*)d_in[16];
    const float* b2   = (const float*)d_in[17];
    float* out = (float*)d_out;

    hf *wq1, *wk1, *wv1, *wo1, *w11, *w21;
    hf *h1h, *h1l, *h2h, *h2l, *qh, *ql, *kh, *vh, *ath, *atl;
    hf *midh, *midl, *ph, *pl;
    float *h2, *sc, *y;
    int* disp;
    cudaGetSymbolAddress((void**)&wq1, g_wq1); cudaGetSymbolAddress((void**)&wk1, g_wk1);
    cudaGetSymbolAddress((void**)&wv1, g_wv1); cudaGetSymbolAddress((void**)&wo1, g_wo1);
    cudaGetSymbolAddress((void**)&w11, g_w11); cudaGetSymbolAddress((void**)&w21, g_w21);
    cudaGetSymbolAddress((void**)&h1h, g_h1h); cudaGetSymbolAddress((void**)&h1l, g_h1l);
    cudaGetSymbolAddress((void**)&h2h, g_h2h); cudaGetSymbolAddress((void**)&h2l, g_h2l);
    cudaGetSymbolAddress((void**)&qh, g_qh);   cudaGetSymbolAddress((void**)&ql, g_ql);
    cudaGetSymbolAddress((void**)&kh, g_kh);   cudaGetSymbolAddress((void**)&vh, g_vh);
    cudaGetSymbolAddress((void**)&ath, g_ath); cudaGetSymbolAddress((void**)&atl, g_atl);
    cudaGetSymbolAddress((void**)&midh, g_midh); cudaGetSymbolAddress((void**)&midl, g_midl);
    cudaGetSymbolAddress((void**)&ph, g_ph);   cudaGetSymbolAddress((void**)&pl, g_pl);
    cudaGetSymbolAddress((void**)&h2, g_h2);
    cudaGetSymbolAddress((void**)&sc, g_sc);
    cudaGetSymbolAddress((void**)&y, g_y);
    cudaGetSymbolAddress((void**)&disp, g_disp);

    constexpr int SMEM128 = 3 * (20480 + 8192);    // 86016
    constexpr int SMEM256 = 3 * (20480 + 16384);   // 110592
    cudaFuncSetAttribute(gemm_mma<128, false, false, true, true>,
                         cudaFuncAttributeMaxDynamicSharedMemorySize, SMEM128);
    cudaFuncSetAttribute(gemm_mma<128, false, false, false, false>,
                         cudaFuncAttributeMaxDynamicSharedMemorySize, SMEM128);
    cudaFuncSetAttribute(gemm_mma<256, true, true, false, true>,
                         cudaFuncAttributeMaxDynamicSharedMemorySize, SMEM256);
    cudaFuncSetAttribute(gemm_mma<256, false, false, false, false>,
                         cudaFuncAttributeMaxDynamicSharedMemorySize, SMEM256);
    cudaFuncSetAttribute(scores_mma, cudaFuncAttributeMaxDynamicSharedMemorySize, SC_SMEM);
    cudaFuncSetAttribute(pv_mma, cudaFuncAttributeMaxDynamicSharedMemorySize, PV_SMEM);

    // 0) weight rounding (single fp16 plane)
    round_attn<<<dim3(256, 1, 4), 256>>>(wq, wk, wv, wo, wq1, wk1, wv1, wo1);
    round_pass<<<4096, 256>>>(w1, w11, 33554432 / 4);
    round_pass<<<4096, 256>>>(w2, w21, 33554432 / 4);

    // 1) LN1 -> split
    ln_kernel<<<N_TOK, 256>>>(x, ln1g, ln1b, nullptr, h1h, h1l);

    // 2) QKV fused (Q split 2-plane; K,V single plane)
    gemm_mma<128, false, false, true, true><<<dim3(8, 16, 3), 256, SMEM128>>>(
        h1h, h1l, wq1, wk1, wv1, bq, bk, bv,
        nullptr, qh, ql, kh, nullptr, vh, nullptr, 0.125f, 1.f, 1.f,
        nullptr, nullptr, 1024, 1024, 0, 0, 0, 0);

    // 3) attention
    scores_mma<<<dim3(4, 4, NB * N_HEADS), 256, SC_SMEM>>>(qh, ql, kh, sc);
    softmax_kernel<<<NB * N_HEADS * SEQ, 128>>>(sc, ph, pl);
    pv_mma<<<dim3(4, NB * N_HEADS), 256, PV_SMEM>>>(ph, pl, vh, ath, atl);

    // 4) O projection + residual
    gemm_mma<128, false, false, false, false><<<dim3(8, 16, 1), 256, SMEM128>>>(
        ath, atl, wo1, nullptr, nullptr, bo, nullptr, nullptr,
        out, nullptr, nullptr, nullptr, nullptr, nullptr, nullptr, 1.f, 0.f, 0.f,
        x, nullptr, 1024, 1024, 0, 0, 0, 0);

    // 5) LN2
    ln_kernel<<<N_TOK, 256>>>(out, ln2g, ln2b, h2, h2h, h2l);

    // 6) router + scan
    router_kernel<<<N_TOK / 8, 256>>>(h2, wr);
    scan_kernel<<<1, 256>>>();

    // 7) FFN1 gathered + relu -> split mid (TN=256)
    gemm_mma<256, true, true, false, true><<<dim3(16, 4, 8), 256, SMEM256>>>(
        h2h, h2l, w11, nullptr, nullptr, b1, nullptr, nullptr,
        nullptr, midh, midl, nullptr, nullptr, nullptr, nullptr, 1.f, 0.f, 0.f,
        nullptr, disp, 1024, 4096, 0, (long)D_MODEL * FFN_D, FFN_D, (long)CAPV * FFN_D);

    // 8) FFN2 -> fp32 y (*0.8) (TN=256)
    gemm_mma<256, false, false, false, false><<<dim3(4, 4, 8), 256, SMEM256>>>(
        midh, midl, w21, nullptr, nullptr, b2, nullptr, nullptr,
        y, nullptr, nullptr, nullptr, nullptr, nullptr, nullptr, 0.8f, 0.f, 0.f,
        nullptr, nullptr, 4096, 1024,
        (long)CAPV * FFN_D, (long)FFN_D * D_MODEL, D_MODEL, (long)CAPV * D_MODEL);

    // 9) combine
    combine_kernel<<<N_TOK, 256>>>(out);
}

// round 12
// speedup vs baseline: 2.0097x; 1.4518x over previous
#include <cuda_runtime.h>
#include <cuda_fp16.h>
#include <cstdint>

#define D_MODEL 1024
#define N_TOK   2048
#define N_HEADS 16
#define HEAD_D  64
#define SEQ     512
#define NB      4
#define FFN_D   4096
#define NEXP    8
#define CAPV    512

typedef __half hf;

// ================= device scratch =================
__device__ hf g_wq1[1048576], g_wk1[1048576], g_wv1[1048576], g_wo1[1048576];
__device__ hf g_w11[33554432], g_w21[33554432];
__device__ hf g_h1h[2097152];
__device__ hf g_h2h[2097152];
__device__ float g_h2[2097152];
__device__ hf g_qh[2097152];
__device__ hf g_kh[2097152];
__device__ hf g_vh[2097152];
__device__ hf g_ath[2097152];
__device__ hf g_midh[16777216];
__device__ hf g_ph[16777216];
__device__ float g_sc[16777216];
__device__ float g_y[4194304];
__device__ int   g_top1[N_TOK], g_top2[N_TOK];
__device__ float g_p1[N_TOK], g_p2[N_TOK];
__device__ int   g_s1[N_TOK], g_s2[N_TOK];
__device__ float g_g1[N_TOK], g_g2[N_TOK];
__device__ int   g_disp[NEXP * CAPV];

// ================= helpers =================
__device__ __forceinline__ uint32_t smem_u32(const void* p) {
    uint32_t a;
    asm("{ .reg .u64 t; cvta.to.shared.u64 t, %1; cvt.u32.u64 %0, t; }" : "=r"(a) : "l"(p));
    return a;
}
__device__ __forceinline__ void ldsm_x4(uint32_t* r, uint32_t addr) {
    asm volatile("ldmatrix.sync.aligned.m8n8.x4.shared.b16 {%0,%1,%2,%3}, [%4];"
        : "=r"(r[0]), "=r"(r[1]), "=r"(r[2]), "=r"(r[3]) : "r"(addr));
}
__device__ __forceinline__ void ldsm_x4t(uint32_t* r, uint32_t addr) {
    asm volatile("ldmatrix.sync.aligned.m8n8.x4.trans.shared.b16 {%0,%1,%2,%3}, [%4];"
        : "=r"(r[0]), "=r"(r[1]), "=r"(r[2]), "=r"(r[3]) : "r"(addr));
}
__device__ __forceinline__ void mma16816(float* c, const uint32_t* a, uint32_t b0, uint32_t b1) {
    asm volatile(
        "mma.sync.aligned.m16n8k16.row.col.f32.f16.f16.f32 "
        "{%0,%1,%2,%3}, {%4,%5,%6,%7}, {%8,%9}, {%0,%1,%2,%3};"
        : "+f"(c[0]), "+f"(c[1]), "+f"(c[2]), "+f"(c[3])
        : "r"(a[0]), "r"(a[1]), "r"(a[2]), "r"(a[3]), "r"(b0), "r"(b1));
}
__device__ __forceinline__ void cp16(uint32_t dst, const void* src) {
    asm volatile("cp.async.cg.shared.global [%0], [%1], 16;" :: "r"(dst), "l"(src) : "memory");
}
#define CP_COMMIT() asm volatile("cp.async.commit_group;" ::: "memory")
__device__ __forceinline__ uint32_t pack2s(float x, float y) {
    return (uint32_t)__half_as_ushort(__float2half_rn(x)) |
           ((uint32_t)__half_as_ushort(__float2half_rn(y)) << 16);
}

// ================= weight rounding passes =================
__global__ __launch_bounds__(256)
void round_pass(const float* __restrict__ src, hf* __restrict__ dst, long n4) {
    for (long i = blockIdx.x * 256 + threadIdx.x; i < n4; i += (long)gridDim.x * 256) {
        float4 v = *(const float4*)(src + i * 4);
        *(uint2*)(dst + i * 4) = make_uint2(pack2s(v.x, v.y), pack2s(v.z, v.w));
    }
}

__global__ __launch_bounds__(256)
void round_attn(const float* __restrict__ wq, const float* __restrict__ wk,
                const float* __restrict__ wv, const float* __restrict__ wo,
                hf* __restrict__ q1, hf* __restrict__ k1,
                hf* __restrict__ v1, hf* __restrict__ o1) {
    int z = blockIdx.z;
    const float* src = (z == 0) ? wq : (z == 1) ? wk : (z == 2) ? wv : wo;
    hf* dst = (z == 0) ? q1 : (z == 1) ? k1 : (z == 2) ? v1 : o1;
    const long n4 = 262144;
    for (long i = blockIdx.x * 256 + threadIdx.x; i < n4; i += (long)gridDim.x * 256) {
        float4 v = *(const float4*)(src + i * 4);
        *(uint2*)(dst + i * 4) = make_uint2(pack2s(v.x, v.y), pack2s(v.z, v.w));
    }
}

// ================= fp16 HMMA GEMM: CTA 128xTN, Kc=32, 3-stage cp.async =================
#define A_O 0
#define B_O 10240

template <int TNv, bool RELU, bool GATHER, bool MULTI, bool OSPLIT>
__global__ __launch_bounds__(256, 1)
void gemm_mma(const hf* __restrict__ A,
              const hf* __restrict__ B0, const hf* __restrict__ B1,
              const hf* __restrict__ B2,
              const float* __restrict__ bi0, const float* __restrict__ bi1,
              const float* __restrict__ bi2,
              float* __restrict__ oF0,
              hf* __restrict__ oH0, hf* __restrict__ oH1, hf* __restrict__ oH2,
              float s0, float s1, float s2,
              const float* __restrict__ resid, const int* __restrict__ gather,
              int K, int N,
              long aStride, long bStride, long biStride, long oStride) {
    constexpr int BROW = TNv * 2;
    constexpr int BPLANE = 32 * BROW;
    constexpr int STGB = B_O + BPLANE;
    constexpr int BPT = TNv / 64;
    constexpr int WN = TNv / 4;
    constexpr int NT = WN / 8;
    constexpr int NBF = WN / 16;

    extern __shared__ char sm[];
    uint32_t sb = smem_u32(sm);
    int tid = threadIdx.x, wid = tid >> 5, lane = tid & 31;
    int z = blockIdx.z;
    int m0 = blockIdx.y * 128, n0 = blockIdx.x * TNv;

    const hf* B; const float* bi; float scale;
    float* oF = nullptr; hf* oH = nullptr;
    if (MULTI) {
        B = (z == 0) ? B0 : (z == 1) ? B1 : B2;
        bi = (z == 0) ? bi0 : (z == 1) ? bi1 : bi2;
        scale = (z == 0) ? s0 : (z == 1) ? s1 : s2;
        oH = (z == 0) ? oH0 : (z == 1) ? oH1 : oH2;
    } else {
        B = B0 + (long)z * bStride;
        bi = bi0 + (long)z * biStride;
        scale = s0;
        if (OSPLIT) oH = oH0 + (long)z * oStride;
        else oF = oF0 + (long)z * oStride;
    }
    const hf* Az = A + (MULTI ? 0 : (long)z * aStride);
    const int* gz = GATHER ? (gather + z * CAPV) : nullptr;

    int aR0 = tid >> 2, aC0 = (tid & 3) * 8;
    int aR1 = (tid + 256) >> 2, aC1 = ((tid + 256) & 3) * 8;
    long aRow0 = GATHER ? (long)gz[m0 + aR0] : (long)(m0 + aR0);
    long aRow1 = GATHER ? (long)gz[m0 + aR1] : (long)(m0 + aR1);
    long aG0 = aRow0 * K + aC0;
    long aG1 = aRow1 * K + aC1;
    int aD0 = aR0 * 80 + aC0 * 2;
    int aD1 = aR1 * 80 + aC1 * 2;

    long bG[BPT]; int bD[BPT];
#pragma unroll
    for (int i = 0; i < BPT; i++) {
        int v = tid + 256 * i;
        int row = (TNv == 256) ? (v >> 5) : (v >> 4);
        int nv  = (TNv == 256) ? (v & 31) : (v & 15);
        bG[i] = (long)row * N + n0 + nv * 8;
        bD[i] = row * BROW + ((nv * 16) ^ ((row & 7) << 4));
    }

    int nCh = K >> 5;
#pragma unroll
    for (int pre = 0; pre < 2; pre++) {
        uint32_t base = sb + (uint32_t)pre * STGB;
        int k0 = pre << 5;
        long ko = (long)k0 * N;
        cp16(base + A_O + aD0, Az + aG0 + k0);
        cp16(base + A_O + aD1, Az + aG1 + k0);
#pragma unroll
        for (int i = 0; i < BPT; i++)
            cp16(base + B_O + bD[i], B + ko + bG[i]);
        CP_COMMIT();
    }

    float c[4][NT][4];
#pragma unroll
    for (int mt = 0; mt < 4; mt++)
#pragma unroll
        for (int nt = 0; nt < NT; nt++)
#pragma unroll
            for (int f = 0; f < 4; f++) c[mt][nt][f] = 0.f;

    int wm = wid >> 2, wn = wid & 3;
    int aRowOff = (lane & 7) + ((lane >> 3) & 1) * 8;
    int aColSel = ((lane >> 4) & 1) * 16;
    int bKoff = (lane & 7) + ((lane >> 3) & 1) * 8;
    int bN8 = ((lane >> 4) & 1) * 8;

    for (int ch = 0; ch < nCh; ch++) {
        if (ch + 1 < nCh) asm volatile("cp.async.wait_group 1;" ::: "memory");
        else              asm volatile("cp.async.wait_group 0;" ::: "memory");
        __syncthreads();
        if (ch + 2 < nCh) {
            int chn = ch + 2;
            uint32_t base = sb + (uint32_t)(chn % 3) * STGB;
            int k0 = chn << 5;
            long ko = (long)k0 * N;
            cp16(base + A_O + aD0, Az + aG0 + k0);
            cp16(base + A_O + aD1, Az + aG1 + k0);
#pragma unroll
            for (int i = 0; i < BPT; i++)
                cp16(base + B_O + bD[i], B + ko + bG[i]);
            CP_COMMIT();
        }
        uint32_t sbuf = sb + (uint32_t)(ch % 3) * STGB;
#pragma unroll
        for (int ks = 0; ks < 2; ks++) {
            uint32_t ah[4][4];
#pragma unroll
            for (int mt = 0; mt < 4; mt++) {
                uint32_t ro = (wm * 64 + mt * 16 + aRowOff) * 80 + ks * 32 + aColSel;
                ldsm_x4(ah[mt], sbuf + A_O + ro);
            }
#pragma unroll
            for (int nb = 0; nb < NBF; nb++) {
                uint32_t bhf[4];
                int kk = ks * 16 + bKoff;
                int nn = wn * WN + nb * 16 + bN8;
                uint32_t off = kk * BROW + ((nn * 2) ^ ((kk & 7) << 4));
                ldsm_x4t(bhf, sbuf + B_O + off);
#pragma unroll
                for (int hfk = 0; hfk < 2; hfk++) {
                    int nt = nb * 2 + hfk;
#pragma unroll
                    for (int mt = 0; mt < 4; mt++)
                        mma16816(c[mt][nt], ah[mt], bhf[hfk * 2], bhf[hfk * 2 + 1]);
                }
            }
        }
    }

    int r0 = m0 + wm * 64 + (lane >> 2);
    int col0 = n0 + wn * WN + (lane & 3) * 2;
#pragma unroll
    for (int mt = 0; mt < 4; mt++) {
#pragma unroll
        for (int nt = 0; nt < NT; nt++) {
            int row = r0 + mt * 16;
            int cn = col0 + nt * 8;
            float2 bb = *(const float2*)(bi + cn);
            float v0x = (c[mt][nt][0] + bb.x) * scale;
            float v0y = (c[mt][nt][1] + bb.y) * scale;
            float v1x = (c[mt][nt][2] + bb.x) * scale;
            float v1y = (c[mt][nt][3] + bb.y) * scale;
            if (resid) {
                float2 ra = *(const float2*)(resid + (long)row * N + cn);
                float2 rb = *(const float2*)(resid + (long)(row + 8) * N + cn);
                v0x += ra.x; v0y += ra.y; v1x += rb.x; v1y += rb.y;
            }
            if (RELU) {
                v0x = fmaxf(v0x, 0.f); v0y = fmaxf(v0y, 0.f);
                v1x = fmaxf(v1x, 0.f); v1y = fmaxf(v1y, 0.f);
            }
            if (OSPLIT) {
                *(uint32_t*)(oH + (long)row * N + cn) = pack2s(v0x, v0y);
                *(uint32_t*)(oH + (long)(row + 8) * N + cn) = pack2s(v1x, v1y);
            } else {
                *(float2*)(oF + (long)row * N + cn) = make_float2(v0x, v0y);
                *(float2*)(oF + (long)(row + 8) * N + cn) = make_float2(v1x, v1y);
            }
        }
    }
}

// ================= scores: S = Q.K^T per (b,h), CTA 128x128, K=64 =================
#define SC_Q 0
#define SC_K 18432
#define SC_SMEM 36864

__global__ __launch_bounds__(256, 1)
void scores_mma(const hf* __restrict__ qh, const hf* __restrict__ kh,
                float* __restrict__ sc) {
    extern __shared__ char sm[];
    uint32_t sb = smem_u32(sm);
    int tid = threadIdx.x, wid = tid >> 5, lane = tid & 31;
    int bh = blockIdx.z;
    int b = bh >> 4, h = bh & 15;
    int m0 = blockIdx.y * 128, n0 = blockIdx.x * 128;

#pragma unroll
    for (int i = 0; i < 4; i++) {
        int v = tid + 256 * i;
        int row = v >> 3, c8 = (v & 7) * 8;
        int off = row * 144 + c8 * 2;
        long qg = (long)(b * SEQ + m0 + row) * D_MODEL + h * HEAD_D + c8;
        long kg = (long)(b * SEQ + n0 + row) * D_MODEL + h * HEAD_D + c8;
        *(uint4*)(sm + SC_Q + off) = *(const uint4*)(qh + qg);
        *(uint4*)(sm + SC_K + off) = *(const uint4*)(kh + kg);
    }
    __syncthreads();

    float c[4][4][4];
#pragma unroll
    for (int mt = 0; mt < 4; mt++)
#pragma unroll
        for (int nt = 0; nt < 4; nt++)
#pragma unroll
            for (int f = 0; f < 4; f++) c[mt][nt][f] = 0.f;

    int wm = wid >> 2, wn = wid & 3;
    int rowOff = (lane & 7) + ((lane >> 3) & 1) * 8;
    int colSel = ((lane >> 4) & 1) * 16;

#pragma unroll
    for (int ks = 0; ks < 4; ks++) {
        uint32_t ah[4][4];
#pragma unroll
        for (int mt = 0; mt < 4; mt++) {
            uint32_t ro = (wm * 64 + mt * 16 + rowOff) * 144 + ks * 32 + colSel;
            ldsm_x4(ah[mt], sb + SC_Q + ro);
        }
        uint32_t bh_[2][4];
#pragma unroll
        for (int nb = 0; nb < 2; nb++) {
            uint32_t ro = (wn * 32 + nb * 16 + rowOff) * 144 + ks * 32 + colSel;
            ldsm_x4(bh_[nb], sb + SC_K + ro);
        }
#pragma unroll
        for (int mt = 0; mt < 4; mt++)
#pragma unroll
            for (int nt = 0; nt < 4; nt++) {
                int nb = nt >> 1, hfk = nt & 1;
                mma16816(c[mt][nt], ah[mt], bh_[nb][hfk], bh_[nb][hfk + 2]);
            }
    }

    long base = (long)bh * SEQ * SEQ;
    int r0 = m0 + wm * 64 + (lane >> 2);
    int col0 = n0 + wn * 32 + (lane & 3) * 2;
#pragma unroll
    for (int mt = 0; mt < 4; mt++)
#pragma unroll
        for (int nt = 0; nt < 4; nt++) {
            int row = r0 + mt * 16, cn = col0 + nt * 8;
            *(float2*)(sc + base + (long)row * SEQ + cn) = make_float2(c[mt][nt][0], c[mt][nt][1]);
            *(float2*)(sc + base + (long)(row + 8) * SEQ + cn) = make_float2(c[mt][nt][2], c[mt][nt][3]);
        }
}

// ================= softmax: fp32 -> fp16 P =================
__global__ __launch_bounds__(128)
void softmax_kernel(const float* __restrict__ sc, hf* __restrict__ ph) {
    __shared__ float redM[4], redS[4];
    const float* row = sc + (size_t)blockIdx.x * SEQ;
    float v[4]; float m = -1e30f;
#pragma unroll
    for (int i = 0; i < 4; i++) { v[i] = row[threadIdx.x + 128 * i]; m = fmaxf(m, v[i]); }
#pragma unroll
    for (int o = 16; o; o >>= 1) m = fmaxf(m, __shfl_xor_sync(~0u, m, o));
    if ((threadIdx.x & 31) == 0) redM[threadIdx.x >> 5] = m;
    __syncthreads();
    m = fmaxf(fmaxf(redM[0], redM[1]), fmaxf(redM[2], redM[3]));
    float s = 0.f;
#pragma unroll
    for (int i = 0; i < 4; i++) { v[i] = expf(v[i] - m); s += v[i]; }
#pragma unroll
    for (int o = 16; o; o >>= 1) s += __shfl_xor_sync(~0u, s, o);
    if ((threadIdx.x & 31) == 0) redS[threadIdx.x >> 5] = s;
    __syncthreads();
    s = redS[0] + redS[1] + redS[2] + redS[3];
    float inv = 1.f / s;
    size_t base = (size_t)blockIdx.x * SEQ;
#pragma unroll
    for (int i = 0; i < 4; i++) {
        float p = v[i] * inv;
        ph[base + threadIdx.x + 128 * i] = __float2half_rn(p);
    }
}

// ================= PV: O = P.V per (b,h), CTA 128x64, Kc=32 =================
#define PV_P 0
#define PV_V 10240
#define PV_BUF 14336
#define PV_SMEM (2 * PV_BUF)

__global__ __launch_bounds__(256, 1)
void pv_mma(const hf* __restrict__ ph, const hf* __restrict__ vh,
            hf* __restrict__ oh) {
    extern __shared__ char sm[];
    uint32_t sb = smem_u32(sm);
    int tid = threadIdx.x, wid = tid >> 5, lane = tid & 31;
    int bh = blockIdx.y;
    int b = bh >> 4, h = bh & 15;
    int m0 = blockIdx.x * 128;

    int v0 = tid, v1 = tid + 256;
    int aR0 = v0 >> 2, aC0 = (v0 & 3) * 8;
    int aR1 = v1 >> 2, aC1 = (v1 & 3) * 8;
    long pBase = (long)bh * SEQ * SEQ;
    long aG0 = pBase + (long)(m0 + aR0) * SEQ + aC0;
    long aG1 = pBase + (long)(m0 + aR1) * SEQ + aC1;
    int aS0 = aR0 * 80 + aC0 * 2;
    int aS1 = aR1 * 80 + aC1 * 2;
    int bKr = tid >> 3, bN0 = (tid & 7) * 8;
    long bG = (long)(b * SEQ + bKr) * D_MODEL + h * HEAD_D + bN0;
    int bS = bKr * 128 + ((bN0 * 2) ^ ((bKr & 7) << 4));

    float c[4][2][4];
#pragma unroll
    for (int mt = 0; mt < 4; mt++)
#pragma unroll
        for (int nt = 0; nt < 2; nt++)
#pragma unroll
            for (int f = 0; f < 4; f++) c[mt][nt][f] = 0.f;

    int wm = wid >> 2, wn = wid & 3;
    int aRowOff = (lane & 7) + ((lane >> 3) & 1) * 8;
    int aColSel = ((lane >> 4) & 1) * 16;
    int bKoff = (lane & 7) + ((lane >> 3) & 1) * 8;
    int bN8 = ((lane >> 4) & 1) * 8;

    uint4 vph0 = *(const uint4*)(ph + aG0), vph1 = *(const uint4*)(ph + aG1);
    uint4 vvh = *(const uint4*)(vh + bG);

    for (int ch = 0; ch < 16; ch++) {
        char* smb = sm + (ch & 1) * PV_BUF;
        uint32_t sbuf = sb + (ch & 1) * PV_BUF;
        __syncthreads();
        *(uint4*)(smb + PV_P + aS0) = vph0; *(uint4*)(smb + PV_P + aS1) = vph1;
        *(uint4*)(smb + PV_V + bS) = vvh;
        __syncthreads();
        if (ch < 15) {
            int k0 = (ch + 1) << 5;
            vph0 = *(const uint4*)(ph + aG0 + k0);
            vph1 = *(const uint4*)(ph + aG1 + k0);
            vvh = *(const uint4*)(vh + bG + (long)k0 * D_MODEL);
        }
#pragma unroll
        for (int ks = 0; ks < 2; ks++) {
            uint32_t ah[4][4];
#pragma unroll
            for (int mt = 0; mt < 4; mt++) {
                uint32_t ro = (wm * 64 + mt * 16 + aRowOff) * 80 + ks * 32 + aColSel;
                ldsm_x4(ah[mt], sbuf + PV_P + ro);
            }
            uint32_t bh_[4];
            {
                int kk = ks * 16 + bKoff;
                int nn = wn * 16 + bN8;
                uint32_t off = kk * 128 + ((nn * 2) ^ ((kk & 7) << 4));
                ldsm_x4t(bh_, sbuf + PV_V + off);
            }
#pragma unroll
            for (int mt = 0; mt < 4; mt++)
#pragma unroll
                for (int nt = 0; nt < 2; nt++)
                    mma16816(c[mt][nt], ah[mt], bh_[nt * 2], bh_[nt * 2 + 1]);
        }
    }

    int r0 = m0 + wm * 64 + (lane >> 2);
    int col0 = wn * 16 + (lane & 3) * 2;
#pragma unroll
    for (int mt = 0; mt < 4; mt++)
#pragma unroll
        for (int nt = 0; nt < 2; nt++) {
            int row = r0 + mt * 16;
            int cn = col0 + nt * 8;
            long o0 = (long)(b * SEQ + row) * D_MODEL + h * HEAD_D + cn;
            long o1 = (long)(b * SEQ + row + 8) * D_MODEL + h * HEAD_D + cn;
            *(uint32_t*)(oh + o0) = pack2s(c[mt][nt][0], c[mt][nt][1]);
            *(uint32_t*)(oh + o1) = pack2s(c[mt][nt][2], c[mt][nt][3]);
        }
}

// ================= LayerNorm -> optional fp32 + fp16 =================
__global__ void ln_kernel(const float* __restrict__ x, const float* __restrict__ gam,
                          const float* __restrict__ bet, float* __restrict__ outF,
                          hf* __restrict__ oh) {
    __shared__ float redA[8], redB[8];
    int t = blockIdx.x;
    const float* xr = x + (size_t)t * D_MODEL;
    float v[4]; float s = 0.f;
#pragma unroll
    for (int i = 0; i < 4; i++) { v[i] = xr[threadIdx.x + 256 * i]; s += v[i]; }
#pragma unroll
    for (int o = 16; o; o >>= 1) s += __shfl_xor_sync(~0u, s, o);
    if ((threadIdx.x & 31) == 0) redA[threadIdx.x >> 5] = s;
    __syncthreads();
    if (threadIdx.x == 0) { float r = 0.f; for (int i = 0; i < 8; i++) r += redA[i]; redA[0] = r; }
    __syncthreads();
    float mu = redA[0] * (1.f / D_MODEL);
    float s2 = 0.f;
#pragma unroll
    for (int i = 0; i < 4; i++) { float d = v[i] - mu; s2 += d * d; }
#pragma unroll
    for (int o = 16; o; o >>= 1) s2 += __shfl_xor_sync(~0u, s2, o);
    if ((threadIdx.x & 31) == 0) redB[threadIdx.x >> 5] = s2;
    __syncthreads();
    if (threadIdx.x == 0) { float r = 0.f; for (int i = 0; i < 8; i++) r += redB[i]; redB[0] = r; }
    __syncthreads();
    float rstd = rsqrtf(redB[0] * (1.f / D_MODEL) + 1e-5f);
    size_t base = (size_t)t * D_MODEL;
#pragma unroll
    for (int i = 0; i < 4; i++) {
        int cc = threadIdx.x + 256 * i;
        float r = (v[i] - mu) * rstd * gam[cc] + bet[cc];
        if (outF) outF[base + cc] = r;
        oh[base + cc] = __float2half_rn(r);
    }
}

// ================= router / scan / combine =================
__global__ __launch_bounds__(256)
void router_kernel(const float* __restrict__ h2, const float* __restrict__ wr) {
    int t = blockIdx.x * 8 + (threadIdx.x >> 5);
    int lane = threadIdx.x & 31;
    const float* xr = h2 + (long)t * D_MODEL;
    float acc[8];
#pragma unroll
    for (int e = 0; e < 8; e++) acc[e] = 0.f;
    for (int i = lane; i < D_MODEL; i += 32) {
        float xv = xr[i];
        const float* w = wr + i * 8;
#pragma unroll
        for (int e = 0; e < 8; e++) acc[e] = fmaf(xv, w[e], acc[e]);
    }
#pragma unroll
    for (int o = 16; o; o >>= 1)
#pragma unroll
        for (int e = 0; e < 8; e++) acc[e] += __shfl_xor_sync(~0u, acc[e], o);
    if (lane == 0) {
        float m = acc[0]; int t1 = 0;
#pragma unroll
        for (int e = 1; e < 8; e++) if (acc[e] > m) { m = acc[e]; t1 = e; }
        float s = 0.f, pr[8];
#pragma unroll
        for (int e = 0; e < 8; e++) { pr[e] = expf(acc[e] - m); s += pr[e]; }
        float inv = 1.f / s;
        float m2 = -1e30f; int t2 = 0;
#pragma unroll
        for (int e = 0; e < 8; e++) {
            if (e == t1) continue;
            if (acc[e] > m2) { m2 = acc[e]; t2 = e; }
        }
        g_top1[t] = t1; g_top2[t] = t2;
        g_p1[t] = pr[t1] * inv;
        g_p2[t] = pr[t2] * inv;
    }
}

__global__ __launch_bounds__(256)
void scan_kernel() {
    int tid = threadIdx.x;
    for (int i = tid; i < NEXP * CAPV; i += 256) g_disp[i] = 0;
    __syncthreads();
    int e = tid >> 5;
    int lane = tid & 31;
    unsigned lt = (1u << lane) - 1u;
    int base = 0;
    for (int c0 = 0; c0 < N_TOK; c0 += 32) {
        int t = c0 + lane;
        bool f = (g_top1[t] == e);
        unsigned msk = __ballot_sync(~0u, f);
        if (f) {
            int loc = base + __popc(msk & lt);
            if (loc < CAPV) { g_s1[t] = loc; g_disp[e * CAPV + loc] = t; }
            else g_s1[t] = -1;
        }
        base += __popc(msk);
    }
    for (int c0 = 0; c0 < N_TOK; c0 += 32) {
        int t = c0 + lane;
        bool f = (g_top2[t] == e);
        unsigned msk = __ballot_sync(~0u, f);
        if (f) {
            int loc = base + __popc(msk & lt);
            if (loc < CAPV) { g_s2[t] = loc; g_disp[e * CAPV + loc] = t; }
            else g_s2[t] = -1;
        }
        base += __popc(msk);
    }
    __syncthreads();
    for (int t = tid; t < N_TOK; t += 256) {
        float t1 = (g_s1[t] >= 0) ? g_p1[t] : 0.f;
        float t2 = (g_s2[t] >= 0) ? g_p2[t] : 0.f;
        float den = fmaxf(t1 + t2, 1.1920929e-7f);
        g_g1[t] = t1 / den;
        g_g2[t] = t2 / den;
    }
}

__global__ __launch_bounds__(256)
void combine_kernel(float* __restrict__ out) {
    int t = blockIdx.x;
    int s1 = g_s1[t], s2 = g_s2[t];
    float g1 = g_g1[t], g2 = g_g2[t];
    const float* y1 = (s1 >= 0) ? g_y + ((long)g_top1[t] * CAPV + s1) * D_MODEL : 0;
    const float* y2 = (s2 >= 0) ? g_y + ((long)g_top2[t] * CAPV + s2) * D_MODEL : 0;
    long ro = (long)t * D_MODEL;
#pragma unroll
    for (int i = 0; i < 4; i++) {
        int d = threadIdx.x + 256 * i;
        float a = out[ro + d];
        if (y1) a = fmaf(g1, y1[d], a);
        if (y2) a = fmaf(g2, y2[d], a);
        out[ro + d] = a;
    }
}

// ================= launch =================
extern "C" void kernel_launch(void* const* d_in, const int* in_sizes, int n_in,
                              void* d_out, int out_size) {
    const float* x    = (const float*)d_in[0];
    const float* wq   = (const float*)d_in[1];
    const float* bq   = (const float*)d_in[2];
    const float* wk   = (const float*)d_in[3];
    const float* bk   = (const float*)d_in[4];
    const float* wv   = (const float*)d_in[5];
    const float* bv   = (const float*)d_in[6];
    const float* wo   = (const float*)d_in[7];
    const float* bo   = (const float*)d_in[8];
    const float* ln1g = (const float*)d_in[9];
    const float* ln1b = (const float*)d_in[10];
    const float* ln2g = (const float*)d_in[11];
    const float* ln2b = (const float*)d_in[12];
    const float* wr   = (const float*)d_in[13];
    const float* w1   = (const float*)d_in[14];
    const float* b1   = (const float*)d_in[15];
    const float* w2   = (const float*)d_in[16];
    const float* b2   = (const float*)d_in[17];
    float* out = (float*)d_out;

    hf *wq1, *wk1, *wv1, *wo1, *w11, *w21;
    hf *h1h, *h2h, *qh, *kh, *vh, *ath, *midh, *ph;
    float *h2, *sc, *y;
    int* disp;
    cudaGetSymbolAddress((void**)&wq1, g_wq1); cudaGetSymbolAddress((void**)&wk1, g_wk1);
    cudaGetSymbolAddress((void**)&wv1, g_wv1); cudaGetSymbolAddress((void**)&wo1, g_wo1);
    cudaGetSymbolAddress((void**)&w11, g_w11); cudaGetSymbolAddress((void**)&w21, g_w21);
    cudaGetSymbolAddress((void**)&h1h, g_h1h); cudaGetSymbolAddress((void**)&h2h, g_h2h);
    cudaGetSymbolAddress((void**)&qh, g_qh);   cudaGetSymbolAddress((void**)&kh, g_kh);
    cudaGetSymbolAddress((void**)&vh, g_vh);   cudaGetSymbolAddress((void**)&ath, g_ath);
    cudaGetSymbolAddress((void**)&midh, g_midh);
    cudaGetSymbolAddress((void**)&ph, g_ph);
    cudaGetSymbolAddress((void**)&h2, g_h2);
    cudaGetSymbolAddress((void**)&sc, g_sc);
    cudaGetSymbolAddress((void**)&y, g_y);
    cudaGetSymbolAddress((void**)&disp, g_disp);

    constexpr int SMEM128 = 3 * (10240 + 8192);    // 55296
    constexpr int SMEM256 = 3 * (10240 + 16384);   // 79872
    cudaFuncSetAttribute(gemm_mma<128, false, false, true, true>,
                         cudaFuncAttributeMaxDynamicSharedMemorySize, SMEM128);
    cudaFuncSetAttribute(gemm_mma<128, false, false, false, false>,
                         cudaFuncAttributeMaxDynamicSharedMemorySize, SMEM128);
    cudaFuncSetAttribute(gemm_mma<256, true, true, false, true>,
                         cudaFuncAttributeMaxDynamicSharedMemorySize, SMEM256);
    cudaFuncSetAttribute(gemm_mma<256, false, false, false, false>,
                         cudaFuncAttributeMaxDynamicSharedMemorySize, SMEM256);
    cudaFuncSetAttribute(scores_mma, cudaFuncAttributeMaxDynamicSharedMemorySize, SC_SMEM);
    cudaFuncSetAttribute(pv_mma, cudaFuncAttributeMaxDynamicSharedMemorySize, PV_SMEM);

    // 0) weight rounding (single fp16 plane)
    round_attn<<<dim3(256, 1, 4), 256>>>(wq, wk, wv, wo, wq1, wk1, wv1, wo1);
    round_pass<<<4096, 256>>>(w1, w11, 33554432 / 4);
    round_pass<<<4096, 256>>>(w2, w21, 33554432 / 4);

    // 1) LN1 -> fp16
    ln_kernel<<<N_TOK, 256>>>(x, ln1g, ln1b, nullptr, h1h);

    // 2) QKV fused
    gemm_mma<128, false, false, true, true><<<dim3(8, 16, 3), 256, SMEM128>>>(
        h1h, wq1, wk1, wv1, bq, bk, bv,
        nullptr, qh, kh, vh, 0.125f, 1.f, 1.f,
        nullptr, nullptr, 1024, 1024, 0, 0, 0, 0);

    // 3) attention
    scores_mma<<<dim3(4, 4, NB * N_HEADS), 256, SC_SMEM>>>(qh, kh, sc);
    softmax_kernel<<<NB * N_HEADS * SEQ, 128>>>(sc, ph);
    pv_mma<<<dim3(4, NB * N_HEADS), 256, PV_SMEM>>>(ph, vh, ath);

    // 4) O projection + residual
    gemm_mma<128, false, false, false, false><<<dim3(8, 16, 1), 256, SMEM128>>>(
        ath, wo1, nullptr, nullptr, bo, nullptr, nullptr,
        out, nullptr, nullptr, nullptr, 1.f, 0.f, 0.f,
        x, nullptr, 1024, 1024, 0, 0, 0, 0);

    // 5) LN2
    ln_kernel<<<N_TOK, 256>>>(out, ln2g, ln2b, h2, h2h);

    // 6) router + scan
    router_kernel<<<N_TOK / 8, 256>>>(h2, wr);
    scan_kernel<<<1, 256>>>();

    // 7) FFN1 gathered + relu -> fp16 mid (TN=256)
    gemm_mma<256, true, true, false, true><<<dim3(16, 4, 8), 256, SMEM256>>>(
        h2h, w11, nullptr, nullptr, b1, nullptr, nullptr,
        nullptr, midh, nullptr, nullptr, 1.f, 0.f, 0.f,
        nullptr, disp, 1024, 4096, 0, (long)D_MODEL * FFN_D, FFN_D, (long)CAPV * FFN_D);

    // 8) FFN2 -> fp32 y (*0.8) (TN=256)
    gemm_mma<256, false, false, false, false><<<dim3(4, 4, 8), 256, SMEM256>>>(
        midh, w21, nullptr, nullptr, b2, nullptr, nullptr,
        y, nullptr, nullptr, nullptr, 0.8f, 0.f, 0.f,
        nullptr, nullptr, 4096, 1024,
        (long)CAPV * FFN_D, (long)FFN_D * D_MODEL, D_MODEL, (long)CAPV * D_MODEL);

    // 9) combine
    combine_kernel<<<N_TOK, 256>>>(out);
}

// round 13
// speedup vs baseline: 2.2074x; 1.0984x over previous
#include <cuda_runtime.h>
#include <cuda_fp16.h>
#include <cstdint>

#define D_MODEL 1024
#define N_TOK   2048
#define N_HEADS 16
#define HEAD_D  64
#define SEQ     512
#define NB      4
#define FFN_D   4096
#define NEXP    8
#define CAPV    512

typedef __half hf;

// ================= device scratch =================
__device__ hf g_wq1[1048576], g_wk1[1048576], g_wv1[1048576], g_wo1[1048576];
__device__ hf g_w11[33554432], g_w21[33554432];
__device__ hf g_h1h[2097152];
__device__ hf g_h2h[2097152];
__device__ float g_h2[2097152];
__device__ hf g_qh[2097152];
__device__ hf g_kh[2097152];
__device__ hf g_vh[2097152];
__device__ hf g_ath[2097152];
__device__ hf g_midh[16777216];
__device__ hf g_ph[16777216];
__device__ float g_sc[16777216];
__device__ float g_y[4194304];
__device__ int   g_top1[N_TOK], g_top2[N_TOK];
__device__ float g_p1[N_TOK], g_p2[N_TOK];
__device__ int   g_s1[N_TOK], g_s2[N_TOK];
__device__ float g_g1[N_TOK], g_g2[N_TOK];
__device__ int   g_disp[NEXP * CAPV];

// ================= helpers =================
__device__ __forceinline__ uint32_t smem_u32(const void* p) {
    uint32_t a;
    asm("{ .reg .u64 t; cvta.to.shared.u64 t, %1; cvt.u32.u64 %0, t; }" : "=r"(a) : "l"(p));
    return a;
}
__device__ __forceinline__ void ldsm_x4(uint32_t* r, uint32_t addr) {
    asm volatile("ldmatrix.sync.aligned.m8n8.x4.shared.b16 {%0,%1,%2,%3}, [%4];"
        : "=r"(r[0]), "=r"(r[1]), "=r"(r[2]), "=r"(r[3]) : "r"(addr));
}
__device__ __forceinline__ void ldsm_x4t(uint32_t* r, uint32_t addr) {
    asm volatile("ldmatrix.sync.aligned.m8n8.x4.trans.shared.b16 {%0,%1,%2,%3}, [%4];"
        : "=r"(r[0]), "=r"(r[1]), "=r"(r[2]), "=r"(r[3]) : "r"(addr));
}
__device__ __forceinline__ void mma16816(float* c, const uint32_t* a, uint32_t b0, uint32_t b1) {
    asm volatile(
        "mma.sync.aligned.m16n8k16.row.col.f32.f16.f16.f32 "
        "{%0,%1,%2,%3}, {%4,%5,%6,%7}, {%8,%9}, {%0,%1,%2,%3};"
        : "+f"(c[0]), "+f"(c[1]), "+f"(c[2]), "+f"(c[3])
        : "r"(a[0]), "r"(a[1]), "r"(a[2]), "r"(a[3]), "r"(b0), "r"(b1));
}
__device__ __forceinline__ void cp16(uint32_t dst, const void* src) {
    asm volatile("cp.async.cg.shared.global [%0], [%1], 16;" :: "r"(dst), "l"(src) : "memory");
}
#define CP_COMMIT() asm volatile("cp.async.commit_group;" ::: "memory")
__device__ __forceinline__ uint32_t pack2s(float x, float y) {
    return (uint32_t)__half_as_ushort(__float2half_rn(x)) |
           ((uint32_t)__half_as_ushort(__float2half_rn(y)) << 16);
}

// ================= weight rounding passes =================
__global__ __launch_bounds__(256)
void round_pass(const float* __restrict__ src, hf* __restrict__ dst, long n4) {
    for (long i = blockIdx.x * 256 + threadIdx.x; i < n4; i += (long)gridDim.x * 256) {
        float4 v = *(const float4*)(src + i * 4);
        *(uint2*)(dst + i * 4) = make_uint2(pack2s(v.x, v.y), pack2s(v.z, v.w));
    }
}

__global__ __launch_bounds__(256)
void round_attn(const float* __restrict__ wq, const float* __restrict__ wk,
                const float* __restrict__ wv, const float* __restrict__ wo,
                hf* __restrict__ q1, hf* __restrict__ k1,
                hf* __restrict__ v1, hf* __restrict__ o1) {
    int z = blockIdx.z;
    const float* src = (z == 0) ? wq : (z == 1) ? wk : (z == 2) ? wv : wo;
    hf* dst = (z == 0) ? q1 : (z == 1) ? k1 : (z == 2) ? v1 : o1;
    const long n4 = 262144;
    for (long i = blockIdx.x * 256 + threadIdx.x; i < n4; i += (long)gridDim.x * 256) {
        float4 v = *(const float4*)(src + i * 4);
        *(uint2*)(dst + i * 4) = make_uint2(pack2s(v.x, v.y), pack2s(v.z, v.w));
    }
}

// ================= fp16 HMMA GEMM: CTA 128x128, Kc=32, 3-stage cp.async, 2 CTAs/SM =================
#define A_O 0
#define B_O 10240
#define STGB 18432
#define GEMM_SMEM (3 * STGB)

template <bool RELU, bool GATHER, bool MULTI, bool OSPLIT>
__global__ __launch_bounds__(256, 2)
void gemm_mma(const hf* __restrict__ A,
              const hf* __restrict__ B0, const hf* __restrict__ B1,
              const hf* __restrict__ B2,
              const float* __restrict__ bi0, const float* __restrict__ bi1,
              const float* __restrict__ bi2,
              float* __restrict__ oF0,
              hf* __restrict__ oH0, hf* __restrict__ oH1, hf* __restrict__ oH2,
              float s0, float s1, float s2,
              const float* __restrict__ resid, const int* __restrict__ gather,
              int K, int N,
              long aStride, long bStride, long biStride, long oStride) {
    extern __shared__ char sm[];
    uint32_t sb = smem_u32(sm);
    int tid = threadIdx.x, wid = tid >> 5, lane = tid & 31;
    int z = blockIdx.z;
    int m0 = blockIdx.y * 128, n0 = blockIdx.x * 128;

    const hf* B; const float* bi; float scale;
    float* oF = nullptr; hf* oH = nullptr;
    if (MULTI) {
        B = (z == 0) ? B0 : (z == 1) ? B1 : B2;
        bi = (z == 0) ? bi0 : (z == 1) ? bi1 : bi2;
        scale = (z == 0) ? s0 : (z == 1) ? s1 : s2;
        oH = (z == 0) ? oH0 : (z == 1) ? oH1 : oH2;
    } else {
        B = B0 + (long)z * bStride;
        bi = bi0 + (long)z * biStride;
        scale = s0;
        if (OSPLIT) oH = oH0 + (long)z * oStride;
        else oF = oF0 + (long)z * oStride;
    }
    const hf* Az = A + (MULTI ? 0 : (long)z * aStride);
    const int* gz = GATHER ? (gather + z * CAPV) : nullptr;

    int aR0 = tid >> 2, aC0 = (tid & 3) * 8;
    int aR1 = (tid + 256) >> 2, aC1 = ((tid + 256) & 3) * 8;
    long aRow0 = GATHER ? (long)gz[m0 + aR0] : (long)(m0 + aR0);
    long aRow1 = GATHER ? (long)gz[m0 + aR1] : (long)(m0 + aR1);
    long aG0 = aRow0 * K + aC0;
    long aG1 = aRow1 * K + aC1;
    int aD0 = aR0 * 80 + aC0 * 2;
    int aD1 = aR1 * 80 + aC1 * 2;

    int bK0 = tid >> 4, bN0 = (tid & 15) * 8;
    long bG0 = (long)bK0 * N + n0 + bN0;
    int bD0 = bK0 * 256 + ((bN0 * 2) ^ ((bK0 & 7) << 4));

    int nCh = K >> 5;
#pragma unroll
    for (int pre = 0; pre < 2; pre++) {
        uint32_t base = sb + (uint32_t)pre * STGB;
        int k0 = pre << 5;
        long ko = (long)k0 * N;
        cp16(base + A_O + aD0, Az + aG0 + k0);
        cp16(base + A_O + aD1, Az + aG1 + k0);
        cp16(base + B_O + bD0, B + ko + bG0);
        cp16(base + B_O + bD0 + 4096, B + ko + bG0 + 16L * N);
        CP_COMMIT();
    }

    float c[4][4][4];
#pragma unroll
    for (int mt = 0; mt < 4; mt++)
#pragma unroll
        for (int nt = 0; nt < 4; nt++)
#pragma unroll
            for (int f = 0; f < 4; f++) c[mt][nt][f] = 0.f;

    int wm = wid >> 2, wn = wid & 3;
    int aRowOff = (lane & 7) + ((lane >> 3) & 1) * 8;
    int aColSel = ((lane >> 4) & 1) * 16;
    int bKoff = (lane & 7) + ((lane >> 3) & 1) * 8;
    int bN8 = ((lane >> 4) & 1) * 8;

    for (int ch = 0; ch < nCh; ch++) {
        if (ch + 1 < nCh) asm volatile("cp.async.wait_group 1;" ::: "memory");
        else              asm volatile("cp.async.wait_group 0;" ::: "memory");
        __syncthreads();
        if (ch + 2 < nCh) {
            int chn = ch + 2;
            uint32_t base = sb + (uint32_t)(chn % 3) * STGB;
            int k0 = chn << 5;
            long ko = (long)k0 * N;
            cp16(base + A_O + aD0, Az + aG0 + k0);
            cp16(base + A_O + aD1, Az + aG1 + k0);
            cp16(base + B_O + bD0, B + ko + bG0);
            cp16(base + B_O + bD0 + 4096, B + ko + bG0 + 16L * N);
            CP_COMMIT();
        }
        uint32_t sbuf = sb + (uint32_t)(ch % 3) * STGB;
#pragma unroll
        for (int ks = 0; ks < 2; ks++) {
            uint32_t ah[4][4];
#pragma unroll
            for (int mt = 0; mt < 4; mt++) {
                uint32_t ro = (wm * 64 + mt * 16 + aRowOff) * 80 + ks * 32 + aColSel;
                ldsm_x4(ah[mt], sbuf + A_O + ro);
            }
#pragma unroll
            for (int nb = 0; nb < 2; nb++) {
                uint32_t bhf[4];
                int kk = ks * 16 + bKoff;
                int nn = wn * 32 + nb * 16 + bN8;
                uint32_t off = kk * 256 + ((nn * 2) ^ ((kk & 7) << 4));
                ldsm_x4t(bhf, sbuf + B_O + off);
#pragma unroll
                for (int hfk = 0; hfk < 2; hfk++) {
                    int nt = nb * 2 + hfk;
#pragma unroll
                    for (int mt = 0; mt < 4; mt++)
                        mma16816(c[mt][nt], ah[mt], bhf[hfk * 2], bhf[hfk * 2 + 1]);
                }
            }
        }
    }

    int r0 = m0 + wm * 64 + (lane >> 2);
    int col0 = n0 + wn * 32 + (lane & 3) * 2;
#pragma unroll
    for (int mt = 0; mt < 4; mt++) {
#pragma unroll
        for (int nt = 0; nt < 4; nt++) {
            int row = r0 + mt * 16;
            int cn = col0 + nt * 8;
            float2 bb = *(const float2*)(bi + cn);
            float v0x = (c[mt][nt][0] + bb.x) * scale;
            float v0y = (c[mt][nt][1] + bb.y) * scale;
            float v1x = (c[mt][nt][2] + bb.x) * scale;
            float v1y = (c[mt][nt][3] + bb.y) * scale;
            if (resid) {
                float2 ra = *(const float2*)(resid + (long)row * N + cn);
                float2 rb = *(const float2*)(resid + (long)(row + 8) * N + cn);
                v0x += ra.x; v0y += ra.y; v1x += rb.x; v1y += rb.y;
            }
            if (RELU) {
                v0x = fmaxf(v0x, 0.f); v0y = fmaxf(v0y, 0.f);
                v1x = fmaxf(v1x, 0.f); v1y = fmaxf(v1y, 0.f);
            }
            if (OSPLIT) {
                *(uint32_t*)(oH + (long)row * N + cn) = pack2s(v0x, v0y);
                *(uint32_t*)(oH + (long)(row + 8) * N + cn) = pack2s(v1x, v1y);
            } else {
                *(float2*)(oF + (long)row * N + cn) = make_float2(v0x, v0y);
                *(float2*)(oF + (long)(row + 8) * N + cn) = make_float2(v1x, v1y);
            }
        }
    }
}

// ================= scores: S = Q.K^T per (b,h), CTA 128x128, K=64 =================
#define SC_Q 0
#define SC_K 18432
#define SC_SMEM 36864

__global__ __launch_bounds__(256, 1)
void scores_mma(const hf* __restrict__ qh, const hf* __restrict__ kh,
                float* __restrict__ sc) {
    extern __shared__ char sm[];
    uint32_t sb = smem_u32(sm);
    int tid = threadIdx.x, wid = tid >> 5, lane = tid & 31;
    int bh = blockIdx.z;
    int b = bh >> 4, h = bh & 15;
    int m0 = blockIdx.y * 128, n0 = blockIdx.x * 128;

#pragma unroll
    for (int i = 0; i < 4; i++) {
        int v = tid + 256 * i;
        int row = v >> 3, c8 = (v & 7) * 8;
        int off = row * 144 + c8 * 2;
        long qg = (long)(b * SEQ + m0 + row) * D_MODEL + h * HEAD_D + c8;
        long kg = (long)(b * SEQ + n0 + row) * D_MODEL + h * HEAD_D + c8;
        *(uint4*)(sm + SC_Q + off) = *(const uint4*)(qh + qg);
        *(uint4*)(sm + SC_K + off) = *(const uint4*)(kh + kg);
    }
    __syncthreads();

    float c[4][4][4];
#pragma unroll
    for (int mt = 0; mt < 4; mt++)
#pragma unroll
        for (int nt = 0; nt < 4; nt++)
#pragma unroll
            for (int f = 0; f < 4; f++) c[mt][nt][f] = 0.f;

    int wm = wid >> 2, wn = wid & 3;
    int rowOff = (lane & 7) + ((lane >> 3) & 1) * 8;
    int colSel = ((lane >> 4) & 1) * 16;

#pragma unroll
    for (int ks = 0; ks < 4; ks++) {
        uint32_t ah[4][4];
#pragma unroll
        for (int mt = 0; mt < 4; mt++) {
            uint32_t ro = (wm * 64 + mt * 16 + rowOff) * 144 + ks * 32 + colSel;
            ldsm_x4(ah[mt], sb + SC_Q + ro);
        }
        uint32_t bh_[2][4];
#pragma unroll
        for (int nb = 0; nb < 2; nb++) {
            uint32_t ro = (wn * 32 + nb * 16 + rowOff) * 144 + ks * 32 + colSel;
            ldsm_x4(bh_[nb], sb + SC_K + ro);
        }
#pragma unroll
        for (int mt = 0; mt < 4; mt++)
#pragma unroll
            for (int nt = 0; nt < 4; nt++) {
                int nb = nt >> 1, hfk = nt & 1;
                mma16816(c[mt][nt], ah[mt], bh_[nb][hfk], bh_[nb][hfk + 2]);
            }
    }

    long base = (long)bh * SEQ * SEQ;
    int r0 = m0 + wm * 64 + (lane >> 2);
    int col0 = n0 + wn * 32 + (lane & 3) * 2;
#pragma unroll
    for (int mt = 0; mt < 4; mt++)
#pragma unroll
        for (int nt = 0; nt < 4; nt++) {
            int row = r0 + mt * 16, cn = col0 + nt * 8;
            *(float2*)(sc + base + (long)row * SEQ + cn) = make_float2(c[mt][nt][0], c[mt][nt][1]);
            *(float2*)(sc + base + (long)(row + 8) * SEQ + cn) = make_float2(c[mt][nt][2], c[mt][nt][3]);
        }
}

// ================= softmax: fp32 -> fp16 P =================
__global__ __launch_bounds__(128)
void softmax_kernel(const float* __restrict__ sc, hf* __restrict__ ph) {
    __shared__ float redM[4], redS[4];
    const float* row = sc + (size_t)blockIdx.x * SEQ;
    float v[4]; float m = -1e30f;
#pragma unroll
    for (int i = 0; i < 4; i++) { v[i] = row[threadIdx.x + 128 * i]; m = fmaxf(m, v[i]); }
#pragma unroll
    for (int o = 16; o; o >>= 1) m = fmaxf(m, __shfl_xor_sync(~0u, m, o));
    if ((threadIdx.x & 31) == 0) redM[threadIdx.x >> 5] = m;
    __syncthreads();
    m = fmaxf(fmaxf(redM[0], redM[1]), fmaxf(redM[2], redM[3]));
    float s = 0.f;
#pragma unroll
    for (int i = 0; i < 4; i++) { v[i] = expf(v[i] - m); s += v[i]; }
#pragma unroll
    for (int o = 16; o; o >>= 1) s += __shfl_xor_sync(~0u, s, o);
    if ((threadIdx.x & 31) == 0) redS[threadIdx.x >> 5] = s;
    __syncthreads();
    s = redS[0] + redS[1] + redS[2] + redS[3];
    float inv = 1.f / s;
    size_t base = (size_t)blockIdx.x * SEQ;
#pragma unroll
    for (int i = 0; i < 4; i++) {
        float p = v[i] * inv;
        ph[base + threadIdx.x + 128 * i] = __float2half_rn(p);
    }
}

// ================= PV: O = P.V per (b,h), CTA 128x64, Kc=32 =================
#define PV_P 0
#define PV_V 10240
#define PV_BUF 14336
#define PV_SMEM (2 * PV_BUF)

__global__ __launch_bounds__(256, 1)
void pv_mma(const hf* __restrict__ ph, const hf* __restrict__ vh,
            hf* __restrict__ oh) {
    extern __shared__ char sm[];
    uint32_t sb = smem_u32(sm);
    int tid = threadIdx.x, wid = tid >> 5, lane = tid & 31;
    int bh = blockIdx.y;
    int b = bh >> 4, h = bh & 15;
    int m0 = blockIdx.x * 128;

    int v0 = tid, v1 = tid + 256;
    int aR0 = v0 >> 2, aC0 = (v0 & 3) * 8;
    int aR1 = v1 >> 2, aC1 = (v1 & 3) * 8;
    long pBase = (long)bh * SEQ * SEQ;
    long aG0 = pBase + (long)(m0 + aR0) * SEQ + aC0;
    long aG1 = pBase + (long)(m0 + aR1) * SEQ + aC1;
    int aS0 = aR0 * 80 + aC0 * 2;
    int aS1 = aR1 * 80 + aC1 * 2;
    int bKr = tid >> 3, bN0 = (tid & 7) * 8;
    long bG = (long)(b * SEQ + bKr) * D_MODEL + h * HEAD_D + bN0;
    int bS = bKr * 128 + ((bN0 * 2) ^ ((bKr & 7) << 4));

    float c[4][2][4];
#pragma unroll
    for (int mt = 0; mt < 4; mt++)
#pragma unroll
        for (int nt = 0; nt < 2; nt++)
#pragma unroll
            for (int f = 0; f < 4; f++) c[mt][nt][f] = 0.f;

    int wm = wid >> 2, wn = wid & 3;
    int aRowOff = (lane & 7) + ((lane >> 3) & 1) * 8;
    int aColSel = ((lane >> 4) & 1) * 16;
    int bKoff = (lane & 7) + ((lane >> 3) & 1) * 8;
    int bN8 = ((lane >> 4) & 1) * 8;

    uint4 vph0 = *(const uint4*)(ph + aG0), vph1 = *(const uint4*)(ph + aG1);
    uint4 vvh = *(const uint4*)(vh + bG);

    for (int ch = 0; ch < 16; ch++) {
        char* smb = sm + (ch & 1) * PV_BUF;
        uint32_t sbuf = sb + (ch & 1) * PV_BUF;
        __syncthreads();
        *(uint4*)(smb + PV_P + aS0) = vph0; *(uint4*)(smb + PV_P + aS1) = vph1;
        *(uint4*)(smb + PV_V + bS) = vvh;
        __syncthreads();
        if (ch < 15) {
            int k0 = (ch + 1) << 5;
            vph0 = *(const uint4*)(ph + aG0 + k0);
            vph1 = *(const uint4*)(ph + aG1 + k0);
            vvh = *(const uint4*)(vh + bG + (long)k0 * D_MODEL);
        }
#pragma unroll
        for (int ks = 0; ks < 2; ks++) {
            uint32_t ah[4][4];
#pragma unroll
            for (int mt = 0; mt < 4; mt++) {
                uint32_t ro = (wm * 64 + mt * 16 + aRowOff) * 80 + ks * 32 + aColSel;
                ldsm_x4(ah[mt], sbuf + PV_P + ro);
            }
            uint32_t bh_[4];
            {
                int kk = ks * 16 + bKoff;
                int nn = wn * 16 + bN8;
                uint32_t off = kk * 128 + ((nn * 2) ^ ((kk & 7) << 4));
                ldsm_x4t(bh_, sbuf + PV_V + off);
            }
#pragma unroll
            for (int mt = 0; mt < 4; mt++)
#pragma unroll
                for (int nt = 0; nt < 2; nt++)
                    mma16816(c[mt][nt], ah[mt], bh_[nt * 2], bh_[nt * 2 + 1]);
        }
    }

    int r0 = m0 + wm * 64 + (lane >> 2);
    int col0 = wn * 16 + (lane & 3) * 2;
#pragma unroll
    for (int mt = 0; mt < 4; mt++)
#pragma unroll
        for (int nt = 0; nt < 2; nt++) {
            int row = r0 + mt * 16;
            int cn = col0 + nt * 8;
            long o0 = (long)(b * SEQ + row) * D_MODEL + h * HEAD_D + cn;
            long o1 = (long)(b * SEQ + row + 8) * D_MODEL + h * HEAD_D + cn;
            *(uint32_t*)(oh + o0) = pack2s(c[mt][nt][0], c[mt][nt][1]);
            *(uint32_t*)(oh + o1) = pack2s(c[mt][nt][2], c[mt][nt][3]);
        }
}

// ================= LayerNorm -> optional fp32 + fp16 =================
__global__ void ln_kernel(const float* __restrict__ x, const float* __restrict__ gam,
                          const float* __restrict__ bet, float* __restrict__ outF,
                          hf* __restrict__ oh) {
    __shared__ float redA[8], redB[8];
    int t = blockIdx.x;
    const float* xr = x + (size_t)t * D_MODEL;
    float v[4]; float s = 0.f;
#pragma unroll
    for (int i = 0; i < 4; i++) { v[i] = xr[threadIdx.x + 256 * i]; s += v[i]; }
#pragma unroll
    for (int o = 16; o; o >>= 1) s += __shfl_xor_sync(~0u, s, o);
    if ((threadIdx.x & 31) == 0) redA[threadIdx.x >> 5] = s;
    __syncthreads();
    if (threadIdx.x == 0) { float r = 0.f; for (int i = 0; i < 8; i++) r += redA[i]; redA[0] = r; }
    __syncthreads();
    float mu = redA[0] * (1.f / D_MODEL);
    float s2 = 0.f;
#pragma unroll
    for (int i = 0; i < 4; i++) { float d = v[i] - mu; s2 += d * d; }
#pragma unroll
    for (int o = 16; o; o >>= 1) s2 += __shfl_xor_sync(~0u, s2, o);
    if ((threadIdx.x & 31) == 0) redB[threadIdx.x >> 5] = s2;
    __syncthreads();
    if (threadIdx.x == 0) { float r = 0.f; for (int i = 0; i < 8; i++) r += redB[i]; redB[0] = r; }
    __syncthreads();
    float rstd = rsqrtf(redB[0] * (1.f / D_MODEL) + 1e-5f);
    size_t base = (size_t)t * D_MODEL;
#pragma unroll
    for (int i = 0; i < 4; i++) {
        int cc = threadIdx.x + 256 * i;
        float r = (v[i] - mu) * rstd * gam[cc] + bet[cc];
        if (outF) outF[base + cc] = r;
        oh[base + cc] = __float2half_rn(r);
    }
}

// ================= router / scan / combine =================
__global__ __launch_bounds__(256)
void router_kernel(const float* __restrict__ h2, const float* __restrict__ wr) {
    int t = blockIdx.x * 8 + (threadIdx.x >> 5);
    int lane = threadIdx.x & 31;
    const float* xr = h2 + (long)t * D_MODEL;
    float acc[8];
#pragma unroll
    for (int e = 0; e < 8; e++) acc[e] = 0.f;
    for (int i = lane; i < D_MODEL; i += 32) {
        float xv = xr[i];
        const float* w = wr + i * 8;
#pragma unroll
        for (int e = 0; e < 8; e++) acc[e] = fmaf(xv, w[e], acc[e]);
    }
#pragma unroll
    for (int o = 16; o; o >>= 1)
#pragma unroll
        for (int e = 0; e < 8; e++) acc[e] += __shfl_xor_sync(~0u, acc[e], o);
    if (lane == 0) {
        float m = acc[0]; int t1 = 0;
#pragma unroll
        for (int e = 1; e < 8; e++) if (acc[e] > m) { m = acc[e]; t1 = e; }
        float s = 0.f, pr[8];
#pragma unroll
        for (int e = 0; e < 8; e++) { pr[e] = expf(acc[e] - m); s += pr[e]; }
        float inv = 1.f / s;
        float m2 = -1e30f; int t2 = 0;
#pragma unroll
        for (int e = 0; e < 8; e++) {
            if (e == t1) continue;
            if (acc[e] > m2) { m2 = acc[e]; t2 = e; }
        }
        g_top1[t] = t1; g_top2[t] = t2;
        g_p1[t] = pr[t1] * inv;
        g_p2[t] = pr[t2] * inv;
    }
}

__global__ __launch_bounds__(256)
void scan_kernel() {
    int tid = threadIdx.x;
    for (int i = tid; i < NEXP * CAPV; i += 256) g_disp[i] = 0;
    __syncthreads();
    int e = tid >> 5;
    int lane = tid & 31;
    unsigned lt = (1u << lane) - 1u;
    int base = 0;
    for (int c0 = 0; c0 < N_TOK; c0 += 32) {
        int t = c0 + lane;
        bool f = (g_top1[t] == e);
        unsigned msk = __ballot_sync(~0u, f);
        if (f) {
            int loc = base + __popc(msk & lt);
            if (loc < CAPV) { g_s1[t] = loc; g_disp[e * CAPV + loc] = t; }
            else g_s1[t] = -1;
        }
        base += __popc(msk);
    }
    for (int c0 = 0; c0 < N_TOK; c0 += 32) {
        int t = c0 + lane;
        bool f = (g_top2[t] == e);
        unsigned msk = __ballot_sync(~0u, f);
        if (f) {
            int loc = base + __popc(msk & lt);
            if (loc < CAPV) { g_s2[t] = loc; g_disp[e * CAPV + loc] = t; }
            else g_s2[t] = -1;
        }
        base += __popc(msk);
    }
    __syncthreads();
    for (int t = tid; t < N_TOK; t += 256) {
        float t1 = (g_s1[t] >= 0) ? g_p1[t] : 0.f;
        float t2 = (g_s2[t] >= 0) ? g_p2[t] : 0.f;
        float den = fmaxf(t1 + t2, 1.1920929e-7f);
        g_g1[t] = t1 / den;
        g_g2[t] = t2 / den;
    }
}

__global__ __launch_bounds__(256)
void combine_kernel(float* __restrict__ out) {
    int t = blockIdx.x;
    int s1 = g_s1[t], s2 = g_s2[t];
    float g1 = g_g1[t], g2 = g_g2[t];
    const float* y1 = (s1 >= 0) ? g_y + ((long)g_top1[t] * CAPV + s1) * D_MODEL : 0;
    const float* y2 = (s2 >= 0) ? g_y + ((long)g_top2[t] * CAPV + s2) * D_MODEL : 0;
    long ro = (long)t * D_MODEL;
#pragma unroll
    for (int i = 0; i < 4; i++) {
        int d = threadIdx.x + 256 * i;
        float a = out[ro + d];
        if (y1) a = fmaf(g1, y1[d], a);
        if (y2) a = fmaf(g2, y2[d], a);
        out[ro + d] = a;
    }
}

// ================= launch =================
extern "C" void kernel_launch(void* const* d_in, const int* in_sizes, int n_in,
                              void* d_out, int out_size) {
    const float* x    = (const float*)d_in[0];
    const float* wq   = (const float*)d_in[1];
    const float* bq   = (const float*)d_in[2];
    const float* wk   = (const float*)d_in[3];
    const float* bk   = (const float*)d_in[4];
    const float* wv   = (const float*)d_in[5];
    const float* bv   = (const float*)d_in[6];
    const float* wo   = (const float*)d_in[7];
    const float* bo   = (const float*)d_in[8];
    const float* ln1g = (const float*)d_in[9];
    const float* ln1b = (const float*)d_in[10];
    const float* ln2g = (const float*)d_in[11];
    const float* ln2b = (const float*)d_in[12];
    const float* wr   = (const float*)d_in[13];
    const float* w1   = (const float*)d_in[14];
    const float* b1   = (const float*)d_in[15];
    const float* w2   = (const float*)d_in[16];
    const float* b2   = (const float*)d_in[17];
    float* out = (float*)d_out;

    hf *wq1, *wk1, *wv1, *wo1, *w11, *w21;
    hf *h1h, *h2h, *qh, *kh, *vh, *ath, *midh, *ph;
    float *h2, *sc, *y;
    int* disp;
    cudaGetSymbolAddress((void**)&wq1, g_wq1); cudaGetSymbolAddress((void**)&wk1, g_wk1);
    cudaGetSymbolAddress((void**)&wv1, g_wv1); cudaGetSymbolAddress((void**)&wo1, g_wo1);
    cudaGetSymbolAddress((void**)&w11, g_w11); cudaGetSymbolAddress((void**)&w21, g_w21);
    cudaGetSymbolAddress((void**)&h1h, g_h1h); cudaGetSymbolAddress((void**)&h2h, g_h2h);
    cudaGetSymbolAddress((void**)&qh, g_qh);   cudaGetSymbolAddress((void**)&kh, g_kh);
    cudaGetSymbolAddress((void**)&vh, g_vh);   cudaGetSymbolAddress((void**)&ath, g_ath);
    cudaGetSymbolAddress((void**)&midh, g_midh);
    cudaGetSymbolAddress((void**)&ph, g_ph);
    cudaGetSymbolAddress((void**)&h2, g_h2);
    cudaGetSymbolAddress((void**)&sc, g_sc);
    cudaGetSymbolAddress((void**)&y, g_y);
    cudaGetSymbolAddress((void**)&disp, g_disp);

    cudaFuncSetAttribute(gemm_mma<false, false, true, true>,
                         cudaFuncAttributeMaxDynamicSharedMemorySize, GEMM_SMEM);
    cudaFuncSetAttribute(gemm_mma<false, false, false, false>,
                         cudaFuncAttributeMaxDynamicSharedMemorySize, GEMM_SMEM);
    cudaFuncSetAttribute(gemm_mma<true, true, false, true>,
                         cudaFuncAttributeMaxDynamicSharedMemorySize, GEMM_SMEM);
    cudaFuncSetAttribute(scores_mma, cudaFuncAttributeMaxDynamicSharedMemorySize, SC_SMEM);
    cudaFuncSetAttribute(pv_mma, cudaFuncAttributeMaxDynamicSharedMemorySize, PV_SMEM);

    // 0) weight rounding (single fp16 plane)
    round_attn<<<dim3(256, 1, 4), 256>>>(wq, wk, wv, wo, wq1, wk1, wv1, wo1);
    round_pass<<<4096, 256>>>(w1, w11, 33554432 / 4);
    round_pass<<<4096, 256>>>(w2, w21, 33554432 / 4);

    // 1) LN1 -> fp16
    ln_kernel<<<N_TOK, 256>>>(x, ln1g, ln1b, nullptr, h1h);

    // 2) QKV fused (2 CTAs/SM)
    gemm_mma<false, false, true, true><<<dim3(8, 16, 3), 256, GEMM_SMEM>>>(
        h1h, wq1, wk1, wv1, bq, bk, bv,
        nullptr, qh, kh, vh, 0.125f, 1.f, 1.f,
        nullptr, nullptr, 1024, 1024, 0, 0, 0, 0);

    // 3) attention
    scores_mma<<<dim3(4, 4, NB * N_HEADS), 256, SC_SMEM>>>(qh, kh, sc);
    softmax_kernel<<<NB * N_HEADS * SEQ, 128>>>(sc, ph);
    pv_mma<<<dim3(4, NB * N_HEADS), 256, PV_SMEM>>>(ph, vh, ath);

    // 4) O projection + residual
    gemm_mma<false, false, false, false><<<dim3(8, 16, 1), 256, GEMM_SMEM>>>(
        ath, wo1, nullptr, nullptr, bo, nullptr, nullptr,
        out, nullptr, nullptr, nullptr, 1.f, 0.f, 0.f,
        x, nullptr, 1024, 1024, 0, 0, 0, 0);

    // 5) LN2
    ln_kernel<<<N_TOK, 256>>>(out, ln2g, ln2b, h2, h2h);

    // 6) router + scan
    router_kernel<<<N_TOK / 8, 256>>>(h2, wr);
    scan_kernel<<<1, 256>>>();

    // 7) FFN1 gathered + relu -> fp16 mid (TN=128, 2 CTAs/SM)
    gemm_mma<true, true, false, true><<<dim3(32, 4, 8), 256, GEMM_SMEM>>>(
        h2h, w11, nullptr, nullptr, b1, nullptr, nullptr,
        nullptr, midh, nullptr, nullptr, 1.f, 0.f, 0.f,
        nullptr, disp, 1024, 4096, 0, (long)D_MODEL * FFN_D, FFN_D, (long)CAPV * FFN_D);

    // 8) FFN2 -> fp32 y (*0.8) (TN=128, 2 CTAs/SM)
    gemm_mma<false, false, false, false><<<dim3(8, 4, 8), 256, GEMM_SMEM>>>(
        midh, w21, nullptr, nullptr, b2, nullptr, nullptr,
        y, nullptr, nullptr, nullptr, 0.8f, 0.f, 0.f,
        nullptr, nullptr, 4096, 1024,
        (long)CAPV * FFN_D, (long)FFN_D * D_MODEL, D_MODEL, (long)CAPV * D_MODEL);

    // 9) combine
    combine_kernel<<<N_TOK, 256>>>(out);
}

// round 14
// speedup vs baseline: 2.2230x; 1.0070x over previous
#include <cuda_runtime.h>
#include <cuda_fp16.h>
#include <cstdint>

#define D_MODEL 1024
#define N_TOK   2048
#define N_HEADS 16
#define HEAD_D  64
#define SEQ     512
#define NB      4
#define FFN_D   4096
#define NEXP    8
#define CAPV    512

typedef __half hf;

// ================= device scratch =================
__device__ hf g_wq1[1048576], g_wk1[1048576], g_wv1[1048576], g_wo1[1048576];
__device__ hf g_w11[33554432], g_w21[33554432];
__device__ hf g_h1h[2097152];
__device__ hf g_h2h[2097152];
__device__ float g_h2[2097152];
__device__ hf g_qh[2097152];
__device__ hf g_kh[2097152];
__device__ hf g_vh[2097152];
__device__ hf g_ath[2097152];
__device__ hf g_midh[16777216];
__device__ hf g_ph[16777216];
__device__ float g_sc[16777216];
__device__ float g_y[4194304];
__device__ int   g_top1[N_TOK], g_top2[N_TOK];
__device__ float g_p1[N_TOK], g_p2[N_TOK];
__device__ int   g_s1[N_TOK], g_s2[N_TOK];
__device__ float g_g1[N_TOK], g_g2[N_TOK];
__device__ int   g_disp[NEXP * CAPV];

// ================= helpers =================
__device__ __forceinline__ uint32_t smem_u32(const void* p) {
    uint32_t a;
    asm("{ .reg .u64 t; cvta.to.shared.u64 t, %1; cvt.u32.u64 %0, t; }" : "=r"(a) : "l"(p));
    return a;
}
__device__ __forceinline__ void ldsm_x4(uint32_t* r, uint32_t addr) {
    asm volatile("ldmatrix.sync.aligned.m8n8.x4.shared.b16 {%0,%1,%2,%3}, [%4];"
        : "=r"(r[0]), "=r"(r[1]), "=r"(r[2]), "=r"(r[3]) : "r"(addr));
}
__device__ __forceinline__ void ldsm_x4t(uint32_t* r, uint32_t addr) {
    asm volatile("ldmatrix.sync.aligned.m8n8.x4.trans.shared.b16 {%0,%1,%2,%3}, [%4];"
        : "=r"(r[0]), "=r"(r[1]), "=r"(r[2]), "=r"(r[3]) : "r"(addr));
}
__device__ __forceinline__ void mma16816(float* c, const uint32_t* a, uint32_t b0, uint32_t b1) {
    asm volatile(
        "mma.sync.aligned.m16n8k16.row.col.f32.f16.f16.f32 "
        "{%0,%1,%2,%3}, {%4,%5,%6,%7}, {%8,%9}, {%0,%1,%2,%3};"
        : "+f"(c[0]), "+f"(c[1]), "+f"(c[2]), "+f"(c[3])
        : "r"(a[0]), "r"(a[1]), "r"(a[2]), "r"(a[3]), "r"(b0), "r"(b1));
}
__device__ __forceinline__ void cp16(uint32_t dst, const void* src) {
    asm volatile("cp.async.cg.shared.global [%0], [%1], 16;" :: "r"(dst), "l"(src) : "memory");
}
#define CP_COMMIT() asm volatile("cp.async.commit_group;" ::: "memory")
__device__ __forceinline__ uint32_t pack2s(float x, float y) {
    return (uint32_t)__half_as_ushort(__float2half_rn(x)) |
           ((uint32_t)__half_as_ushort(__float2half_rn(y)) << 16);
}

// ================= weight rounding passes =================
__global__ __launch_bounds__(256)
void round_pass(const float* __restrict__ src, hf* __restrict__ dst, long n4) {
    for (long i = blockIdx.x * 256 + threadIdx.x; i < n4; i += (long)gridDim.x * 256) {
        float4 v = *(const float4*)(src + i * 4);
        *(uint2*)(dst + i * 4) = make_uint2(pack2s(v.x, v.y), pack2s(v.z, v.w));
    }
}

__global__ __launch_bounds__(256)
void round_attn(const float* __restrict__ wq, const float* __restrict__ wk,
                const float* __restrict__ wv, const float* __restrict__ wo,
                hf* __restrict__ q1, hf* __restrict__ k1,
                hf* __restrict__ v1, hf* __restrict__ o1) {
    int z = blockIdx.z;
    const float* src = (z == 0) ? wq : (z == 1) ? wk : (z == 2) ? wv : wo;
    hf* dst = (z == 0) ? q1 : (z == 1) ? k1 : (z == 2) ? v1 : o1;
    const long n4 = 262144;
    for (long i = blockIdx.x * 256 + threadIdx.x; i < n4; i += (long)gridDim.x * 256) {
        float4 v = *(const float4*)(src + i * 4);
        *(uint2*)(dst + i * 4) = make_uint2(pack2s(v.x, v.y), pack2s(v.z, v.w));
    }
}

// ================= fp16 HMMA GEMM: CTA TMx128, Kc=32, 3-stage cp.async, 2 CTAs/SM =================
template <int TMv, bool RELU, bool GATHER, bool MULTI, bool OSPLIT>
__global__ __launch_bounds__(256, 2)
void gemm_mma(const hf* __restrict__ A,
              const hf* __restrict__ B0, const hf* __restrict__ B1,
              const hf* __restrict__ B2,
              const float* __restrict__ bi0, const float* __restrict__ bi1,
              const float* __restrict__ bi2,
              float* __restrict__ oF0,
              hf* __restrict__ oH0, hf* __restrict__ oH1, hf* __restrict__ oH2,
              float s0, float s1, float s2,
              const float* __restrict__ resid, const int* __restrict__ gather,
              int K, int N,
              long aStride, long bStride, long biStride, long oStride) {
    constexpr int A_SZ = TMv * 80;           // A stage bytes (80 B/row)
    constexpr int B_O  = A_SZ;
    constexpr int STGB = A_SZ + 8192;        // + B stage (32 rows x 256 B)
    constexpr int MT   = TMv / 32;           // m output tiles per warp
    constexpr int WMROWS = TMv / 2;          // rows per warp m-slice

    extern __shared__ char sm[];
    uint32_t sb = smem_u32(sm);
    int tid = threadIdx.x, wid = tid >> 5, lane = tid & 31;
    int z = blockIdx.z;
    int m0 = blockIdx.y * TMv, n0 = blockIdx.x * 128;

    const hf* B; const float* bi; float scale;
    float* oF = nullptr; hf* oH = nullptr;
    if (MULTI) {
        B = (z == 0) ? B0 : (z == 1) ? B1 : B2;
        bi = (z == 0) ? bi0 : (z == 1) ? bi1 : bi2;
        scale = (z == 0) ? s0 : (z == 1) ? s1 : s2;
        oH = (z == 0) ? oH0 : (z == 1) ? oH1 : oH2;
    } else {
        B = B0 + (long)z * bStride;
        bi = bi0 + (long)z * biStride;
        scale = s0;
        if (OSPLIT) oH = oH0 + (long)z * oStride;
        else oF = oF0 + (long)z * oStride;
    }
    const hf* Az = A + (MULTI ? 0 : (long)z * aStride);
    const int* gz = GATHER ? (gather + z * CAPV) : nullptr;

    // A load mapping: TMv rows x 4 vectors/row; 256 threads -> TMv/64 vectors/thread
    int aR0 = tid >> 2, aC0 = (tid & 3) * 8;
    long aRow0 = GATHER ? (long)gz[m0 + aR0] : (long)(m0 + aR0);
    long aG0 = aRow0 * K + aC0;
    int aD0 = aR0 * 80 + aC0 * 2;
    long aG1 = 0; int aD1 = 0;
    if (TMv == 128) {
        int aR1 = (tid + 256) >> 2, aC1 = ((tid + 256) & 3) * 8;
        long aRow1 = GATHER ? (long)gz[m0 + aR1] : (long)(m0 + aR1);
        aG1 = aRow1 * K + aC1;
        aD1 = aR1 * 80 + aC1 * 2;
    }

    int bK0 = tid >> 4, bN0 = (tid & 15) * 8;
    long bG0 = (long)bK0 * N + n0 + bN0;
    int bD0 = bK0 * 256 + ((bN0 * 2) ^ ((bK0 & 7) << 4));

    int nCh = K >> 5;
#pragma unroll
    for (int pre = 0; pre < 2; pre++) {
        uint32_t base = sb + (uint32_t)pre * STGB;
        int k0 = pre << 5;
        long ko = (long)k0 * N;
        cp16(base + aD0, Az + aG0 + k0);
        if (TMv == 128) cp16(base + aD1, Az + aG1 + k0);
        cp16(base + B_O + bD0, B + ko + bG0);
        cp16(base + B_O + bD0 + 4096, B + ko + bG0 + 16L * N);
        CP_COMMIT();
    }

    float c[MT][4][4];
#pragma unroll
    for (int mt = 0; mt < MT; mt++)
#pragma unroll
        for (int nt = 0; nt < 4; nt++)
#pragma unroll
            for (int f = 0; f < 4; f++) c[mt][nt][f] = 0.f;

    int wm = wid >> 2, wn = wid & 3;
    int aRowOff = (lane & 7) + ((lane >> 3) & 1) * 8;
    int aColSel = ((lane >> 4) & 1) * 16;
    int bKoff = (lane & 7) + ((lane >> 3) & 1) * 8;
    int bN8 = ((lane >> 4) & 1) * 8;

    for (int ch = 0; ch < nCh; ch++) {
        if (ch + 1 < nCh) asm volatile("cp.async.wait_group 1;" ::: "memory");
        else              asm volatile("cp.async.wait_group 0;" ::: "memory");
        __syncthreads();
        if (ch + 2 < nCh) {
            int chn = ch + 2;
            uint32_t base = sb + (uint32_t)(chn % 3) * STGB;
            int k0 = chn << 5;
            long ko = (long)k0 * N;
            cp16(base + aD0, Az + aG0 + k0);
            if (TMv == 128) cp16(base + aD1, Az + aG1 + k0);
            cp16(base + B_O + bD0, B + ko + bG0);
            cp16(base + B_O + bD0 + 4096, B + ko + bG0 + 16L * N);
            CP_COMMIT();
        }
        uint32_t sbuf = sb + (uint32_t)(ch % 3) * STGB;
#pragma unroll
        for (int ks = 0; ks < 2; ks++) {
            uint32_t ah[MT][4];
#pragma unroll
            for (int mt = 0; mt < MT; mt++) {
                uint32_t ro = (wm * WMROWS + mt * 16 + aRowOff) * 80 + ks * 32 + aColSel;
                ldsm_x4(ah[mt], sbuf + ro);
            }
#pragma unroll
            for (int nb = 0; nb < 2; nb++) {
                uint32_t bhf[4];
                int kk = ks * 16 + bKoff;
                int nn = wn * 32 + nb * 16 + bN8;
                uint32_t off = kk * 256 + ((nn * 2) ^ ((kk & 7) << 4));
                ldsm_x4t(bhf, sbuf + B_O + off);
#pragma unroll
                for (int hfk = 0; hfk < 2; hfk++) {
                    int nt = nb * 2 + hfk;
#pragma unroll
                    for (int mt = 0; mt < MT; mt++)
                        mma16816(c[mt][nt], ah[mt], bhf[hfk * 2], bhf[hfk * 2 + 1]);
                }
            }
        }
    }

    int r0 = m0 + wm * WMROWS + (lane >> 2);
    int col0 = n0 + wn * 32 + (lane & 3) * 2;
#pragma unroll
    for (int mt = 0; mt < MT; mt++) {
#pragma unroll
        for (int nt = 0; nt < 4; nt++) {
            int row = r0 + mt * 16;
            int cn = col0 + nt * 8;
            float2 bb = *(const float2*)(bi + cn);
            float v0x = (c[mt][nt][0] + bb.x) * scale;
            float v0y = (c[mt][nt][1] + bb.y) * scale;
            float v1x = (c[mt][nt][2] + bb.x) * scale;
            float v1y = (c[mt][nt][3] + bb.y) * scale;
            if (resid) {
                float2 ra = *(const float2*)(resid + (long)row * N + cn);
                float2 rb = *(const float2*)(resid + (long)(row + 8) * N + cn);
                v0x += ra.x; v0y += ra.y; v1x += rb.x; v1y += rb.y;
            }
            if (RELU) {
                v0x = fmaxf(v0x, 0.f); v0y = fmaxf(v0y, 0.f);
                v1x = fmaxf(v1x, 0.f); v1y = fmaxf(v1y, 0.f);
            }
            if (OSPLIT) {
                *(uint32_t*)(oH + (long)row * N + cn) = pack2s(v0x, v0y);
                *(uint32_t*)(oH + (long)(row + 8) * N + cn) = pack2s(v1x, v1y);
            } else {
                *(float2*)(oF + (long)row * N + cn) = make_float2(v0x, v0y);
                *(float2*)(oF + (long)(row + 8) * N + cn) = make_float2(v1x, v1y);
            }
        }
    }
}

// ================= scores: S = Q.K^T per (b,h), CTA 128x128, K=64 =================
#define SC_Q 0
#define SC_K 18432
#define SC_SMEM 36864

__global__ __launch_bounds__(256, 1)
void scores_mma(const hf* __restrict__ qh, const hf* __restrict__ kh,
                float* __restrict__ sc) {
    extern __shared__ char sm[];
    uint32_t sb = smem_u32(sm);
    int tid = threadIdx.x, wid = tid >> 5, lane = tid & 31;
    int bh = blockIdx.z;
    int b = bh >> 4, h = bh & 15;
    int m0 = blockIdx.y * 128, n0 = blockIdx.x * 128;

#pragma unroll
    for (int i = 0; i < 4; i++) {
        int v = tid + 256 * i;
        int row = v >> 3, c8 = (v & 7) * 8;
        int off = row * 144 + c8 * 2;
        long qg = (long)(b * SEQ + m0 + row) * D_MODEL + h * HEAD_D + c8;
        long kg = (long)(b * SEQ + n0 + row) * D_MODEL + h * HEAD_D + c8;
        *(uint4*)(sm + SC_Q + off) = *(const uint4*)(qh + qg);
        *(uint4*)(sm + SC_K + off) = *(const uint4*)(kh + kg);
    }
    __syncthreads();

    float c[4][4][4];
#pragma unroll
    for (int mt = 0; mt < 4; mt++)
#pragma unroll
        for (int nt = 0; nt < 4; nt++)
#pragma unroll
            for (int f = 0; f < 4; f++) c[mt][nt][f] = 0.f;

    int wm = wid >> 2, wn = wid & 3;
    int rowOff = (lane & 7) + ((lane >> 3) & 1) * 8;
    int colSel = ((lane >> 4) & 1) * 16;

#pragma unroll
    for (int ks = 0; ks < 4; ks++) {
        uint32_t ah[4][4];
#pragma unroll
        for (int mt = 0; mt < 4; mt++) {
            uint32_t ro = (wm * 64 + mt * 16 + rowOff) * 144 + ks * 32 + colSel;
            ldsm_x4(ah[mt], sb + SC_Q + ro);
        }
        uint32_t bh_[2][4];
#pragma unroll
        for (int nb = 0; nb < 2; nb++) {
            uint32_t ro = (wn * 32 + nb * 16 + rowOff) * 144 + ks * 32 + colSel;
            ldsm_x4(bh_[nb], sb + SC_K + ro);
        }
#pragma unroll
        for (int mt = 0; mt < 4; mt++)
#pragma unroll
            for (int nt = 0; nt < 4; nt++) {
                int nb = nt >> 1, hfk = nt & 1;
                mma16816(c[mt][nt], ah[mt], bh_[nb][hfk], bh_[nb][hfk + 2]);
            }
    }

    long base = (long)bh * SEQ * SEQ;
    int r0 = m0 + wm * 64 + (lane >> 2);
    int col0 = n0 + wn * 32 + (lane & 3) * 2;
#pragma unroll
    for (int mt = 0; mt < 4; mt++)
#pragma unroll
        for (int nt = 0; nt < 4; nt++) {
            int row = r0 + mt * 16, cn = col0 + nt * 8;
            *(float2*)(sc + base + (long)row * SEQ + cn) = make_float2(c[mt][nt][0], c[mt][nt][1]);
            *(float2*)(sc + base + (long)(row + 8) * SEQ + cn) = make_float2(c[mt][nt][2], c[mt][nt][3]);
        }
}

// ================= softmax: fp32 -> fp16 P =================
__global__ __launch_bounds__(128)
void softmax_kernel(const float* __restrict__ sc, hf* __restrict__ ph) {
    __shared__ float redM[4], redS[4];
    const float* row = sc + (size_t)blockIdx.x * SEQ;
    float v[4]; float m = -1e30f;
#pragma unroll
    for (int i = 0; i < 4; i++) { v[i] = row[threadIdx.x + 128 * i]; m = fmaxf(m, v[i]); }
#pragma unroll
    for (int o = 16; o; o >>= 1) m = fmaxf(m, __shfl_xor_sync(~0u, m, o));
    if ((threadIdx.x & 31) == 0) redM[threadIdx.x >> 5] = m;
    __syncthreads();
    m = fmaxf(fmaxf(redM[0], redM[1]), fmaxf(redM[2], redM[3]));
    float s = 0.f;
#pragma unroll
    for (int i = 0; i < 4; i++) { v[i] = expf(v[i] - m); s += v[i]; }
#pragma unroll
    for (int o = 16; o; o >>= 1) s += __shfl_xor_sync(~0u, s, o);
    if ((threadIdx.x & 31) == 0) redS[threadIdx.x >> 5] = s;
    __syncthreads();
    s = redS[0] + redS[1] + redS[2] + redS[3];
    float inv = 1.f / s;
    size_t base = (size_t)blockIdx.x * SEQ;
#pragma unroll
    for (int i = 0; i < 4; i++) {
        float p = v[i] * inv;
        ph[base + threadIdx.x + 128 * i] = __float2half_rn(p);
    }
}

// ================= PV: O = P.V per (b,h), CTA 128x64, Kc=32 =================
#define PV_P 0
#define PV_V 10240
#define PV_BUF 14336
#define PV_SMEM (2 * PV_BUF)

__global__ __launch_bounds__(256, 1)
void pv_mma(const hf* __restrict__ ph, const hf* __restrict__ vh,
            hf* __restrict__ oh) {
    extern __shared__ char sm[];
    uint32_t sb = smem_u32(sm);
    int tid = threadIdx.x, wid = tid >> 5, lane = tid & 31;
    int bh = blockIdx.y;
    int b = bh >> 4, h = bh & 15;
    int m0 = blockIdx.x * 128;

    int v0 = tid, v1 = tid + 256;
    int aR0 = v0 >> 2, aC0 = (v0 & 3) * 8;
    int aR1 = v1 >> 2, aC1 = (v1 & 3) * 8;
    long pBase = (long)bh * SEQ * SEQ;
    long aG0 = pBase + (long)(m0 + aR0) * SEQ + aC0;
    long aG1 = pBase + (long)(m0 + aR1) * SEQ + aC1;
    int aS0 = aR0 * 80 + aC0 * 2;
    int aS1 = aR1 * 80 + aC1 * 2;
    int bKr = tid >> 3, bN0 = (tid & 7) * 8;
    long bG = (long)(b * SEQ + bKr) * D_MODEL + h * HEAD_D + bN0;
    int bS = bKr * 128 + ((bN0 * 2) ^ ((bKr & 7) << 4));

    float c[4][2][4];
#pragma unroll
    for (int mt = 0; mt < 4; mt++)
#pragma unroll
        for (int nt = 0; nt < 2; nt++)
#pragma unroll
            for (int f = 0; f < 4; f++) c[mt][nt][f] = 0.f;

    int wm = wid >> 2, wn = wid & 3;
    int aRowOff = (lane & 7) + ((lane >> 3) & 1) * 8;
    int aColSel = ((lane >> 4) & 1) * 16;
    int bKoff = (lane & 7) + ((lane >> 3) & 1) * 8;
    int bN8 = ((lane >> 4) & 1) * 8;

    uint4 vph0 = *(const uint4*)(ph + aG0), vph1 = *(const uint4*)(ph + aG1);
    uint4 vvh = *(const uint4*)(vh + bG);

    for (int ch = 0; ch < 16; ch++) {
        char* smb = sm + (ch & 1) * PV_BUF;
        uint32_t sbuf = sb + (ch & 1) * PV_BUF;
        __syncthreads();
        *(uint4*)(smb + PV_P + aS0) = vph0; *(uint4*)(smb + PV_P + aS1) = vph1;
        *(uint4*)(smb + PV_V + bS) = vvh;
        __syncthreads();
        if (ch < 15) {
            int k0 = (ch + 1) << 5;
            vph0 = *(const uint4*)(ph + aG0 + k0);
            vph1 = *(const uint4*)(ph + aG1 + k0);
            vvh = *(const uint4*)(vh + bG + (long)k0 * D_MODEL);
        }
#pragma unroll
        for (int ks = 0; ks < 2; ks++) {
            uint32_t ah[4][4];
#pragma unroll
            for (int mt = 0; mt < 4; mt++) {
                uint32_t ro = (wm * 64 + mt * 16 + aRowOff) * 80 + ks * 32 + aColSel;
                ldsm_x4(ah[mt], sbuf + PV_P + ro);
            }
            uint32_t bh_[4];
            {
                int kk = ks * 16 + bKoff;
                int nn = wn * 16 + bN8;
                uint32_t off = kk * 128 + ((nn * 2) ^ ((kk & 7) << 4));
                ldsm_x4t(bh_, sbuf + PV_V + off);
            }
#pragma unroll
            for (int mt = 0; mt < 4; mt++)
#pragma unroll
                for (int nt = 0; nt < 2; nt++)
                    mma16816(c[mt][nt], ah[mt], bh_[nt * 2], bh_[nt * 2 + 1]);
        }
    }

    int r0 = m0 + wm * 64 + (lane >> 2);
    int col0 = wn * 16 + (lane & 3) * 2;
#pragma unroll
    for (int mt = 0; mt < 4; mt++)
#pragma unroll
        for (int nt = 0; nt < 2; nt++) {
            int row = r0 + mt * 16;
            int cn = col0 + nt * 8;
            long o0 = (long)(b * SEQ + row) * D_MODEL + h * HEAD_D + cn;
            long o1 = (long)(b * SEQ + row + 8) * D_MODEL + h * HEAD_D + cn;
            *(uint32_t*)(oh + o0) = pack2s(c[mt][nt][0], c[mt][nt][1]);
            *(uint32_t*)(oh + o1) = pack2s(c[mt][nt][2], c[mt][nt][3]);
        }
}

// ================= LayerNorm -> optional fp32 + fp16 =================
__global__ void ln_kernel(const float* __restrict__ x, const float* __restrict__ gam,
                          const float* __restrict__ bet, float* __restrict__ outF,
                          hf* __restrict__ oh) {
    __shared__ float redA[8], redB[8];
    int t = blockIdx.x;
    const float* xr = x + (size_t)t * D_MODEL;
    float v[4]; float s = 0.f;
#pragma unroll
    for (int i = 0; i < 4; i++) { v[i] = xr[threadIdx.x + 256 * i]; s += v[i]; }
#pragma unroll
    for (int o = 16; o; o >>= 1) s += __shfl_xor_sync(~0u, s, o);
    if ((threadIdx.x & 31) == 0) redA[threadIdx.x >> 5] = s;
    __syncthreads();
    if (threadIdx.x == 0) { float r = 0.f; for (int i = 0; i < 8; i++) r += redA[i]; redA[0] = r; }
    __syncthreads();
    float mu = redA[0] * (1.f / D_MODEL);
    float s2 = 0.f;
#pragma unroll
    for (int i = 0; i < 4; i++) { float d = v[i] - mu; s2 += d * d; }
#pragma unroll
    for (int o = 16; o; o >>= 1) s2 += __shfl_xor_sync(~0u, s2, o);
    if ((threadIdx.x & 31) == 0) redB[threadIdx.x >> 5] = s2;
    __syncthreads();
    if (threadIdx.x == 0) { float r = 0.f; for (int i = 0; i < 8; i++) r += redB[i]; redB[0] = r; }
    __syncthreads();
    float rstd = rsqrtf(redB[0] * (1.f / D_MODEL) + 1e-5f);
    size_t base = (size_t)t * D_MODEL;
#pragma unroll
    for (int i = 0; i < 4; i++) {
        int cc = threadIdx.x + 256 * i;
        float r = (v[i] - mu) * rstd * gam[cc] + bet[cc];
        if (outF) outF[base + cc] = r;
        oh[base + cc] = __float2half_rn(r);
    }
}

// ================= router / scan / combine =================
__global__ __launch_bounds__(256)
void router_kernel(const float* __restrict__ h2, const float* __restrict__ wr) {
    int t = blockIdx.x * 8 + (threadIdx.x >> 5);
    int lane = threadIdx.x & 31;
    const float* xr = h2 + (long)t * D_MODEL;
    float acc[8];
#pragma unroll
    for (int e = 0; e < 8; e++) acc[e] = 0.f;
    for (int i = lane; i < D_MODEL; i += 32) {
        float xv = xr[i];
        const float* w = wr + i * 8;
#pragma unroll
        for (int e = 0; e < 8; e++) acc[e] = fmaf(xv, w[e], acc[e]);
    }
#pragma unroll
    for (int o = 16; o; o >>= 1)
#pragma unroll
        for (int e = 0; e < 8; e++) acc[e] += __shfl_xor_sync(~0u, acc[e], o);
    if (lane == 0) {
        float m = acc[0]; int t1 = 0;
#pragma unroll
        for (int e = 1; e < 8; e++) if (acc[e] > m) { m = acc[e]; t1 = e; }
        float s = 0.f, pr[8];
#pragma unroll
        for (int e = 0; e < 8; e++) { pr[e] = expf(acc[e] - m); s += pr[e]; }
        float inv = 1.f / s;
        float m2 = -1e30f; int t2 = 0;
#pragma unroll
        for (int e = 0; e < 8; e++) {
            if (e == t1) continue;
            if (acc[e] > m2) { m2 = acc[e]; t2 = e; }
        }
        g_top1[t] = t1; g_top2[t] = t2;
        g_p1[t] = pr[t1] * inv;
        g_p2[t] = pr[t2] * inv;
    }
}

__global__ __launch_bounds__(256)
void scan_kernel() {
    int tid = threadIdx.x;
    for (int i = tid; i < NEXP * CAPV; i += 256) g_disp[i] = 0;
    __syncthreads();
    int e = tid >> 5;
    int lane = tid & 31;
    unsigned lt = (1u << lane) - 1u;
    int base = 0;
    for (int c0 = 0; c0 < N_TOK; c0 += 32) {
        int t = c0 + lane;
        bool f = (g_top1[t] == e);
        unsigned msk = __ballot_sync(~0u, f);
        if (f) {
            int loc = base + __popc(msk & lt);
            if (loc < CAPV) { g_s1[t] = loc; g_disp[e * CAPV + loc] = t; }
            else g_s1[t] = -1;
        }
        base += __popc(msk);
    }
    for (int c0 = 0; c0 < N_TOK; c0 += 32) {
        int t = c0 + lane;
        bool f = (g_top2[t] == e);
        unsigned msk = __ballot_sync(~0u, f);
        if (f) {
            int loc = base + __popc(msk & lt);
            if (loc < CAPV) { g_s2[t] = loc; g_disp[e * CAPV + loc] = t; }
            else g_s2[t] = -1;
        }
        base += __popc(msk);
    }
    __syncthreads();
    for (int t = tid; t < N_TOK; t += 256) {
        float t1 = (g_s1[t] >= 0) ? g_p1[t] : 0.f;
        float t2 = (g_s2[t] >= 0) ? g_p2[t] : 0.f;
        float den = fmaxf(t1 + t2, 1.1920929e-7f);
        g_g1[t] = t1 / den;
        g_g2[t] = t2 / den;
    }
}

__global__ __launch_bounds__(256)
void combine_kernel(float* __restrict__ out) {
    int t = blockIdx.x;
    int s1 = g_s1[t], s2 = g_s2[t];
    float g1 = g_g1[t], g2 = g_g2[t];
    const float* y1 = (s1 >= 0) ? g_y + ((long)g_top1[t] * CAPV + s1) * D_MODEL : 0;
    const float* y2 = (s2 >= 0) ? g_y + ((long)g_top2[t] * CAPV + s2) * D_MODEL : 0;
    long ro = (long)t * D_MODEL;
#pragma unroll
    for (int i = 0; i < 4; i++) {
        int d = threadIdx.x + 256 * i;
        float a = out[ro + d];
        if (y1) a = fmaf(g1, y1[d], a);
        if (y2) a = fmaf(g2, y2[d], a);
        out[ro + d] = a;
    }
}

// ================= launch =================
extern "C" void kernel_launch(void* const* d_in, const int* in_sizes, int n_in,
                              void* d_out, int out_size) {
    const float* x    = (const float*)d_in[0];
    const float* wq   = (const float*)d_in[1];
    const float* bq   = (const float*)d_in[2];
    const float* wk   = (const float*)d_in[3];
    const float* bk   = (const float*)d_in[4];
    const float* wv   = (const float*)d_in[5];
    const float* bv   = (const float*)d_in[6];
    const float* wo   = (const float*)d_in[7];
    const float* bo   = (const float*)d_in[8];
    const float* ln1g = (const float*)d_in[9];
    const float* ln1b = (const float*)d_in[10];
    const float* ln2g = (const float*)d_in[11];
    const float* ln2b = (const float*)d_in[12];
    const float* wr   = (const float*)d_in[13];
    const float* w1   = (const float*)d_in[14];
    const float* b1   = (const float*)d_in[15];
    const float* w2   = (const float*)d_in[16];
    const float* b2   = (const float*)d_in[17];
    float* out = (float*)d_out;

    hf *wq1, *wk1, *wv1, *wo1, *w11, *w21;
    hf *h1h, *h2h, *qh, *kh, *vh, *ath, *midh, *ph;
    float *h2, *sc, *y;
    int* disp;
    cudaGetSymbolAddress((void**)&wq1, g_wq1); cudaGetSymbolAddress((void**)&wk1, g_wk1);
    cudaGetSymbolAddress((void**)&wv1, g_wv1); cudaGetSymbolAddress((void**)&wo1, g_wo1);
    cudaGetSymbolAddress((void**)&w11, g_w11); cudaGetSymbolAddress((void**)&w21, g_w21);
    cudaGetSymbolAddress((void**)&h1h, g_h1h); cudaGetSymbolAddress((void**)&h2h, g_h2h);
    cudaGetSymbolAddress((void**)&qh, g_qh);   cudaGetSymbolAddress((void**)&kh, g_kh);
    cudaGetSymbolAddress((void**)&vh, g_vh);   cudaGetSymbolAddress((void**)&ath, g_ath);
    cudaGetSymbolAddress((void**)&midh, g_midh);
    cudaGetSymbolAddress((void**)&ph, g_ph);
    cudaGetSymbolAddress((void**)&h2, g_h2);
    cudaGetSymbolAddress((void**)&sc, g_sc);
    cudaGetSymbolAddress((void**)&y, g_y);
    cudaGetSymbolAddress((void**)&disp, g_disp);

    constexpr int SMEM64  = 3 * (64 * 80 + 8192);    // 39936
    constexpr int SMEM128 = 3 * (128 * 80 + 8192);   // 55296
    cudaFuncSetAttribute(gemm_mma<64, false, false, true, true>,
                         cudaFuncAttributeMaxDynamicSharedMemorySize, SMEM64);
    cudaFuncSetAttribute(gemm_mma<64, false, false, false, false>,
                         cudaFuncAttributeMaxDynamicSharedMemorySize, SMEM64);
    cudaFuncSetAttribute(gemm_mma<128, true, true, false, true>,
                         cudaFuncAttributeMaxDynamicSharedMemorySize, SMEM128);
    cudaFuncSetAttribute(gemm_mma<128, false, false, false, false>,
                         cudaFuncAttributeMaxDynamicSharedMemorySize, SMEM128);
    cudaFuncSetAttribute(scores_mma, cudaFuncAttributeMaxDynamicSharedMemorySize, SC_SMEM);
    cudaFuncSetAttribute(pv_mma, cudaFuncAttributeMaxDynamicSharedMemorySize, PV_SMEM);

    // 0) weight rounding (single fp16 plane)
    round_attn<<<dim3(256, 1, 4), 256>>>(wq, wk, wv, wo, wq1, wk1, wv1, wo1);
    round_pass<<<4096, 256>>>(w1, w11, 33554432 / 4);
    round_pass<<<4096, 256>>>(w2, w21, 33554432 / 4);

    // 1) LN1 -> fp16
    ln_kernel<<<N_TOK, 256>>>(x, ln1g, ln1b, nullptr, h1h);

    // 2) QKV fused (TM=64: 768 CTAs, full waves)
    gemm_mma<64, false, false, true, true><<<dim3(8, 32, 3), 256, SMEM64>>>(
        h1h, wq1, wk1, wv1, bq, bk, bv,
        nullptr, qh, kh, vh, 0.125f, 1.f, 1.f,
        nullptr, nullptr, 1024, 1024, 0, 0, 0, 0);

    // 3) attention
    scores_mma<<<dim3(4, 4, NB * N_HEADS), 256, SC_SMEM>>>(qh, kh, sc);
    softmax_kernel<<<NB * N_HEADS * SEQ, 128>>>(sc, ph);
    pv_mma<<<dim3(4, NB * N_HEADS), 256, PV_SMEM>>>(ph, vh, ath);

    // 4) O projection + residual (TM=64: 256 CTAs)
    gemm_mma<64, false, false, false, false><<<dim3(8, 32, 1), 256, SMEM64>>>(
        ath, wo1, nullptr, nullptr, bo, nullptr, nullptr,
        out, nullptr, nullptr, nullptr, 1.f, 0.f, 0.f,
        x, nullptr, 1024, 1024, 0, 0, 0, 0);

    // 5) LN2
    ln_kernel<<<N_TOK, 256>>>(out, ln2g, ln2b, h2, h2h);

    // 6) router + scan
    router_kernel<<<N_TOK / 8, 256>>>(h2, wr);
    scan_kernel<<<1, 256>>>();

    // 7) FFN1 gathered + relu -> fp16 mid (TM=128, proven)
    gemm_mma<128, true, true, false, true><<<dim3(32, 4, 8), 256, SMEM128>>>(
        h2h, w11, nullptr, nullptr, b1, nullptr, nullptr,
        nullptr, midh, nullptr, nullptr, 1.f, 0.f, 0.f,
        nullptr, disp, 1024, 4096, 0, (long)D_MODEL * FFN_D, FFN_D, (long)CAPV * FFN_D);

    // 8) FFN2 -> fp32 y (*0.8) (TM=128)
    gemm_mma<128, false, false, false, false><<<dim3(8, 4, 8), 256, SMEM128>>>(
        midh, w21, nullptr, nullptr, b2, nullptr, nullptr,
        y, nullptr, nullptr, nullptr, 0.8f, 0.f, 0.f,
        nullptr, nullptr, 4096, 1024,
        (long)CAPV * FFN_D, (long)FFN_D * D_MODEL, D_MODEL, (long)CAPV * D_MODEL);

    // 9) combine
    combine_kernel<<<N_TOK, 256>>>(out);
}

// round 15
// speedup vs baseline: 2.3334x; 1.0497x over previous
#include <cuda_runtime.h>
#include <cuda_fp16.h>
#include <cstdint>

#define D_MODEL 1024
#define N_TOK   2048
#define N_HEADS 16
#define HEAD_D  64
#define SEQ     512
#define NB      4
#define FFN_D   4096
#define NEXP    8
#define CAPV    512

typedef __half hf;

// ================= device scratch =================
__device__ hf g_wq1[1048576], g_wk1[1048576], g_wv1[1048576], g_wo1[1048576];
__device__ hf g_w11[33554432], g_w21[33554432];
__device__ hf g_h1h[2097152];
__device__ hf g_h2h[2097152];
__device__ float g_h2[2097152];
__device__ hf g_qh[2097152];
__device__ hf g_kh[2097152];
__device__ hf g_vh[2097152];
__device__ hf g_ath[2097152];
__device__ hf g_midh[16777216];
__device__ float g_y[4194304];
__device__ int   g_top1[N_TOK], g_top2[N_TOK];
__device__ float g_p1[N_TOK], g_p2[N_TOK];
__device__ int   g_s1[N_TOK], g_s2[N_TOK];
__device__ float g_g1[N_TOK], g_g2[N_TOK];
__device__ int   g_disp[NEXP * CAPV];

// ================= helpers =================
__device__ __forceinline__ uint32_t smem_u32(const void* p) {
    uint32_t a;
    asm("{ .reg .u64 t; cvta.to.shared.u64 t, %1; cvt.u32.u64 %0, t; }" : "=r"(a) : "l"(p));
    return a;
}
__device__ __forceinline__ void ldsm_x4(uint32_t* r, uint32_t addr) {
    asm volatile("ldmatrix.sync.aligned.m8n8.x4.shared.b16 {%0,%1,%2,%3}, [%4];"
        : "=r"(r[0]), "=r"(r[1]), "=r"(r[2]), "=r"(r[3]) : "r"(addr));
}
__device__ __forceinline__ void ldsm_x4t(uint32_t* r, uint32_t addr) {
    asm volatile("ldmatrix.sync.aligned.m8n8.x4.trans.shared.b16 {%0,%1,%2,%3}, [%4];"
        : "=r"(r[0]), "=r"(r[1]), "=r"(r[2]), "=r"(r[3]) : "r"(addr));
}
__device__ __forceinline__ void mma16816(float* c, const uint32_t* a, uint32_t b0, uint32_t b1) {
    asm volatile(
        "mma.sync.aligned.m16n8k16.row.col.f32.f16.f16.f32 "
        "{%0,%1,%2,%3}, {%4,%5,%6,%7}, {%8,%9}, {%0,%1,%2,%3};"
        : "+f"(c[0]), "+f"(c[1]), "+f"(c[2]), "+f"(c[3])
        : "r"(a[0]), "r"(a[1]), "r"(a[2]), "r"(a[3]), "r"(b0), "r"(b1));
}
__device__ __forceinline__ void cp16(uint32_t dst, const void* src) {
    asm volatile("cp.async.cg.shared.global [%0], [%1], 16;" :: "r"(dst), "l"(src) : "memory");
}
#define CP_COMMIT() asm volatile("cp.async.commit_group;" ::: "memory")
__device__ __forceinline__ uint32_t pack2s(float x, float y) {
    return (uint32_t)__half_as_ushort(__float2half_rn(x)) |
           ((uint32_t)__half_as_ushort(__float2half_rn(y)) << 16);
}

// ================= weight rounding passes =================
__global__ __launch_bounds__(256)
void round_pass(const float* __restrict__ src, hf* __restrict__ dst, long n4) {
    for (long i = blockIdx.x * 256 + threadIdx.x; i < n4; i += (long)gridDim.x * 256) {
        float4 v = *(const float4*)(src + i * 4);
        *(uint2*)(dst + i * 4) = make_uint2(pack2s(v.x, v.y), pack2s(v.z, v.w));
    }
}

__global__ __launch_bounds__(256)
void round_attn(const float* __restrict__ wq, const float* __restrict__ wk,
                const float* __restrict__ wv, const float* __restrict__ wo,
                hf* __restrict__ q1, hf* __restrict__ k1,
                hf* __restrict__ v1, hf* __restrict__ o1) {
    int z = blockIdx.z;
    const float* src = (z == 0) ? wq : (z == 1) ? wk : (z == 2) ? wv : wo;
    hf* dst = (z == 0) ? q1 : (z == 1) ? k1 : (z == 2) ? v1 : o1;
    const long n4 = 262144;
    for (long i = blockIdx.x * 256 + threadIdx.x; i < n4; i += (long)gridDim.x * 256) {
        float4 v = *(const float4*)(src + i * 4);
        *(uint2*)(dst + i * 4) = make_uint2(pack2s(v.x, v.y), pack2s(v.z, v.w));
    }
}

// ================= fp16 HMMA GEMM: CTA TMx128, Kc=32, 3-stage cp.async, 2 CTAs/SM =================
template <int TMv, bool RELU, bool GATHER, bool MULTI, bool OSPLIT>
__global__ __launch_bounds__(256, 2)
void gemm_mma(const hf* __restrict__ A,
              const hf* __restrict__ B0, const hf* __restrict__ B1,
              const hf* __restrict__ B2,
              const float* __restrict__ bi0, const float* __restrict__ bi1,
              const float* __restrict__ bi2,
              float* __restrict__ oF0,
              hf* __restrict__ oH0, hf* __restrict__ oH1, hf* __restrict__ oH2,
              float s0, float s1, float s2,
              const float* __restrict__ resid, const int* __restrict__ gather,
              int K, int N,
              long aStride, long bStride, long biStride, long oStride) {
    constexpr int A_SZ = TMv * 80;
    constexpr int B_O  = A_SZ;
    constexpr int STGB = A_SZ + 8192;
    constexpr int MT   = TMv / 32;
    constexpr int WMROWS = TMv / 2;

    extern __shared__ char sm[];
    uint32_t sb = smem_u32(sm);
    int tid = threadIdx.x, wid = tid >> 5, lane = tid & 31;
    int z = blockIdx.z;
    int m0 = blockIdx.y * TMv, n0 = blockIdx.x * 128;

    const hf* B; const float* bi; float scale;
    float* oF = nullptr; hf* oH = nullptr;
    if (MULTI) {
        B = (z == 0) ? B0 : (z == 1) ? B1 : B2;
        bi = (z == 0) ? bi0 : (z == 1) ? bi1 : bi2;
        scale = (z == 0) ? s0 : (z == 1) ? s1 : s2;
        oH = (z == 0) ? oH0 : (z == 1) ? oH1 : oH2;
    } else {
        B = B0 + (long)z * bStride;
        bi = bi0 + (long)z * biStride;
        scale = s0;
        if (OSPLIT) oH = oH0 + (long)z * oStride;
        else oF = oF0 + (long)z * oStride;
    }
    const hf* Az = A + (MULTI ? 0 : (long)z * aStride);
    const int* gz = GATHER ? (gather + z * CAPV) : nullptr;

    int aR0 = tid >> 2, aC0 = (tid & 3) * 8;
    long aRow0 = GATHER ? (long)gz[m0 + aR0] : (long)(m0 + aR0);
    long aG0 = aRow0 * K + aC0;
    int aD0 = aR0 * 80 + aC0 * 2;
    long aG1 = 0; int aD1 = 0;
    if (TMv == 128) {
        int aR1 = (tid + 256) >> 2, aC1 = ((tid + 256) & 3) * 8;
        long aRow1 = GATHER ? (long)gz[m0 + aR1] : (long)(m0 + aR1);
        aG1 = aRow1 * K + aC1;
        aD1 = aR1 * 80 + aC1 * 2;
    }

    int bK0 = tid >> 4, bN0 = (tid & 15) * 8;
    long bG0 = (long)bK0 * N + n0 + bN0;
    int bD0 = bK0 * 256 + ((bN0 * 2) ^ ((bK0 & 7) << 4));

    int nCh = K >> 5;
#pragma unroll
    for (int pre = 0; pre < 2; pre++) {
        uint32_t base = sb + (uint32_t)pre * STGB;
        int k0 = pre << 5;
        long ko = (long)k0 * N;
        cp16(base + aD0, Az + aG0 + k0);
        if (TMv == 128) cp16(base + aD1, Az + aG1 + k0);
        cp16(base + B_O + bD0, B + ko + bG0);
        cp16(base + B_O + bD0 + 4096, B + ko + bG0 + 16L * N);
        CP_COMMIT();
    }

    float c[MT][4][4];
#pragma unroll
    for (int mt = 0; mt < MT; mt++)
#pragma unroll
        for (int nt = 0; nt < 4; nt++)
#pragma unroll
            for (int f = 0; f < 4; f++) c[mt][nt][f] = 0.f;

    int wm = wid >> 2, wn = wid & 3;
    int aRowOff = (lane & 7) + ((lane >> 3) & 1) * 8;
    int aColSel = ((lane >> 4) & 1) * 16;
    int bKoff = (lane & 7) + ((lane >> 3) & 1) * 8;
    int bN8 = ((lane >> 4) & 1) * 8;

    for (int ch = 0; ch < nCh; ch++) {
        if (ch + 1 < nCh) asm volatile("cp.async.wait_group 1;" ::: "memory");
        else              asm volatile("cp.async.wait_group 0;" ::: "memory");
        __syncthreads();
        if (ch + 2 < nCh) {
            int chn = ch + 2;
            uint32_t base = sb + (uint32_t)(chn % 3) * STGB;
            int k0 = chn << 5;
            long ko = (long)k0 * N;
            cp16(base + aD0, Az + aG0 + k0);
            if (TMv == 128) cp16(base + aD1, Az + aG1 + k0);
            cp16(base + B_O + bD0, B + ko + bG0);
            cp16(base + B_O + bD0 + 4096, B + ko + bG0 + 16L * N);
            CP_COMMIT();
        }
        uint32_t sbuf = sb + (uint32_t)(ch % 3) * STGB;
#pragma unroll
        for (int ks = 0; ks < 2; ks++) {
            uint32_t ah[MT][4];
#pragma unroll
            for (int mt = 0; mt < MT; mt++) {
                uint32_t ro = (wm * WMROWS + mt * 16 + aRowOff) * 80 + ks * 32 + aColSel;
                ldsm_x4(ah[mt], sbuf + ro);
            }
#pragma unroll
            for (int nb = 0; nb < 2; nb++) {
                uint32_t bhf[4];
                int kk = ks * 16 + bKoff;
                int nn = wn * 32 + nb * 16 + bN8;
                uint32_t off = kk * 256 + ((nn * 2) ^ ((kk & 7) << 4));
                ldsm_x4t(bhf, sbuf + B_O + off);
#pragma unroll
                for (int hfk = 0; hfk < 2; hfk++) {
                    int nt = nb * 2 + hfk;
#pragma unroll
                    for (int mt = 0; mt < MT; mt++)
                        mma16816(c[mt][nt], ah[mt], bhf[hfk * 2], bhf[hfk * 2 + 1]);
                }
            }
        }
    }

    int r0 = m0 + wm * WMROWS + (lane >> 2);
    int col0 = n0 + wn * 32 + (lane & 3) * 2;
#pragma unroll
    for (int mt = 0; mt < MT; mt++) {
#pragma unroll
        for (int nt = 0; nt < 4; nt++) {
            int row = r0 + mt * 16;
            int cn = col0 + nt * 8;
            float2 bb = *(const float2*)(bi + cn);
            float v0x = (c[mt][nt][0] + bb.x) * scale;
            float v0y = (c[mt][nt][1] + bb.y) * scale;
            float v1x = (c[mt][nt][2] + bb.x) * scale;
            float v1y = (c[mt][nt][3] + bb.y) * scale;
            if (resid) {
                float2 ra = *(const float2*)(resid + (long)row * N + cn);
                float2 rb = *(const float2*)(resid + (long)(row + 8) * N + cn);
                v0x += ra.x; v0y += ra.y; v1x += rb.x; v1y += rb.y;
            }
            if (RELU) {
                v0x = fmaxf(v0x, 0.f); v0y = fmaxf(v0y, 0.f);
                v1x = fmaxf(v1x, 0.f); v1y = fmaxf(v1y, 0.f);
            }
            if (OSPLIT) {
                *(uint32_t*)(oH + (long)row * N + cn) = pack2s(v0x, v0y);
                *(uint32_t*)(oH + (long)(row + 8) * N + cn) = pack2s(v1x, v1y);
            } else {
                *(float2*)(oF + (long)row * N + cn) = make_float2(v0x, v0y);
                *(float2*)(oF + (long)(row + 8) * N + cn) = make_float2(v1x, v1y);
            }
        }
    }
}

// ================= fused flash attention: per (qblock 128, b*h), KV chunks of 64 =================
// smem: Q 128x144B | K 64x144B | V 64x128B(sw) | P 128x128B(sw) | stats
#define FA_Q  0
#define FA_K  18432
#define FA_V  27648
#define FA_P  35840
#define FA_M  52224
#define FA_L  52736
#define FA_AL 53248
#define FA_PM 53760
#define FA_PS 55808
#define FA_SMEM 57856

__global__ __launch_bounds__(256, 2)
void flash_attn(const hf* __restrict__ qh, const hf* __restrict__ kh,
                const hf* __restrict__ vh, hf* __restrict__ oh) {
    extern __shared__ char sm[];
    uint32_t sb = smem_u32(sm);
    float* M  = (float*)(sm + FA_M);
    float* L  = (float*)(sm + FA_L);
    float* AL = (float*)(sm + FA_AL);
    float* PM = (float*)(sm + FA_PM);
    float* PS = (float*)(sm + FA_PS);

    int tid = threadIdx.x, wid = tid >> 5, lane = tid & 31;
    int bh = blockIdx.y;
    int b = bh >> 4, h = bh & 15;
    int m0 = blockIdx.x * 128;

    // load Q once: 1024 vectors, 4/thread
#pragma unroll
    for (int i = 0; i < 4; i++) {
        int v = tid + 256 * i;
        int row = v >> 3, c8 = (v & 7) * 8;
        long qg = (long)(b * SEQ + m0 + row) * D_MODEL + h * HEAD_D + c8;
        *(uint4*)(sm + FA_Q + row * 144 + c8 * 2) = *(const uint4*)(qh + qg);
    }
    if (tid < 128) { M[tid] = -1e30f; L[tid] = 0.f; }

    int wm = wid >> 2, wn = wid & 3;
    int rowOff = (lane & 7) + ((lane >> 3) & 1) * 8;
    int colSel = ((lane >> 4) & 1) * 16;
    int bKoff = rowOff;
    int bN8 = colSel >> 1;  // ((lane>>4)&1)*8

    float oc[4][2][4];
#pragma unroll
    for (int mt = 0; mt < 4; mt++)
#pragma unroll
        for (int nt = 0; nt < 2; nt++)
#pragma unroll
            for (int f = 0; f < 4; f++) oc[mt][nt][f] = 0.f;

    int qr = lane >> 2;           // row offset within 16-row tile (0..7)
    int qc = (lane & 3) * 2;      // col pair base

    for (int j = 0; j < SEQ / 64; j++) {
        __syncthreads();   // prev chunk's K/V/P fully consumed
        // load K,V chunk: 512 vectors each, 2/thread
#pragma unroll
        for (int i = 0; i < 2; i++) {
            int v = tid + 256 * i;
            int row = v >> 3, c8 = (v & 7) * 8;
            long kg = (long)(b * SEQ + j * 64 + row) * D_MODEL + h * HEAD_D + c8;
            *(uint4*)(sm + FA_K + row * 144 + c8 * 2) = *(const uint4*)(kh + kg);
            *(uint4*)(sm + FA_V + row * 128 + ((c8 * 2) ^ ((row & 7) << 4))) =
                *(const uint4*)(vh + kg);
        }
        __syncthreads();

        // S = Q.K^T  (warp: rows wm*64..+64, cols wn*16..+16)
        float c[4][2][4];
#pragma unroll
        for (int mt = 0; mt < 4; mt++)
#pragma unroll
            for (int nt = 0; nt < 2; nt++)
#pragma unroll
                for (int f = 0; f < 4; f++) c[mt][nt][f] = 0.f;
#pragma unroll
        for (int ks = 0; ks < 4; ks++) {
            uint32_t ah[4][4];
#pragma unroll
            for (int mt = 0; mt < 4; mt++) {
                uint32_t ro = (wm * 64 + mt * 16 + rowOff) * 144 + ks * 32 + colSel;
                ldsm_x4(ah[mt], sb + FA_Q + ro);
            }
            uint32_t bh_[4];
            {
                uint32_t ro = (wn * 16 + rowOff) * 144 + ks * 32 + colSel;
                ldsm_x4(bh_, sb + FA_K + ro);
            }
#pragma unroll
            for (int mt = 0; mt < 4; mt++)
#pragma unroll
                for (int nt = 0; nt < 2; nt++)
                    mma16816(c[mt][nt], ah[mt], bh_[nt], bh_[nt + 2]);
        }

        // row partial max (quad shuffle), write PM[row*4+wn]
#pragma unroll
        for (int mt = 0; mt < 4; mt++) {
            float mA = fmaxf(fmaxf(c[mt][0][0], c[mt][0][1]), fmaxf(c[mt][1][0], c[mt][1][1]));
            float mB = fmaxf(fmaxf(c[mt][0][2], c[mt][0][3]), fmaxf(c[mt][1][2], c[mt][1][3]));
#pragma unroll
            for (int o = 1; o <= 2; o <<= 1) {
                mA = fmaxf(mA, __shfl_xor_sync(~0u, mA, o));
                mB = fmaxf(mB, __shfl_xor_sync(~0u, mB, o));
            }
            if ((lane & 3) == 0) {
                int rA = wm * 64 + mt * 16 + qr;
                PM[rA * 4 + wn] = mA;
                PM[(rA + 8) * 4 + wn] = mB;
            }
        }
        __syncthreads();

        // p = exp(s - m_new); partial sums; write P (fp16, swizzled)
#pragma unroll
        for (int mt = 0; mt < 4; mt++) {
            int rA = wm * 64 + mt * 16 + qr;
            int rB = rA + 8;
            float mnA = fmaxf(M[rA], fmaxf(fmaxf(PM[rA * 4], PM[rA * 4 + 1]),
                                           fmaxf(PM[rA * 4 + 2], PM[rA * 4 + 3])));
            float mnB = fmaxf(M[rB], fmaxf(fmaxf(PM[rB * 4], PM[rB * 4 + 1]),
                                           fmaxf(PM[rB * 4 + 2], PM[rB * 4 + 3])));
            float sA = 0.f, sB = 0.f;
#pragma unroll
            for (int nt = 0; nt < 2; nt++) {
                float p0 = expf(c[mt][nt][0] - mnA);
                float p1 = expf(c[mt][nt][1] - mnA);
                float p2 = expf(c[mt][nt][2] - mnB);
                float p3 = expf(c[mt][nt][3] - mnB);
                sA += p0 + p1; sB += p2 + p3;
                int cn = wn * 16 + nt * 8 + qc;
                *(uint32_t*)(sm + FA_P + rA * 128 + ((cn * 2) ^ ((rA & 7) << 4))) = pack2s(p0, p1);
                *(uint32_t*)(sm + FA_P + rB * 128 + ((cn * 2) ^ ((rB & 7) << 4))) = pack2s(p2, p3);
            }
#pragma unroll
            for (int o = 1; o <= 2; o <<= 1) {
                sA += __shfl_xor_sync(~0u, sA, o);
                sB += __shfl_xor_sync(~0u, sB, o);
            }
            if ((lane & 3) == 0) {
                PS[rA * 4 + wn] = sA;
                PS[rB * 4 + wn] = sB;
            }
        }
        __syncthreads();

        // single-writer stat update per row
        if (tid < 128) {
            int r = tid;
            float mo = M[r];
            float mn = fmaxf(mo, fmaxf(fmaxf(PM[r * 4], PM[r * 4 + 1]),
                                       fmaxf(PM[r * 4 + 2], PM[r * 4 + 3])));
            float a = expf(mo - mn);
            AL[r] = a;
            L[r] = a * L[r] + PS[r * 4] + PS[r * 4 + 1] + PS[r * 4 + 2] + PS[r * 4 + 3];
            M[r] = mn;
        }
        __syncthreads();

        // O = alpha*O + P.V  (warp: rows wm*64..+64, cols wn*16..+16)
#pragma unroll
        for (int mt = 0; mt < 4; mt++) {
            int rA = wm * 64 + mt * 16 + qr;
            float aA = AL[rA], aB = AL[rA + 8];
#pragma unroll
            for (int nt = 0; nt < 2; nt++) {
                oc[mt][nt][0] *= aA; oc[mt][nt][1] *= aA;
                oc[mt][nt][2] *= aB; oc[mt][nt][3] *= aB;
            }
        }
#pragma unroll
        for (int ks = 0; ks < 4; ks++) {
            uint32_t pa[4][4];
#pragma unroll
            for (int mt = 0; mt < 4; mt++) {
                int row = wm * 64 + mt * 16 + rowOff;
                uint32_t ro = row * 128 + (((uint32_t)(ks * 32 + colSel)) ^ ((row & 7) << 4));
                ldsm_x4(pa[mt], sb + FA_P + ro);
            }
            uint32_t vb[4];
            {
                int kk = ks * 16 + bKoff;
                int nn = wn * 16 + bN8;
                uint32_t off = kk * 128 + ((nn * 2) ^ ((kk & 7) << 4));
                ldsm_x4t(vb, sb + FA_V + off);
            }
#pragma unroll
            for (int mt = 0; mt < 4; mt++)
#pragma unroll
                for (int nt = 0; nt < 2; nt++)
                    mma16816(oc[mt][nt], pa[mt], vb[nt * 2], vb[nt * 2 + 1]);
        }
    }

    // epilogue: O /= L, store fp16
#pragma unroll
    for (int mt = 0; mt < 4; mt++) {
        int rA = wm * 64 + mt * 16 + qr;
        int rB = rA + 8;
        float iA = 1.f / L[rA], iB = 1.f / L[rB];
#pragma unroll
        for (int nt = 0; nt < 2; nt++) {
            int cn = wn * 16 + nt * 8 + qc;
            long o0 = (long)(b * SEQ + m0 + rA) * D_MODEL + h * HEAD_D + cn;
            long o1 = (long)(b * SEQ + m0 + rB) * D_MODEL + h * HEAD_D + cn;
            *(uint32_t*)(oh + o0) = pack2s(oc[mt][nt][0] * iA, oc[mt][nt][1] * iA);
            *(uint32_t*)(oh + o1) = pack2s(oc[mt][nt][2] * iB, oc[mt][nt][3] * iB);
        }
    }
}

// ================= LayerNorm -> optional fp32 + fp16 =================
__global__ void ln_kernel(const float* __restrict__ x, const float* __restrict__ gam,
                          const float* __restrict__ bet, float* __restrict__ outF,
                          hf* __restrict__ oh) {
    __shared__ float redA[8], redB[8];
    int t = blockIdx.x;
    const float* xr = x + (size_t)t * D_MODEL;
    float v[4]; float s = 0.f;
#pragma unroll
    for (int i = 0; i < 4; i++) { v[i] = xr[threadIdx.x + 256 * i]; s += v[i]; }
#pragma unroll
    for (int o = 16; o; o >>= 1) s += __shfl_xor_sync(~0u, s, o);
    if ((threadIdx.x & 31) == 0) redA[threadIdx.x >> 5] = s;
    __syncthreads();
    if (threadIdx.x == 0) { float r = 0.f; for (int i = 0; i < 8; i++) r += redA[i]; redA[0] = r; }
    __syncthreads();
    float mu = redA[0] * (1.f / D_MODEL);
    float s2 = 0.f;
#pragma unroll
    for (int i = 0; i < 4; i++) { float d = v[i] - mu; s2 += d * d; }
#pragma unroll
    for (int o = 16; o; o >>= 1) s2 += __shfl_xor_sync(~0u, s2, o);
    if ((threadIdx.x & 31) == 0) redB[threadIdx.x >> 5] = s2;
    __syncthreads();
    if (threadIdx.x == 0) { float r = 0.f; for (int i = 0; i < 8; i++) r += redB[i]; redB[0] = r; }
    __syncthreads();
    float rstd = rsqrtf(redB[0] * (1.f / D_MODEL) + 1e-5f);
    size_t base = (size_t)t * D_MODEL;
#pragma unroll
    for (int i = 0; i < 4; i++) {
        int cc = threadIdx.x + 256 * i;
        float r = (v[i] - mu) * rstd * gam[cc] + bet[cc];
        if (outF) outF[base + cc] = r;
        oh[base + cc] = __float2half_rn(r);
    }
}

// ================= router / scan / combine =================
__global__ __launch_bounds__(256)
void router_kernel(const float* __restrict__ h2, const float* __restrict__ wr) {
    int t = blockIdx.x * 8 + (threadIdx.x >> 5);
    int lane = threadIdx.x & 31;
    const float* xr = h2 + (long)t * D_MODEL;
    float acc[8];
#pragma unroll
    for (int e = 0; e < 8; e++) acc[e] = 0.f;
    for (int i = lane; i < D_MODEL; i += 32) {
        float xv = xr[i];
        const float* w = wr + i * 8;
#pragma unroll
        for (int e = 0; e < 8; e++) acc[e] = fmaf(xv, w[e], acc[e]);
    }
#pragma unroll
    for (int o = 16; o; o >>= 1)
#pragma unroll
        for (int e = 0; e < 8; e++) acc[e] += __shfl_xor_sync(~0u, acc[e], o);
    if (lane == 0) {
        float m = acc[0]; int t1 = 0;
#pragma unroll
        for (int e = 1; e < 8; e++) if (acc[e] > m) { m = acc[e]; t1 = e; }
        float s = 0.f, pr[8];
#pragma unroll
        for (int e = 0; e < 8; e++) { pr[e] = expf(acc[e] - m); s += pr[e]; }
        float inv = 1.f / s;
        float m2 = -1e30f; int t2 = 0;
#pragma unroll
        for (int e = 0; e < 8; e++) {
            if (e == t1) continue;
            if (acc[e] > m2) { m2 = acc[e]; t2 = e; }
        }
        g_top1[t] = t1; g_top2[t] = t2;
        g_p1[t] = pr[t1] * inv;
        g_p2[t] = pr[t2] * inv;
    }
}

__global__ __launch_bounds__(256)
void scan_kernel() {
    int tid = threadIdx.x;
    for (int i = tid; i < NEXP * CAPV; i += 256) g_disp[i] = 0;
    __syncthreads();
    int e = tid >> 5;
    int lane = tid & 31;
    unsigned lt = (1u << lane) - 1u;
    int base = 0;
    for (int c0 = 0; c0 < N_TOK; c0 += 32) {
        int t = c0 + lane;
        bool f = (g_top1[t] == e);
        unsigned msk = __ballot_sync(~0u, f);
        if (f) {
            int loc = base + __popc(msk & lt);
            if (loc < CAPV) { g_s1[t] = loc; g_disp[e * CAPV + loc] = t; }
            else g_s1[t] = -1;
        }
        base += __popc(msk);
    }
    for (int c0 = 0; c0 < N_TOK; c0 += 32) {
        int t = c0 + lane;
        bool f = (g_top2[t] == e);
        unsigned msk = __ballot_sync(~0u, f);
        if (f) {
            int loc = base + __popc(msk & lt);
            if (loc < CAPV) { g_s2[t] = loc; g_disp[e * CAPV + loc] = t; }
            else g_s2[t] = -1;
        }
        base += __popc(msk);
    }
    __syncthreads();
    for (int t = tid; t < N_TOK; t += 256) {
        float t1 = (g_s1[t] >= 0) ? g_p1[t] : 0.f;
        float t2 = (g_s2[t] >= 0) ? g_p2[t] : 0.f;
        float den = fmaxf(t1 + t2, 1.1920929e-7f);
        g_g1[t] = t1 / den;
        g_g2[t] = t2 / den;
    }
}

__global__ __launch_bounds__(256)
void combine_kernel(float* __restrict__ out) {
    int t = blockIdx.x;
    int s1 = g_s1[t], s2 = g_s2[t];
    float g1 = g_g1[t], g2 = g_g2[t];
    const float* y1 = (s1 >= 0) ? g_y + ((long)g_top1[t] * CAPV + s1) * D_MODEL : 0;
    const float* y2 = (s2 >= 0) ? g_y + ((long)g_top2[t] * CAPV + s2) * D_MODEL : 0;
    long ro = (long)t * D_MODEL;
#pragma unroll
    for (int i = 0; i < 4; i++) {
        int d = threadIdx.x + 256 * i;
        float a = out[ro + d];
        if (y1) a = fmaf(g1, y1[d], a);
        if (y2) a = fmaf(g2, y2[d], a);
        out[ro + d] = a;
    }
}

// ================= launch =================
extern "C" void kernel_launch(void* const* d_in, const int* in_sizes, int n_in,
                              void* d_out, int out_size) {
    const float* x    = (const float*)d_in[0];
    const float* wq   = (const float*)d_in[1];
    const float* bq   = (const float*)d_in[2];
    const float* wk   = (const float*)d_in[3];
    const float* bk   = (const float*)d_in[4];
    const float* wv   = (const float*)d_in[5];
    const float* bv   = (const float*)d_in[6];
    const float* wo   = (const float*)d_in[7];
    const float* bo   = (const float*)d_in[8];
    const float* ln1g = (const float*)d_in[9];
    const float* ln1b = (const float*)d_in[10];
    const float* ln2g = (const float*)d_in[11];
    const float* ln2b = (const float*)d_in[12];
    const float* wr   = (const float*)d_in[13];
    const float* w1   = (const float*)d_in[14];
    const float* b1   = (const float*)d_in[15];
    const float* w2   = (const float*)d_in[16];
    const float* b2   = (const float*)d_in[17];
    float* out = (float*)d_out;

    hf *wq1, *wk1, *wv1, *wo1, *w11, *w21;
    hf *h1h, *h2h, *qh, *kh, *vh, *ath, *midh;
    float *h2, *y;
    int* disp;
    cudaGetSymbolAddress((void**)&wq1, g_wq1); cudaGetSymbolAddress((void**)&wk1, g_wk1);
    cudaGetSymbolAddress((void**)&wv1, g_wv1); cudaGetSymbolAddress((void**)&wo1, g_wo1);
    cudaGetSymbolAddress((void**)&w11, g_w11); cudaGetSymbolAddress((void**)&w21, g_w21);
    cudaGetSymbolAddress((void**)&h1h, g_h1h); cudaGetSymbolAddress((void**)&h2h, g_h2h);
    cudaGetSymbolAddress((void**)&qh, g_qh);   cudaGetSymbolAddress((void**)&kh, g_kh);
    cudaGetSymbolAddress((void**)&vh, g_vh);   cudaGetSymbolAddress((void**)&ath, g_ath);
    cudaGetSymbolAddress((void**)&midh, g_midh);
    cudaGetSymbolAddress((void**)&h2, g_h2);
    cudaGetSymbolAddress((void**)&y, g_y);
    cudaGetSymbolAddress((void**)&disp, g_disp);

    constexpr int SMEM64  = 3 * (64 * 80 + 8192);
    constexpr int SMEM128 = 3 * (128 * 80 + 8192);
    cudaFuncSetAttribute(gemm_mma<64, false, false, true, true>,
                         cudaFuncAttributeMaxDynamicSharedMemorySize, SMEM64);
    cudaFuncSetAttribute(gemm_mma<64, false, false, false, false>,
                         cudaFuncAttributeMaxDynamicSharedMemorySize, SMEM64);
    cudaFuncSetAttribute(gemm_mma<128, true, true, false, true>,
                         cudaFuncAttributeMaxDynamicSharedMemorySize, SMEM128);
    cudaFuncSetAttribute(gemm_mma<128, false, false, false, false>,
                         cudaFuncAttributeMaxDynamicSharedMemorySize, SMEM128);
    cudaFuncSetAttribute(flash_attn, cudaFuncAttributeMaxDynamicSharedMemorySize, FA_SMEM);

    // 0) weight rounding (single fp16 plane)
    round_attn<<<dim3(256, 1, 4), 256>>>(wq, wk, wv, wo, wq1, wk1, wv1, wo1);
    round_pass<<<4096, 256>>>(w1, w11, 33554432 / 4);
    round_pass<<<4096, 256>>>(w2, w21, 33554432 / 4);

    // 1) LN1 -> fp16
    ln_kernel<<<N_TOK, 256>>>(x, ln1g, ln1b, nullptr, h1h);

    // 2) QKV fused (TM=64)
    gemm_mma<64, false, false, true, true><<<dim3(8, 32, 3), 256, SMEM64>>>(
        h1h, wq1, wk1, wv1, bq, bk, bv,
        nullptr, qh, kh, vh, 0.125f, 1.f, 1.f,
        nullptr, nullptr, 1024, 1024, 0, 0, 0, 0);

    // 3) fused flash attention
    flash_attn<<<dim3(SEQ / 128, NB * N_HEADS), 256, FA_SMEM>>>(qh, kh, vh, ath);

    // 4) O projection + residual (TM=64)
    gemm_mma<64, false, false, false, false><<<dim3(8, 32, 1), 256, SMEM64>>>(
        ath, wo1, nullptr, nullptr, bo, nullptr, nullptr,
        out, nullptr, nullptr, nullptr, 1.f, 0.f, 0.f,
        x, nullptr, 1024, 1024, 0, 0, 0, 0);

    // 5) LN2
    ln_kernel<<<N_TOK, 256>>>(out, ln2g, ln2b, h2, h2h);

    // 6) router + scan
    router_kernel<<<N_TOK / 8, 256>>>(h2, wr);
    scan_kernel<<<1, 256>>>();

    // 7) FFN1 gathered + relu -> fp16 mid (TM=128)
    gemm_mma<128, true, true, false, true><<<dim3(32, 4, 8), 256, SMEM128>>>(
        h2h, w11, nullptr, nullptr, b1, nullptr, nullptr,
        nullptr, midh, nullptr, nullptr, 1.f, 0.f, 0.f,
        nullptr, disp, 1024, 4096, 0, (long)D_MODEL * FFN_D, FFN_D, (long)CAPV * FFN_D);

    // 8) FFN2 -> fp32 y (*0.8) (TM=128)
    gemm_mma<128, false, false, false, false><<<dim3(8, 4, 8), 256, SMEM128>>>(
        midh, w21, nullptr, nullptr, b2, nullptr, nullptr,
        y, nullptr, nullptr, nullptr, 0.8f, 0.f, 0.f,
        nullptr, nullptr, 4096, 1024,
        (long)CAPV * FFN_D, (long)FFN_D * D_MODEL, D_MODEL, (long)CAPV * D_MODEL);

    // 9) combine
    combine_kernel<<<N_TOK, 256>>>(out);
}